// round 6
// baseline (speedup 1.0000x reference)
#include <cuda_runtime.h>
#include <cuda_bf16.h>
#include <cuda_pipeline.h>
#include <mma.h>
#include <cstdint>

using namespace nvcuda;

#define NN 50000
#define HH 128
#define OUTC 64
#define DEPTH 3
#define LN_EPS 1e-5f
#define EGMAX 600000
#define ELMAX 400000
#define NB196 196
#define TILES 391          // ceil(NN/128)
#define LDT 40             // smem leading dim (bf16): 80B rows -> conflict-free LDSM
#define TSZ (128 * LDT)
#define STAGE (4 * TSZ)

// ================= scratch =================
__device__ float g_x[NN * HH];
__device__ float g_hG[NN * HH];
__device__ float g_hL[NN * HH];
__device__ __nv_bfloat16 g_xh[NN * HH];
__device__ __nv_bfloat16 g_xl[NN * HH];
__device__ __nv_bfloat16 g_cath[NN * 2 * HH];
__device__ __nv_bfloat16 g_catl[NN * 2 * HH];
__device__ int   g_degG[NN];
__device__ int   g_degL[NN];
__device__ float g_dinvG[NN];
__device__ float g_dinvL[NN];
__device__ int   g_rowptrG[NN + 1];
__device__ int   g_rowptrL[NN + 1];
__device__ int   g_fillG[NN];
__device__ int   g_fillL[NN];
__device__ int   g_colG[EGMAX];
__device__ int   g_colL[ELMAX];
__device__ float g_coefG[EGMAX];
__device__ float g_coefL[ELMAX];
__device__ int   g_bsum[2][256];
__device__ __nv_bfloat16 g_BGh[DEPTH * HH * HH];
__device__ __nv_bfloat16 g_BGl[DEPTH * HH * HH];
__device__ __nv_bfloat16 g_BLh[DEPTH * HH * HH];
__device__ __nv_bfloat16 g_BLl[DEPTH * HH * HH];
__device__ __nv_bfloat16 g_Blinh[DEPTH * HH * 2 * HH];
__device__ __nv_bfloat16 g_Blinl[DEPTH * HH * 2 * HH];
__device__ __nv_bfloat16 g_Bfinh[OUTC * HH];
__device__ __nv_bfloat16 g_Bfinl[OUTC * HH];

// ================= setup kernels =================
__global__ void zero_deg_kernel(int* degG, int* degL, int n) {
    int i = blockIdx.x * blockDim.x + threadIdx.x;
    if (i < n) { degG[i] = 0; degL[i] = 0; }
}

__global__ void wsplit_all_kernel(const float* __restrict__ WG, const float* __restrict__ WLp,
                                  const float* __restrict__ linW, const float* __restrict__ finW,
                                  __nv_bfloat16* BGh, __nv_bfloat16* BGl,
                                  __nv_bfloat16* BLh, __nv_bfloat16* BLl,
                                  __nv_bfloat16* Blinh, __nv_bfloat16* Blinl,
                                  __nv_bfloat16* Bfinh, __nv_bfloat16* Bfinl) {
    int seg = blockIdx.z;
    const float* W;
    __nv_bfloat16 *Bh, *Bl;
    int K, N;
    if (seg < 3)      { K = HH;     N = HH;   W = WG  + (size_t)seg * HH * HH;           Bh = BGh  + (size_t)seg * HH * HH;           Bl = BGl  + (size_t)seg * HH * HH; }
    else if (seg < 6) { K = HH;     N = HH;   W = WLp + (size_t)(seg - 3) * HH * HH;     Bh = BLh  + (size_t)(seg - 3) * HH * HH;     Bl = BLl  + (size_t)(seg - 3) * HH * HH; }
    else if (seg < 9) { K = 2 * HH; N = HH;   W = linW + (size_t)(seg - 6) * 2 * HH * HH; Bh = Blinh + (size_t)(seg - 6) * 2 * HH * HH; Bl = Blinl + (size_t)(seg - 6) * 2 * HH * HH; }
    else              { K = HH;     N = OUTC; W = finW;                                   Bh = Bfinh;                                   Bl = Bfinl; }
    int n0 = blockIdx.x * 32, k0 = blockIdx.y * 32;
    if (n0 >= N || k0 >= K) return;
    __shared__ float t[32][33];
    int tx = threadIdx.x, ty = threadIdx.y;
    #pragma unroll
    for (int i = 0; i < 4; i++)
        t[ty + i * 8][tx] = W[(size_t)(k0 + ty + i * 8) * N + n0 + tx];
    __syncthreads();
    #pragma unroll
    for (int i = 0; i < 4; i++) {
        float v = t[tx][ty + i * 8];
        __nv_bfloat16 h = __float2bfloat16(v);
        __nv_bfloat16 l = __float2bfloat16(v - __bfloat162float(h));
        size_t o = (size_t)(n0 + ty + i * 8) * K + k0 + tx;
        Bh[o] = h;
        Bl[o] = l;
    }
}

__global__ void init_split_kernel(const float4* __restrict__ xin4, float4* __restrict__ px4,
                                  __nv_bfloat16* __restrict__ xh, __nv_bfloat16* __restrict__ xl) {
    int i = blockIdx.x * blockDim.x + threadIdx.x;
    if (i >= NN * HH / 4) return;
    float4 v = xin4[i];
    px4[i] = v;
    __nv_bfloat16 h0 = __float2bfloat16(v.x), h1 = __float2bfloat16(v.y);
    __nv_bfloat16 h2 = __float2bfloat16(v.z), h3 = __float2bfloat16(v.w);
    __nv_bfloat16 l0 = __float2bfloat16(v.x - __bfloat162float(h0));
    __nv_bfloat16 l1 = __float2bfloat16(v.y - __bfloat162float(h1));
    __nv_bfloat16 l2 = __float2bfloat16(v.z - __bfloat162float(h2));
    __nv_bfloat16 l3 = __float2bfloat16(v.w - __bfloat162float(h3));
    __nv_bfloat162 ph0(h0, h1), ph1(h2, h3), pl0(l0, l1), pl1(l2, l3);
    uint2 uh = { *(unsigned*)&ph0, *(unsigned*)&ph1 };
    uint2 ul = { *(unsigned*)&pl0, *(unsigned*)&pl1 };
    *reinterpret_cast<uint2*>(&xh[i * 4]) = uh;
    *reinterpret_cast<uint2*>(&xl[i * 4]) = ul;
}

__global__ void count_deg_kernel(const int* __restrict__ dstG, int EG,
                                 const int* __restrict__ dstL, int EL,
                                 int* __restrict__ degG, int* __restrict__ degL) {
    int i = blockIdx.x * blockDim.x + threadIdx.x;
    if (i < EG) atomicAdd(&degG[dstG[i]], 1);
    else if (i < EG + EL) atomicAdd(&degL[dstL[i - EG]], 1);
}
__global__ void make_dinv_kernel(const int* __restrict__ degG, float* __restrict__ dinvG,
                                 const int* __restrict__ degL, float* __restrict__ dinvL, int n) {
    int i = blockIdx.x * blockDim.x + threadIdx.x;
    if (i < n) {
        dinvG[i] = rsqrtf((float)degG[i] + 2.0f);
        dinvL[i] = rsqrtf((float)degL[i] + 2.0f);
    }
}
__global__ void scan_block_kernel(const int* __restrict__ degG, const int* __restrict__ degL,
                                  int* __restrict__ rowG, int* __restrict__ rowL,
                                  int* __restrict__ bsum, int n) {
    __shared__ int s[256];
    const int* deg = blockIdx.y ? degL : degG;
    int* rowptr = blockIdx.y ? rowL : rowG;
    int* bs = bsum + blockIdx.y * 256;
    int i = blockIdx.x * 256 + threadIdx.x;
    int v = (i < n) ? deg[i] : 0;
    s[threadIdx.x] = v;
    __syncthreads();
    #pragma unroll
    for (int o = 1; o < 256; o <<= 1) {
        int t = (threadIdx.x >= o) ? s[threadIdx.x - o] : 0;
        __syncthreads();
        s[threadIdx.x] += t;
        __syncthreads();
    }
    if (i < n) rowptr[i] = s[threadIdx.x] - v;
    if (threadIdx.x == 255) bs[blockIdx.x] = s[255];
}
__global__ void scan_aux_kernel(int* bsum, int nb) {
    if (threadIdx.x == 0) {
        for (int y = 0; y < 2; y++) {
            int run = 0;
            int* b = bsum + y * 256;
            for (int i = 0; i < nb; i++) { int t = b[i]; b[i] = run; run += t; }
        }
    }
}
__global__ void scan_add_kernel(int* __restrict__ rowG, int* __restrict__ rowL,
                                int* __restrict__ fillG, int* __restrict__ fillL,
                                const int* __restrict__ bsum, int n, int EG, int EL) {
    int* rowptr = blockIdx.y ? rowL : rowG;
    int* fill = blockIdx.y ? fillL : fillG;
    const int* bs = bsum + blockIdx.y * 256;
    int E = blockIdx.y ? EL : EG;
    int i = blockIdx.x * 256 + threadIdx.x;
    if (i < n) {
        int v = rowptr[i] + bs[i >> 8];
        rowptr[i] = v;
        fill[i] = v;
    }
    if (i == 0) rowptr[n] = E;
}
__global__ void fill_csr_kernel(const int* __restrict__ Ge, int EG, const int* __restrict__ Le, int EL,
                                int* __restrict__ fillG, int* __restrict__ fillL,
                                int* __restrict__ colG, int* __restrict__ colL,
                                float* __restrict__ coefG, float* __restrict__ coefL,
                                const float* __restrict__ dinvG, const float* __restrict__ dinvL) {
    int e = blockIdx.x * blockDim.x + threadIdx.x;
    const int* src; const int* dst; int* fill; int* col; float* coef; const float* dinv; int E;
    if (blockIdx.y == 0) { src = Ge; dst = Ge + EG; fill = fillG; col = colG; coef = coefG; dinv = dinvG; E = EG; }
    else                 { src = Le; dst = Le + EL; fill = fillL; col = colL; coef = coefL; dinv = dinvL; E = EL; }
    if (e < E) {
        int s = src[e], d = dst[e];
        int p = atomicAdd(&fill[d], 1);
        col[p] = s;
        coef[p] = dinv[s] * dinv[d];
    }
}

// ================= bf16x3 GEMM: 4 warps, 64x64 warp tiles, 2-stage cp.async ============
__global__ __launch_bounds__(128)
void gemm_bf16x3_kernel(const __nv_bfloat16* __restrict__ Ah, const __nv_bfloat16* __restrict__ Al,
                        int lda,
                        const __nv_bfloat16* __restrict__ Bh0, const __nv_bfloat16* __restrict__ Bl0,
                        const __nv_bfloat16* __restrict__ Bh1, const __nv_bfloat16* __restrict__ Bl1,
                        float* __restrict__ C0, float* __restrict__ C1,
                        __nv_bfloat16* __restrict__ Csh, __nv_bfloat16* __restrict__ Csl,
                        const float* __restrict__ bias, int M, int K, int Nout) {
    extern __shared__ __nv_bfloat16 sm[];
    const __nv_bfloat16* gBh = blockIdx.y ? Bh1 : Bh0;
    const __nv_bfloat16* gBl = blockIdx.y ? Bl1 : Bl0;
    float* C = blockIdx.y ? C1 : C0;

    const int tid = threadIdx.x;
    const int wid = tid >> 5;
    const int lane = tid & 31;
    const int wr = wid >> 1;        // 0..1, 64 rows each
    const int wc = wid & 1;         // 0..1
    const int row0 = blockIdx.x * 128;
    const int halfN = Nout >> 1;    // 64 or 32
    const int nf = halfN >> 4;      // 4 or 2

    wmma::fragment<wmma::accumulator, 16, 16, 16, float> acc[4][4];
    #pragma unroll
    for (int i = 0; i < 4; i++)
        #pragma unroll
        for (int j = 0; j < 4; j++)
            wmma::fill_fragment(acc[i][j], 0.0f);

    const int nc = K >> 5;

    auto load_stage = [&](int s, int kc) {
        __nv_bfloat16* base = sm + s * STAGE;
        #pragma unroll
        for (int c = tid; c < 512; c += 128) {
            int r = c >> 2;
            int ko = (c & 3) * 8;
            int gr = row0 + r;
            if (gr < M) {
                size_t go = (size_t)gr * lda + kc * 32 + ko;
                __pipeline_memcpy_async(&base[r * LDT + ko], &Ah[go], 16);
                __pipeline_memcpy_async(&base[TSZ + r * LDT + ko], &Al[go], 16);
            }
        }
        for (int c = tid; c < Nout * 4; c += 128) {
            int r = c >> 2;
            int ko = (c & 3) * 8;
            size_t go = (size_t)r * K + kc * 32 + ko;
            __pipeline_memcpy_async(&base[2 * TSZ + r * LDT + ko], &gBh[go], 16);
            __pipeline_memcpy_async(&base[3 * TSZ + r * LDT + ko], &gBl[go], 16);
        }
    };

    load_stage(0, 0);
    __pipeline_commit();

    for (int kc = 0; kc < nc; kc++) {
        if (kc + 1 < nc) {
            load_stage((kc + 1) & 1, kc + 1);
            __pipeline_commit();
            __pipeline_wait_prior(1);
        } else {
            __pipeline_wait_prior(0);
        }
        __syncthreads();

        __nv_bfloat16* Ahs = sm + (kc & 1) * STAGE;
        __nv_bfloat16* Als = Ahs + TSZ;
        __nv_bfloat16* Bhs = Ahs + 2 * TSZ;
        __nv_bfloat16* Bls = Ahs + 3 * TSZ;

        #pragma unroll
        for (int ks = 0; ks < 32; ks += 16) {
            wmma::fragment<wmma::matrix_a, 16, 16, 16, __nv_bfloat16, wmma::row_major> fah[4], fal[4];
            #pragma unroll
            for (int i = 0; i < 4; i++) {
                wmma::load_matrix_sync(fah[i], &Ahs[(wr * 64 + i * 16) * LDT + ks], LDT);
                wmma::load_matrix_sync(fal[i], &Als[(wr * 64 + i * 16) * LDT + ks], LDT);
            }
            wmma::fragment<wmma::matrix_b, 16, 16, 16, __nv_bfloat16, wmma::col_major> fb[4];
            // pass 1+2: B-hi against A-hi and A-lo
            for (int j = 0; j < nf; j++)
                wmma::load_matrix_sync(fb[j], &Bhs[(wc * halfN + j * 16) * LDT + ks], LDT);
            #pragma unroll
            for (int i = 0; i < 4; i++)
                for (int j = 0; j < nf; j++)
                    wmma::mma_sync(acc[i][j], fah[i], fb[j], acc[i][j]);
            #pragma unroll
            for (int i = 0; i < 4; i++)
                for (int j = 0; j < nf; j++)
                    wmma::mma_sync(acc[i][j], fal[i], fb[j], acc[i][j]);
            // pass 3: B-lo against A-hi (reuse fb regs)
            for (int j = 0; j < nf; j++)
                wmma::load_matrix_sync(fb[j], &Bls[(wc * halfN + j * 16) * LDT + ks], LDT);
            #pragma unroll
            for (int i = 0; i < 4; i++)
                for (int j = 0; j < nf; j++)
                    wmma::mma_sync(acc[i][j], fah[i], fb[j], acc[i][j]);
        }
        __syncthreads();
    }

    // epilogue via smem staging
    float* st = reinterpret_cast<float*>(sm) + wid * 320;
    #pragma unroll
    for (int i = 0; i < 4; i++)
        for (int j = 0; j < nf; j++) {
            wmma::store_matrix_sync(st, acc[i][j], 20, wmma::mem_row_major);
            __syncwarp();
            #pragma unroll
            for (int e = 0; e < 8; e++) {
                int idx = lane + e * 32;
                int r = idx >> 4;
                int c = idx & 15;
                int grow = row0 + wr * 64 + i * 16 + r;
                int gcol = wc * halfN + j * 16 + c;
                if (grow < M) {
                    float v = st[r * 20 + c];
                    if (bias) v += __ldg(&bias[gcol]);
                    C[(size_t)grow * Nout + gcol] = v;
                    if (Csh) {
                        __nv_bfloat16 h = __float2bfloat16(v);
                        __nv_bfloat16 l = __float2bfloat16(v - __bfloat162float(h));
                        Csh[(size_t)grow * Nout + gcol] = h;
                        Csl[(size_t)grow * Nout + gcol] = l;
                    }
                }
            }
            __syncwarp();
        }
}

// ================= fused gather + LN + ReLU + residual + concat (bf16-split output) =========
__global__ void gather_ln_kernel(const float4* __restrict__ hG4, const float4* __restrict__ hL4,
                                 const float4* __restrict__ x4,
                                 const int* __restrict__ rowG, const int* __restrict__ rowL,
                                 const int* __restrict__ colG, const int* __restrict__ colL,
                                 const float* __restrict__ coefG, const float* __restrict__ coefL,
                                 const float* __restrict__ dinvG, const float* __restrict__ dinvL,
                                 const float4* __restrict__ biasG4, const float4* __restrict__ biasL4,
                                 const float4* __restrict__ g4, const float4* __restrict__ b4,
                                 __nv_bfloat16* __restrict__ cath, __nv_bfloat16* __restrict__ catl,
                                 int residual) {
    int warp = (blockIdx.x * blockDim.x + threadIdx.x) >> 5;
    int lane = threadIdx.x & 31;
    if (warp >= NN) return;
    int n = warp;
    int half = blockIdx.y;

    const float4* h4 = half ? hL4 : hG4;
    const int* rowptr = half ? rowL : rowG;
    const int* col = half ? colL : colG;
    const float* coef = half ? coefL : coefG;
    const float* dinv = half ? dinvL : dinvG;
    const float4* bias4 = half ? biasL4 : biasG4;

    float dv = __ldg(&dinv[n]);
    float sl = 2.0f * dv * dv;
    float4 h = h4[n * 32 + lane];
    float4 bb = __ldg(&bias4[lane]);
    float4 acc;
    acc.x = h.x * sl + bb.x;
    acc.y = h.y * sl + bb.y;
    acc.z = h.z * sl + bb.z;
    acc.w = h.w * sl + bb.w;

    int e = __ldg(&rowptr[n]);
    int e1 = __ldg(&rowptr[n + 1]);
    for (; e + 1 < e1; e += 2) {
        int s0 = __ldg(&col[e]);
        int s1 = __ldg(&col[e + 1]);
        float c0 = __ldg(&coef[e]);
        float c1 = __ldg(&coef[e + 1]);
        float4 v0 = h4[s0 * 32 + lane];
        float4 v1 = h4[s1 * 32 + lane];
        acc.x += c0 * v0.x + c1 * v1.x;
        acc.y += c0 * v0.y + c1 * v1.y;
        acc.z += c0 * v0.z + c1 * v1.z;
        acc.w += c0 * v0.w + c1 * v1.w;
    }
    if (e < e1) {
        int s0 = __ldg(&col[e]);
        float c0 = __ldg(&coef[e]);
        float4 v0 = h4[s0 * 32 + lane];
        acc.x += c0 * v0.x; acc.y += c0 * v0.y; acc.z += c0 * v0.z; acc.w += c0 * v0.w;
    }

    float s1 = acc.x + acc.y + acc.z + acc.w;
    float s2 = acc.x * acc.x + acc.y * acc.y + acc.z * acc.z + acc.w * acc.w;
    #pragma unroll
    for (int o = 16; o > 0; o >>= 1) {
        s1 += __shfl_xor_sync(0xffffffffu, s1, o);
        s2 += __shfl_xor_sync(0xffffffffu, s2, o);
    }
    float mu = s1 * (1.0f / HH);
    float var = s2 * (1.0f / HH) - mu * mu;
    float rstd = rsqrtf(var + LN_EPS);

    float4 gg = __ldg(&g4[lane]);
    float4 be = __ldg(&b4[lane]);
    float4 y;
    y.x = fmaxf((acc.x - mu) * rstd * gg.x + be.x, 0.0f);
    y.y = fmaxf((acc.y - mu) * rstd * gg.y + be.y, 0.0f);
    y.z = fmaxf((acc.z - mu) * rstd * gg.z + be.z, 0.0f);
    y.w = fmaxf((acc.w - mu) * rstd * gg.w + be.w, 0.0f);
    if (residual) {
        float4 xv = x4[n * 32 + lane];
        y.x += xv.x; y.y += xv.y; y.z += xv.z; y.w += xv.w;
    }
    __nv_bfloat16 h0 = __float2bfloat16(y.x), h1 = __float2bfloat16(y.y);
    __nv_bfloat16 h2 = __float2bfloat16(y.z), h3 = __float2bfloat16(y.w);
    __nv_bfloat16 l0 = __float2bfloat16(y.x - __bfloat162float(h0));
    __nv_bfloat16 l1 = __float2bfloat16(y.y - __bfloat162float(h1));
    __nv_bfloat16 l2 = __float2bfloat16(y.z - __bfloat162float(h2));
    __nv_bfloat16 l3 = __float2bfloat16(y.w - __bfloat162float(h3));
    __nv_bfloat162 ph0(h0, h1), ph1(h2, h3), pl0(l0, l1), pl1(l2, l3);
    uint2 uh = { *(unsigned*)&ph0, *(unsigned*)&ph1 };
    uint2 ul = { *(unsigned*)&pl0, *(unsigned*)&pl1 };
    size_t o = (size_t)n * 256 + half * 128 + lane * 4;
    *reinterpret_cast<uint2*>(&cath[o]) = uh;
    *reinterpret_cast<uint2*>(&catl[o]) = ul;
}

// ================= launch =================
extern "C" void kernel_launch(void* const* d_in, const int* in_sizes, int n_in,
                              void* d_out, int out_size) {
    const float* x_in  = (const float*)d_in[0];
    const float* WL    = (const float*)d_in[1];
    const float* bL    = (const float*)d_in[2];
    const float* WG    = (const float*)d_in[3];
    const float* bG    = (const float*)d_in[4];
    const float* linW  = (const float*)d_in[5];
    const float* linb  = (const float*)d_in[6];
    const float* ln_g  = (const float*)d_in[7];
    const float* ln_b  = (const float*)d_in[8];
    const float* finW  = (const float*)d_in[9];
    const float* finb  = (const float*)d_in[10];
    const int*   Ge    = (const int*)d_in[11];
    const int*   Le    = (const int*)d_in[12];
    int E_G = in_sizes[11] / 2;
    int E_L = in_sizes[12] / 2;
    float* out = (float*)d_out;

    float *px, *phG, *phL, *pdinvG, *pdinvL, *pcoefG, *pcoefL;
    int *pdegG, *pdegL, *prowG, *prowL, *pfillG, *pfillL, *pcolG, *pcolL, *pbsum;
    __nv_bfloat16 *pxh, *pxl, *pcath, *pcatl;
    __nv_bfloat16 *pBGh, *pBGl, *pBLh, *pBLl, *pBlinh, *pBlinl, *pBfinh, *pBfinl;
    cudaGetSymbolAddress((void**)&px,     g_x);
    cudaGetSymbolAddress((void**)&phG,    g_hG);
    cudaGetSymbolAddress((void**)&phL,    g_hL);
    cudaGetSymbolAddress((void**)&pxh,    g_xh);
    cudaGetSymbolAddress((void**)&pxl,    g_xl);
    cudaGetSymbolAddress((void**)&pcath,  g_cath);
    cudaGetSymbolAddress((void**)&pcatl,  g_catl);
    cudaGetSymbolAddress((void**)&pdegG,  g_degG);
    cudaGetSymbolAddress((void**)&pdegL,  g_degL);
    cudaGetSymbolAddress((void**)&pdinvG, g_dinvG);
    cudaGetSymbolAddress((void**)&pdinvL, g_dinvL);
    cudaGetSymbolAddress((void**)&prowG,  g_rowptrG);
    cudaGetSymbolAddress((void**)&prowL,  g_rowptrL);
    cudaGetSymbolAddress((void**)&pfillG, g_fillG);
    cudaGetSymbolAddress((void**)&pfillL, g_fillL);
    cudaGetSymbolAddress((void**)&pcolG,  g_colG);
    cudaGetSymbolAddress((void**)&pcolL,  g_colL);
    cudaGetSymbolAddress((void**)&pcoefG, g_coefG);
    cudaGetSymbolAddress((void**)&pcoefL, g_coefL);
    cudaGetSymbolAddress((void**)&pbsum,  g_bsum);
    cudaGetSymbolAddress((void**)&pBGh,   g_BGh);
    cudaGetSymbolAddress((void**)&pBGl,   g_BGl);
    cudaGetSymbolAddress((void**)&pBLh,   g_BLh);
    cudaGetSymbolAddress((void**)&pBLl,   g_BLl);
    cudaGetSymbolAddress((void**)&pBlinh, g_Blinh);
    cudaGetSymbolAddress((void**)&pBlinl, g_Blinl);
    cudaGetSymbolAddress((void**)&pBfinh, g_Bfinh);
    cudaGetSymbolAddress((void**)&pBfinl, g_Bfinl);

    const int GEMM_SMEM = 2 * STAGE * 2;   // 81920 bytes
    static int attr_set = 0;
    if (!attr_set) {
        cudaFuncSetAttribute(gemm_bf16x3_kernel, cudaFuncAttributeMaxDynamicSharedMemorySize, GEMM_SMEM);
        attr_set = 1;
    }

    // ---- ordered so the 4th kernel is the first (dual-branch) GEMM ----
    zero_deg_kernel<<<NB196, 256>>>(pdegG, pdegL, NN);
    wsplit_all_kernel<<<dim3(4, 8, 10), dim3(32, 8)>>>(WG, WL, linW, finW,
        pBGh, pBGl, pBLh, pBLl, pBlinh, pBlinl, pBfinh, pBfinl);
    init_split_kernel<<<(NN * HH / 4 + 255) / 256, 256>>>((const float4*)x_in,
        (float4*)px, pxh, pxl);
    gemm_bf16x3_kernel<<<dim3(TILES, 2), 128, GEMM_SMEM>>>(
        pxh, pxl, HH, pBGh, pBGl, pBLh, pBLl, phG, phL,
        nullptr, nullptr, nullptr, NN, HH, HH);
    // CSR setup
    count_deg_kernel<<<(E_G + E_L + 255) / 256, 256>>>(Ge + E_G, E_G, Le + E_L, E_L, pdegG, pdegL);
    make_dinv_kernel<<<NB196, 256>>>(pdegG, pdinvG, pdegL, pdinvL, NN);
    scan_block_kernel<<<dim3(NB196, 2), 256>>>(pdegG, pdegL, prowG, prowL, pbsum, NN);
    scan_aux_kernel<<<1, 32>>>(pbsum, NB196);
    scan_add_kernel<<<dim3(NB196, 2), 256>>>(prowG, prowL, pfillG, pfillL, pbsum, NN, E_G, E_L);
    int fe = (E_G > E_L ? E_G : E_L);
    fill_csr_kernel<<<dim3((fe + 255) / 256, 2), 256>>>(Ge, E_G, Le, E_L,
        pfillG, pfillL, pcolG, pcolL, pcoefG, pcoefL, pdinvG, pdinvL);

    int gatherBlocks = (NN * 32 + 255) / 256;

    for (int i = 0; i < DEPTH; i++) {
        if (i > 0) {
            size_t wo = (size_t)i * HH * HH;
            gemm_bf16x3_kernel<<<dim3(TILES, 2), 128, GEMM_SMEM>>>(
                pxh, pxl, HH, pBGh + wo, pBGl + wo, pBLh + wo, pBLl + wo,
                phG, phL, nullptr, nullptr, nullptr, NN, HH, HH);
        }
        int res = (i > 0) ? 1 : 0;
        gather_ln_kernel<<<dim3(gatherBlocks, 2), 256>>>(
            (const float4*)phG, (const float4*)phL, (const float4*)px,
            prowG, prowL, pcolG, pcolL, pcoefG, pcoefL, pdinvG, pdinvL,
            (const float4*)(bG + (size_t)i * HH), (const float4*)(bL + (size_t)i * HH),
            (const float4*)ln_g, (const float4*)ln_b, pcath, pcatl, res);
        size_t lo = (size_t)i * HH * 2 * HH;
        gemm_bf16x3_kernel<<<dim3(TILES, 1), 128, GEMM_SMEM>>>(
            pcath, pcatl, 2 * HH, pBlinh + lo, pBlinl + lo, nullptr, nullptr,
            px, nullptr, pxh, pxl, linb + (size_t)i * HH, NN, 2 * HH, HH);
    }

    gemm_bf16x3_kernel<<<dim3(TILES, 1), 128, GEMM_SMEM>>>(
        pxh, pxl, HH, pBfinh, pBfinl, nullptr, nullptr,
        out, nullptr, nullptr, nullptr, finb, NN, HH, OUTC);
    cudaMemcpyAsync(out + (size_t)NN * OUTC, px, (size_t)NN * HH * sizeof(float),
                    cudaMemcpyDeviceToDevice);
}

// round 7
// speedup vs baseline: 3.8120x; 3.8120x over previous
#include <cuda_runtime.h>
#include <cuda_bf16.h>
#include <cuda_pipeline.h>
#include <mma.h>
#include <cstdint>

using namespace nvcuda;

#define NN 50000
#define HH 128
#define OUTC 64
#define DEPTH 3
#define LN_EPS 1e-5f
#define EGMAX 600000
#define ELMAX 400000
#define NB196 196
#define TILES 391          // ceil(NN/128)
#define LDT 40             // smem leading dim (bf16): 80B rows -> conflict-free LDSM
#define TSZ (128 * LDT)
#define STAGE (4 * TSZ)

// ================= scratch =================
__device__ float g_x[NN * HH];
__device__ float g_hG[NN * HH];
__device__ float g_hL[NN * HH];
__device__ __nv_bfloat16 g_xh[NN * HH];
__device__ __nv_bfloat16 g_xl[NN * HH];
__device__ __nv_bfloat16 g_cath[NN * 2 * HH];
__device__ __nv_bfloat16 g_catl[NN * 2 * HH];
__device__ int   g_degG[NN];
__device__ int   g_degL[NN];
__device__ float g_dinvG[NN];
__device__ float g_dinvL[NN];
__device__ int   g_rowptrG[NN + 1];
__device__ int   g_rowptrL[NN + 1];
__device__ int   g_fillG[NN];
__device__ int   g_fillL[NN];
__device__ int   g_colG[EGMAX];
__device__ int   g_colL[ELMAX];
__device__ float g_coefG[EGMAX];
__device__ float g_coefL[ELMAX];
__device__ int   g_bsum[2][256];
__device__ __nv_bfloat16 g_BGh[DEPTH * HH * HH];
__device__ __nv_bfloat16 g_BGl[DEPTH * HH * HH];
__device__ __nv_bfloat16 g_BLh[DEPTH * HH * HH];
__device__ __nv_bfloat16 g_BLl[DEPTH * HH * HH];
__device__ __nv_bfloat16 g_Blinh[DEPTH * HH * 2 * HH];
__device__ __nv_bfloat16 g_Blinl[DEPTH * HH * 2 * HH];
__device__ __nv_bfloat16 g_Bfinh[OUTC * HH];
__device__ __nv_bfloat16 g_Bfinl[OUTC * HH];

// ================= setup kernels =================
__global__ void zero_deg_kernel(int* degG, int* degL, int n) {
    int i = blockIdx.x * blockDim.x + threadIdx.x;
    if (i < n) { degG[i] = 0; degL[i] = 0; }
}

__global__ void wsplit_all_kernel(const float* __restrict__ WG, const float* __restrict__ WLp,
                                  const float* __restrict__ linW, const float* __restrict__ finW,
                                  __nv_bfloat16* BGh, __nv_bfloat16* BGl,
                                  __nv_bfloat16* BLh, __nv_bfloat16* BLl,
                                  __nv_bfloat16* Blinh, __nv_bfloat16* Blinl,
                                  __nv_bfloat16* Bfinh, __nv_bfloat16* Bfinl) {
    int seg = blockIdx.z;
    const float* W;
    __nv_bfloat16 *Bh, *Bl;
    int K, N;
    if (seg < 3)      { K = HH;     N = HH;   W = WG  + (size_t)seg * HH * HH;           Bh = BGh  + (size_t)seg * HH * HH;           Bl = BGl  + (size_t)seg * HH * HH; }
    else if (seg < 6) { K = HH;     N = HH;   W = WLp + (size_t)(seg - 3) * HH * HH;     Bh = BLh  + (size_t)(seg - 3) * HH * HH;     Bl = BLl  + (size_t)(seg - 3) * HH * HH; }
    else if (seg < 9) { K = 2 * HH; N = HH;   W = linW + (size_t)(seg - 6) * 2 * HH * HH; Bh = Blinh + (size_t)(seg - 6) * 2 * HH * HH; Bl = Blinl + (size_t)(seg - 6) * 2 * HH * HH; }
    else              { K = HH;     N = OUTC; W = finW;                                   Bh = Bfinh;                                   Bl = Bfinl; }
    int n0 = blockIdx.x * 32, k0 = blockIdx.y * 32;
    if (n0 >= N || k0 >= K) return;
    __shared__ float t[32][33];
    int tx = threadIdx.x, ty = threadIdx.y;
    #pragma unroll
    for (int i = 0; i < 4; i++)
        t[ty + i * 8][tx] = W[(size_t)(k0 + ty + i * 8) * N + n0 + tx];
    __syncthreads();
    #pragma unroll
    for (int i = 0; i < 4; i++) {
        float v = t[tx][ty + i * 8];
        __nv_bfloat16 h = __float2bfloat16(v);
        __nv_bfloat16 l = __float2bfloat16(v - __bfloat162float(h));
        size_t o = (size_t)(n0 + ty + i * 8) * K + k0 + tx;
        Bh[o] = h;
        Bl[o] = l;
    }
}

__global__ void init_split_kernel(const float4* __restrict__ xin4, float4* __restrict__ px4,
                                  __nv_bfloat16* __restrict__ xh, __nv_bfloat16* __restrict__ xl) {
    int i = blockIdx.x * blockDim.x + threadIdx.x;
    if (i >= NN * HH / 4) return;
    float4 v = xin4[i];
    px4[i] = v;
    __nv_bfloat16 h0 = __float2bfloat16(v.x), h1 = __float2bfloat16(v.y);
    __nv_bfloat16 h2 = __float2bfloat16(v.z), h3 = __float2bfloat16(v.w);
    __nv_bfloat16 l0 = __float2bfloat16(v.x - __bfloat162float(h0));
    __nv_bfloat16 l1 = __float2bfloat16(v.y - __bfloat162float(h1));
    __nv_bfloat16 l2 = __float2bfloat16(v.z - __bfloat162float(h2));
    __nv_bfloat16 l3 = __float2bfloat16(v.w - __bfloat162float(h3));
    __nv_bfloat162 ph0(h0, h1), ph1(h2, h3), pl0(l0, l1), pl1(l2, l3);
    uint2 uh = { *(unsigned*)&ph0, *(unsigned*)&ph1 };
    uint2 ul = { *(unsigned*)&pl0, *(unsigned*)&pl1 };
    *reinterpret_cast<uint2*>(&xh[i * 4]) = uh;
    *reinterpret_cast<uint2*>(&xl[i * 4]) = ul;
}

__global__ void count_deg_kernel(const int* __restrict__ dstG, int EG,
                                 const int* __restrict__ dstL, int EL,
                                 int* __restrict__ degG, int* __restrict__ degL) {
    int i = blockIdx.x * blockDim.x + threadIdx.x;
    if (i < EG) atomicAdd(&degG[dstG[i]], 1);
    else if (i < EG + EL) atomicAdd(&degL[dstL[i - EG]], 1);
}
__global__ void make_dinv_kernel(const int* __restrict__ degG, float* __restrict__ dinvG,
                                 const int* __restrict__ degL, float* __restrict__ dinvL, int n) {
    int i = blockIdx.x * blockDim.x + threadIdx.x;
    if (i < n) {
        dinvG[i] = rsqrtf((float)degG[i] + 2.0f);
        dinvL[i] = rsqrtf((float)degL[i] + 2.0f);
    }
}
__global__ void scan_block_kernel(const int* __restrict__ degG, const int* __restrict__ degL,
                                  int* __restrict__ rowG, int* __restrict__ rowL,
                                  int* __restrict__ bsum, int n) {
    __shared__ int s[256];
    const int* deg = blockIdx.y ? degL : degG;
    int* rowptr = blockIdx.y ? rowL : rowG;
    int* bs = bsum + blockIdx.y * 256;
    int i = blockIdx.x * 256 + threadIdx.x;
    int v = (i < n) ? deg[i] : 0;
    s[threadIdx.x] = v;
    __syncthreads();
    #pragma unroll
    for (int o = 1; o < 256; o <<= 1) {
        int t = (threadIdx.x >= o) ? s[threadIdx.x - o] : 0;
        __syncthreads();
        s[threadIdx.x] += t;
        __syncthreads();
    }
    if (i < n) rowptr[i] = s[threadIdx.x] - v;
    if (threadIdx.x == 255) bs[blockIdx.x] = s[255];
}
__global__ void scan_aux_kernel(int* bsum, int nb) {
    if (threadIdx.x == 0) {
        for (int y = 0; y < 2; y++) {
            int run = 0;
            int* b = bsum + y * 256;
            for (int i = 0; i < nb; i++) { int t = b[i]; b[i] = run; run += t; }
        }
    }
}
__global__ void scan_add_kernel(int* __restrict__ rowG, int* __restrict__ rowL,
                                int* __restrict__ fillG, int* __restrict__ fillL,
                                const int* __restrict__ bsum, int n, int EG, int EL) {
    int* rowptr = blockIdx.y ? rowL : rowG;
    int* fill = blockIdx.y ? fillL : fillG;
    const int* bs = bsum + blockIdx.y * 256;
    int E = blockIdx.y ? EL : EG;
    int i = blockIdx.x * 256 + threadIdx.x;
    if (i < n) {
        int v = rowptr[i] + bs[i >> 8];
        rowptr[i] = v;
        fill[i] = v;
    }
    if (i == 0) rowptr[n] = E;
}
__global__ void fill_csr_kernel(const int* __restrict__ Ge, int EG, const int* __restrict__ Le, int EL,
                                int* __restrict__ fillG, int* __restrict__ fillL,
                                int* __restrict__ colG, int* __restrict__ colL,
                                float* __restrict__ coefG, float* __restrict__ coefL,
                                const float* __restrict__ dinvG, const float* __restrict__ dinvL) {
    int e = blockIdx.x * blockDim.x + threadIdx.x;
    const int* src; const int* dst; int* fill; int* col; float* coef; const float* dinv; int E;
    if (blockIdx.y == 0) { src = Ge; dst = Ge + EG; fill = fillG; col = colG; coef = coefG; dinv = dinvG; E = EG; }
    else                 { src = Le; dst = Le + EL; fill = fillL; col = colL; coef = coefL; dinv = dinvL; E = EL; }
    if (e < E) {
        int s = src[e], d = dst[e];
        int p = atomicAdd(&fill[d], 1);
        col[p] = s;
        coef[p] = dinv[s] * dinv[d];
    }
}

// ================= bf16x3 GEMM: compile-time NOUT, 8 warps, 32x64 warp tiles ============
template <int NOUT>
__global__ __launch_bounds__(256)
void gemm_bf16x3_kernel(const __nv_bfloat16* __restrict__ Ah, const __nv_bfloat16* __restrict__ Al,
                        int lda,
                        const __nv_bfloat16* __restrict__ Bh0, const __nv_bfloat16* __restrict__ Bl0,
                        const __nv_bfloat16* __restrict__ Bh1, const __nv_bfloat16* __restrict__ Bl1,
                        float* __restrict__ C0, float* __restrict__ C1,
                        __nv_bfloat16* __restrict__ Csh, __nv_bfloat16* __restrict__ Csl,
                        const float* __restrict__ bias, int M, int K) {
    constexpr int HALFN = NOUT / 2;    // 64 or 32
    constexpr int NF = HALFN / 16;     // 4 or 2
    extern __shared__ __nv_bfloat16 sm[];
    const __nv_bfloat16* gBh = blockIdx.y ? Bh1 : Bh0;
    const __nv_bfloat16* gBl = blockIdx.y ? Bl1 : Bl0;
    float* C = blockIdx.y ? C1 : C0;

    const int tid = threadIdx.x;
    const int wid = tid >> 5;
    const int lane = tid & 31;
    const int wr = wid >> 1;        // 0..3, 32 rows each
    const int wc = wid & 1;         // 0..1
    const int row0 = blockIdx.x * 128;

    wmma::fragment<wmma::accumulator, 16, 16, 16, float> acc[2][NF];
    #pragma unroll
    for (int i = 0; i < 2; i++)
        #pragma unroll
        for (int j = 0; j < NF; j++)
            wmma::fill_fragment(acc[i][j], 0.0f);

    const int nc = K >> 5;

    auto load_stage = [&](int s, int kc) {
        __nv_bfloat16* base = sm + s * STAGE;
        #pragma unroll
        for (int c = tid; c < 512; c += 256) {
            int r = c >> 2;
            int ko = (c & 3) * 8;
            int gr = row0 + r;
            if (gr < M) {
                size_t go = (size_t)gr * lda + kc * 32 + ko;
                __pipeline_memcpy_async(&base[r * LDT + ko], &Ah[go], 16);
                __pipeline_memcpy_async(&base[TSZ + r * LDT + ko], &Al[go], 16);
            }
        }
        #pragma unroll
        for (int c = tid; c < NOUT * 4; c += 256) {
            int r = c >> 2;
            int ko = (c & 3) * 8;
            size_t go = (size_t)r * K + kc * 32 + ko;
            __pipeline_memcpy_async(&base[2 * TSZ + r * LDT + ko], &gBh[go], 16);
            __pipeline_memcpy_async(&base[3 * TSZ + r * LDT + ko], &gBl[go], 16);
        }
    };

    load_stage(0, 0);
    __pipeline_commit();

    for (int kc = 0; kc < nc; kc++) {
        if (kc + 1 < nc) {
            load_stage((kc + 1) & 1, kc + 1);
            __pipeline_commit();
            __pipeline_wait_prior(1);
        } else {
            __pipeline_wait_prior(0);
        }
        __syncthreads();

        __nv_bfloat16* Ahs = sm + (kc & 1) * STAGE;
        __nv_bfloat16* Als = Ahs + TSZ;
        __nv_bfloat16* Bhs = Ahs + 2 * TSZ;
        __nv_bfloat16* Bls = Ahs + 3 * TSZ;

        #pragma unroll
        for (int ks = 0; ks < 32; ks += 16) {
            wmma::fragment<wmma::matrix_a, 16, 16, 16, __nv_bfloat16, wmma::row_major> fah[2], fal[2];
            #pragma unroll
            for (int i = 0; i < 2; i++) {
                wmma::load_matrix_sync(fah[i], &Ahs[(wr * 32 + i * 16) * LDT + ks], LDT);
                wmma::load_matrix_sync(fal[i], &Als[(wr * 32 + i * 16) * LDT + ks], LDT);
            }
            wmma::fragment<wmma::matrix_b, 16, 16, 16, __nv_bfloat16, wmma::col_major> fb[NF];
            // pass 1+2: B-hi vs A-hi, A-lo
            #pragma unroll
            for (int j = 0; j < NF; j++)
                wmma::load_matrix_sync(fb[j], &Bhs[(wc * HALFN + j * 16) * LDT + ks], LDT);
            #pragma unroll
            for (int i = 0; i < 2; i++)
                #pragma unroll
                for (int j = 0; j < NF; j++)
                    wmma::mma_sync(acc[i][j], fah[i], fb[j], acc[i][j]);
            #pragma unroll
            for (int i = 0; i < 2; i++)
                #pragma unroll
                for (int j = 0; j < NF; j++)
                    wmma::mma_sync(acc[i][j], fal[i], fb[j], acc[i][j]);
            // pass 3: B-lo vs A-hi
            #pragma unroll
            for (int j = 0; j < NF; j++)
                wmma::load_matrix_sync(fb[j], &Bls[(wc * HALFN + j * 16) * LDT + ks], LDT);
            #pragma unroll
            for (int i = 0; i < 2; i++)
                #pragma unroll
                for (int j = 0; j < NF; j++)
                    wmma::mma_sync(acc[i][j], fah[i], fb[j], acc[i][j]);
        }
        __syncthreads();
    }

    // epilogue via smem staging
    float* st = reinterpret_cast<float*>(sm) + wid * 320;
    #pragma unroll
    for (int i = 0; i < 2; i++)
        #pragma unroll
        for (int j = 0; j < NF; j++) {
            wmma::store_matrix_sync(st, acc[i][j], 20, wmma::mem_row_major);
            __syncwarp();
            #pragma unroll
            for (int e = 0; e < 8; e++) {
                int idx = lane + e * 32;
                int r = idx >> 4;
                int c = idx & 15;
                int grow = row0 + wr * 32 + i * 16 + r;
                int gcol = wc * HALFN + j * 16 + c;
                if (grow < M) {
                    float v = st[r * 20 + c];
                    if (bias) v += __ldg(&bias[gcol]);
                    C[(size_t)grow * NOUT + gcol] = v;
                    if (Csh) {
                        __nv_bfloat16 h = __float2bfloat16(v);
                        __nv_bfloat16 l = __float2bfloat16(v - __bfloat162float(h));
                        Csh[(size_t)grow * NOUT + gcol] = h;
                        Csl[(size_t)grow * NOUT + gcol] = l;
                    }
                }
            }
            __syncwarp();
        }
}

// ================= fused gather + LN + ReLU + residual + concat (bf16-split output) =========
__global__ void gather_ln_kernel(const float4* __restrict__ hG4, const float4* __restrict__ hL4,
                                 const float4* __restrict__ x4,
                                 const int* __restrict__ rowG, const int* __restrict__ rowL,
                                 const int* __restrict__ colG, const int* __restrict__ colL,
                                 const float* __restrict__ coefG, const float* __restrict__ coefL,
                                 const float* __restrict__ dinvG, const float* __restrict__ dinvL,
                                 const float4* __restrict__ biasG4, const float4* __restrict__ biasL4,
                                 const float4* __restrict__ g4, const float4* __restrict__ b4,
                                 __nv_bfloat16* __restrict__ cath, __nv_bfloat16* __restrict__ catl,
                                 int residual) {
    int warp = (blockIdx.x * blockDim.x + threadIdx.x) >> 5;
    int lane = threadIdx.x & 31;
    if (warp >= NN) return;
    int n = warp;
    int half = blockIdx.y;

    const float4* h4 = half ? hL4 : hG4;
    const int* rowptr = half ? rowL : rowG;
    const int* col = half ? colL : colG;
    const float* coef = half ? coefL : coefG;
    const float* dinv = half ? dinvL : dinvG;
    const float4* bias4 = half ? biasL4 : biasG4;

    float dv = __ldg(&dinv[n]);
    float sl = 2.0f * dv * dv;
    float4 h = h4[n * 32 + lane];
    float4 bb = __ldg(&bias4[lane]);
    float4 acc;
    acc.x = h.x * sl + bb.x;
    acc.y = h.y * sl + bb.y;
    acc.z = h.z * sl + bb.z;
    acc.w = h.w * sl + bb.w;

    int e = __ldg(&rowptr[n]);
    int e1 = __ldg(&rowptr[n + 1]);
    for (; e + 1 < e1; e += 2) {
        int s0 = __ldg(&col[e]);
        int s1 = __ldg(&col[e + 1]);
        float c0 = __ldg(&coef[e]);
        float c1 = __ldg(&coef[e + 1]);
        float4 v0 = h4[s0 * 32 + lane];
        float4 v1 = h4[s1 * 32 + lane];
        acc.x += c0 * v0.x + c1 * v1.x;
        acc.y += c0 * v0.y + c1 * v1.y;
        acc.z += c0 * v0.z + c1 * v1.z;
        acc.w += c0 * v0.w + c1 * v1.w;
    }
    if (e < e1) {
        int s0 = __ldg(&col[e]);
        float c0 = __ldg(&coef[e]);
        float4 v0 = h4[s0 * 32 + lane];
        acc.x += c0 * v0.x; acc.y += c0 * v0.y; acc.z += c0 * v0.z; acc.w += c0 * v0.w;
    }

    float s1 = acc.x + acc.y + acc.z + acc.w;
    float s2 = acc.x * acc.x + acc.y * acc.y + acc.z * acc.z + acc.w * acc.w;
    #pragma unroll
    for (int o = 16; o > 0; o >>= 1) {
        s1 += __shfl_xor_sync(0xffffffffu, s1, o);
        s2 += __shfl_xor_sync(0xffffffffu, s2, o);
    }
    float mu = s1 * (1.0f / HH);
    float var = s2 * (1.0f / HH) - mu * mu;
    float rstd = rsqrtf(var + LN_EPS);

    float4 gg = __ldg(&g4[lane]);
    float4 be = __ldg(&b4[lane]);
    float4 y;
    y.x = fmaxf((acc.x - mu) * rstd * gg.x + be.x, 0.0f);
    y.y = fmaxf((acc.y - mu) * rstd * gg.y + be.y, 0.0f);
    y.z = fmaxf((acc.z - mu) * rstd * gg.z + be.z, 0.0f);
    y.w = fmaxf((acc.w - mu) * rstd * gg.w + be.w, 0.0f);
    if (residual) {
        float4 xv = x4[n * 32 + lane];
        y.x += xv.x; y.y += xv.y; y.z += xv.z; y.w += xv.w;
    }
    __nv_bfloat16 h0 = __float2bfloat16(y.x), h1 = __float2bfloat16(y.y);
    __nv_bfloat16 h2 = __float2bfloat16(y.z), h3 = __float2bfloat16(y.w);
    __nv_bfloat16 l0 = __float2bfloat16(y.x - __bfloat162float(h0));
    __nv_bfloat16 l1 = __float2bfloat16(y.y - __bfloat162float(h1));
    __nv_bfloat16 l2 = __float2bfloat16(y.z - __bfloat162float(h2));
    __nv_bfloat16 l3 = __float2bfloat16(y.w - __bfloat162float(h3));
    __nv_bfloat162 ph0(h0, h1), ph1(h2, h3), pl0(l0, l1), pl1(l2, l3);
    uint2 uh = { *(unsigned*)&ph0, *(unsigned*)&ph1 };
    uint2 ul = { *(unsigned*)&pl0, *(unsigned*)&pl1 };
    size_t o = (size_t)n * 256 + half * 128 + lane * 4;
    *reinterpret_cast<uint2*>(&cath[o]) = uh;
    *reinterpret_cast<uint2*>(&catl[o]) = ul;
}

// ================= launch =================
extern "C" void kernel_launch(void* const* d_in, const int* in_sizes, int n_in,
                              void* d_out, int out_size) {
    const float* x_in  = (const float*)d_in[0];
    const float* WL    = (const float*)d_in[1];
    const float* bL    = (const float*)d_in[2];
    const float* WG    = (const float*)d_in[3];
    const float* bG    = (const float*)d_in[4];
    const float* linW  = (const float*)d_in[5];
    const float* linb  = (const float*)d_in[6];
    const float* ln_g  = (const float*)d_in[7];
    const float* ln_b  = (const float*)d_in[8];
    const float* finW  = (const float*)d_in[9];
    const float* finb  = (const float*)d_in[10];
    const int*   Ge    = (const int*)d_in[11];
    const int*   Le    = (const int*)d_in[12];
    int E_G = in_sizes[11] / 2;
    int E_L = in_sizes[12] / 2;
    float* out = (float*)d_out;

    float *px, *phG, *phL, *pdinvG, *pdinvL, *pcoefG, *pcoefL;
    int *pdegG, *pdegL, *prowG, *prowL, *pfillG, *pfillL, *pcolG, *pcolL, *pbsum;
    __nv_bfloat16 *pxh, *pxl, *pcath, *pcatl;
    __nv_bfloat16 *pBGh, *pBGl, *pBLh, *pBLl, *pBlinh, *pBlinl, *pBfinh, *pBfinl;
    cudaGetSymbolAddress((void**)&px,     g_x);
    cudaGetSymbolAddress((void**)&phG,    g_hG);
    cudaGetSymbolAddress((void**)&phL,    g_hL);
    cudaGetSymbolAddress((void**)&pxh,    g_xh);
    cudaGetSymbolAddress((void**)&pxl,    g_xl);
    cudaGetSymbolAddress((void**)&pcath,  g_cath);
    cudaGetSymbolAddress((void**)&pcatl,  g_catl);
    cudaGetSymbolAddress((void**)&pdegG,  g_degG);
    cudaGetSymbolAddress((void**)&pdegL,  g_degL);
    cudaGetSymbolAddress((void**)&pdinvG, g_dinvG);
    cudaGetSymbolAddress((void**)&pdinvL, g_dinvL);
    cudaGetSymbolAddress((void**)&prowG,  g_rowptrG);
    cudaGetSymbolAddress((void**)&prowL,  g_rowptrL);
    cudaGetSymbolAddress((void**)&pfillG, g_fillG);
    cudaGetSymbolAddress((void**)&pfillL, g_fillL);
    cudaGetSymbolAddress((void**)&pcolG,  g_colG);
    cudaGetSymbolAddress((void**)&pcolL,  g_colL);
    cudaGetSymbolAddress((void**)&pcoefG, g_coefG);
    cudaGetSymbolAddress((void**)&pcoefL, g_coefL);
    cudaGetSymbolAddress((void**)&pbsum,  g_bsum);
    cudaGetSymbolAddress((void**)&pBGh,   g_BGh);
    cudaGetSymbolAddress((void**)&pBGl,   g_BGl);
    cudaGetSymbolAddress((void**)&pBLh,   g_BLh);
    cudaGetSymbolAddress((void**)&pBLl,   g_BLl);
    cudaGetSymbolAddress((void**)&pBlinh, g_Blinh);
    cudaGetSymbolAddress((void**)&pBlinl, g_Blinl);
    cudaGetSymbolAddress((void**)&pBfinh, g_Bfinh);
    cudaGetSymbolAddress((void**)&pBfinl, g_Bfinl);

    const int GEMM_SMEM = 2 * STAGE * 2;   // 81920 bytes
    static int attr_set = 0;
    if (!attr_set) {
        cudaFuncSetAttribute(gemm_bf16x3_kernel<128>, cudaFuncAttributeMaxDynamicSharedMemorySize, GEMM_SMEM);
        cudaFuncSetAttribute(gemm_bf16x3_kernel<64>,  cudaFuncAttributeMaxDynamicSharedMemorySize, GEMM_SMEM);
        attr_set = 1;
    }

    // ---- ordered so the 4th kernel is the first (dual-branch) GEMM ----
    zero_deg_kernel<<<NB196, 256>>>(pdegG, pdegL, NN);
    wsplit_all_kernel<<<dim3(4, 8, 10), dim3(32, 8)>>>(WG, WL, linW, finW,
        pBGh, pBGl, pBLh, pBLl, pBlinh, pBlinl, pBfinh, pBfinl);
    init_split_kernel<<<(NN * HH / 4 + 255) / 256, 256>>>((const float4*)x_in,
        (float4*)px, pxh, pxl);
    gemm_bf16x3_kernel<128><<<dim3(TILES, 2), 256, GEMM_SMEM>>>(
        pxh, pxl, HH, pBGh, pBGl, pBLh, pBLl, phG, phL,
        nullptr, nullptr, nullptr, NN, HH);
    // CSR setup
    count_deg_kernel<<<(E_G + E_L + 255) / 256, 256>>>(Ge + E_G, E_G, Le + E_L, E_L, pdegG, pdegL);
    make_dinv_kernel<<<NB196, 256>>>(pdegG, pdinvG, pdegL, pdinvL, NN);
    scan_block_kernel<<<dim3(NB196, 2), 256>>>(pdegG, pdegL, prowG, prowL, pbsum, NN);
    scan_aux_kernel<<<1, 32>>>(pbsum, NB196);
    scan_add_kernel<<<dim3(NB196, 2), 256>>>(prowG, prowL, pfillG, pfillL, pbsum, NN, E_G, E_L);
    int fe = (E_G > E_L ? E_G : E_L);
    fill_csr_kernel<<<dim3((fe + 255) / 256, 2), 256>>>(Ge, E_G, Le, E_L,
        pfillG, pfillL, pcolG, pcolL, pcoefG, pcoefL, pdinvG, pdinvL);

    int gatherBlocks = (NN * 32 + 255) / 256;

    for (int i = 0; i < DEPTH; i++) {
        if (i > 0) {
            size_t wo = (size_t)i * HH * HH;
            gemm_bf16x3_kernel<128><<<dim3(TILES, 2), 256, GEMM_SMEM>>>(
                pxh, pxl, HH, pBGh + wo, pBGl + wo, pBLh + wo, pBLl + wo,
                phG, phL, nullptr, nullptr, nullptr, NN, HH);
        }
        int res = (i > 0) ? 1 : 0;
        gather_ln_kernel<<<dim3(gatherBlocks, 2), 256>>>(
            (const float4*)phG, (const float4*)phL, (const float4*)px,
            prowG, prowL, pcolG, pcolL, pcoefG, pcoefL, pdinvG, pdinvL,
            (const float4*)(bG + (size_t)i * HH), (const float4*)(bL + (size_t)i * HH),
            (const float4*)ln_g, (const float4*)ln_b, pcath, pcatl, res);
        size_t lo = (size_t)i * HH * 2 * HH;
        gemm_bf16x3_kernel<128><<<dim3(TILES, 1), 256, GEMM_SMEM>>>(
            pcath, pcatl, 2 * HH, pBlinh + lo, pBlinl + lo, nullptr, nullptr,
            px, nullptr, pxh, pxl, linb + (size_t)i * HH, NN, 2 * HH);
    }

    gemm_bf16x3_kernel<64><<<dim3(TILES, 1), 256, GEMM_SMEM>>>(
        pxh, pxl, HH, pBfinh, pBfinl, nullptr, nullptr,
        out, nullptr, nullptr, nullptr, finb, NN, HH);
    cudaMemcpyAsync(out + (size_t)NN * OUTC, px, (size_t)NN * HH * sizeof(float),
                    cudaMemcpyDeviceToDevice);
}

// round 8
// speedup vs baseline: 4.4468x; 1.1665x over previous
#include <cuda_runtime.h>
#include <cuda_bf16.h>
#include <cuda_fp16.h>
#include <cuda_pipeline.h>
#include <mma.h>
#include <cstdint>

using namespace nvcuda;

#define NN 50000
#define HH 128
#define OUTC 64
#define DEPTH 3
#define LN_EPS 1e-5f
#define EGMAX 600000
#define ELMAX 400000
#define NB196 196
#define TILES 391          // ceil(NN/128)
#define LDT 40             // smem leading dim (bf16): 80B rows -> conflict-free LDSM
#define TSZ (128 * LDT)
#define STAGE (4 * TSZ)

// ================= scratch =================
__device__ float g_x[NN * HH];
__device__ __half g_hG[NN * HH];          // branch GEMM outputs in fp16 (gather input)
__device__ __half g_hL[NN * HH];
__device__ __nv_bfloat16 g_xh[NN * HH];
__device__ __nv_bfloat16 g_xl[NN * HH];
__device__ __nv_bfloat16 g_cath[NN * 2 * HH];
__device__ __nv_bfloat16 g_catl[NN * 2 * HH];
__device__ int   g_degG[NN];
__device__ int   g_degL[NN];
__device__ float g_dinvG[NN];
__device__ float g_dinvL[NN];
__device__ int   g_rowptrG[NN + 1];
__device__ int   g_rowptrL[NN + 1];
__device__ int   g_fillG[NN];
__device__ int   g_fillL[NN];
__device__ int   g_colG[EGMAX];
__device__ int   g_colL[ELMAX];
__device__ float g_coefG[EGMAX];
__device__ float g_coefL[ELMAX];
__device__ int   g_bsum[2][256];
__device__ __nv_bfloat16 g_BGh[DEPTH * HH * HH];
__device__ __nv_bfloat16 g_BGl[DEPTH * HH * HH];
__device__ __nv_bfloat16 g_BLh[DEPTH * HH * HH];
__device__ __nv_bfloat16 g_BLl[DEPTH * HH * HH];
__device__ __nv_bfloat16 g_Blinh[DEPTH * HH * 2 * HH];
__device__ __nv_bfloat16 g_Blinl[DEPTH * HH * 2 * HH];
__device__ __nv_bfloat16 g_Bfinh[OUTC * HH];
__device__ __nv_bfloat16 g_Bfinl[OUTC * HH];

// ================= setup kernels =================
__global__ void zero_deg_kernel(int* degG, int* degL, int n) {
    int i = blockIdx.x * blockDim.x + threadIdx.x;
    if (i < n) { degG[i] = 0; degL[i] = 0; }
}

__global__ void wsplit_all_kernel(const float* __restrict__ WG, const float* __restrict__ WLp,
                                  const float* __restrict__ linW, const float* __restrict__ finW,
                                  __nv_bfloat16* BGh, __nv_bfloat16* BGl,
                                  __nv_bfloat16* BLh, __nv_bfloat16* BLl,
                                  __nv_bfloat16* Blinh, __nv_bfloat16* Blinl,
                                  __nv_bfloat16* Bfinh, __nv_bfloat16* Bfinl) {
    int seg = blockIdx.z;
    const float* W;
    __nv_bfloat16 *Bh, *Bl;
    int K, N;
    if (seg < 3)      { K = HH;     N = HH;   W = WG  + (size_t)seg * HH * HH;           Bh = BGh  + (size_t)seg * HH * HH;           Bl = BGl  + (size_t)seg * HH * HH; }
    else if (seg < 6) { K = HH;     N = HH;   W = WLp + (size_t)(seg - 3) * HH * HH;     Bh = BLh  + (size_t)(seg - 3) * HH * HH;     Bl = BLl  + (size_t)(seg - 3) * HH * HH; }
    else if (seg < 9) { K = 2 * HH; N = HH;   W = linW + (size_t)(seg - 6) * 2 * HH * HH; Bh = Blinh + (size_t)(seg - 6) * 2 * HH * HH; Bl = Blinl + (size_t)(seg - 6) * 2 * HH * HH; }
    else              { K = HH;     N = OUTC; W = finW;                                   Bh = Bfinh;                                   Bl = Bfinl; }
    int n0 = blockIdx.x * 32, k0 = blockIdx.y * 32;
    if (n0 >= N || k0 >= K) return;
    __shared__ float t[32][33];
    int tx = threadIdx.x, ty = threadIdx.y;
    #pragma unroll
    for (int i = 0; i < 4; i++)
        t[ty + i * 8][tx] = W[(size_t)(k0 + ty + i * 8) * N + n0 + tx];
    __syncthreads();
    #pragma unroll
    for (int i = 0; i < 4; i++) {
        float v = t[tx][ty + i * 8];
        __nv_bfloat16 h = __float2bfloat16(v);
        __nv_bfloat16 l = __float2bfloat16(v - __bfloat162float(h));
        size_t o = (size_t)(n0 + ty + i * 8) * K + k0 + tx;
        Bh[o] = h;
        Bl[o] = l;
    }
}

__global__ void init_split_kernel(const float4* __restrict__ xin4, float4* __restrict__ px4,
                                  __nv_bfloat16* __restrict__ xh, __nv_bfloat16* __restrict__ xl) {
    int i = blockIdx.x * blockDim.x + threadIdx.x;
    if (i >= NN * HH / 4) return;
    float4 v = xin4[i];
    px4[i] = v;
    __nv_bfloat16 h0 = __float2bfloat16(v.x), h1 = __float2bfloat16(v.y);
    __nv_bfloat16 h2 = __float2bfloat16(v.z), h3 = __float2bfloat16(v.w);
    __nv_bfloat16 l0 = __float2bfloat16(v.x - __bfloat162float(h0));
    __nv_bfloat16 l1 = __float2bfloat16(v.y - __bfloat162float(h1));
    __nv_bfloat16 l2 = __float2bfloat16(v.z - __bfloat162float(h2));
    __nv_bfloat16 l3 = __float2bfloat16(v.w - __bfloat162float(h3));
    __nv_bfloat162 ph0(h0, h1), ph1(h2, h3), pl0(l0, l1), pl1(l2, l3);
    uint2 uh = { *(unsigned*)&ph0, *(unsigned*)&ph1 };
    uint2 ul = { *(unsigned*)&pl0, *(unsigned*)&pl1 };
    *reinterpret_cast<uint2*>(&xh[i * 4]) = uh;
    *reinterpret_cast<uint2*>(&xl[i * 4]) = ul;
}

__global__ void count_deg_kernel(const int* __restrict__ dstG, int EG,
                                 const int* __restrict__ dstL, int EL,
                                 int* __restrict__ degG, int* __restrict__ degL) {
    int i = blockIdx.x * blockDim.x + threadIdx.x;
    if (i < EG) atomicAdd(&degG[dstG[i]], 1);
    else if (i < EG + EL) atomicAdd(&degL[dstL[i - EG]], 1);
}
__global__ void make_dinv_kernel(const int* __restrict__ degG, float* __restrict__ dinvG,
                                 const int* __restrict__ degL, float* __restrict__ dinvL, int n) {
    int i = blockIdx.x * blockDim.x + threadIdx.x;
    if (i < n) {
        dinvG[i] = rsqrtf((float)degG[i] + 2.0f);
        dinvL[i] = rsqrtf((float)degL[i] + 2.0f);
    }
}
__global__ void scan_block_kernel(const int* __restrict__ degG, const int* __restrict__ degL,
                                  int* __restrict__ rowG, int* __restrict__ rowL,
                                  int* __restrict__ bsum, int n) {
    __shared__ int s[256];
    const int* deg = blockIdx.y ? degL : degG;
    int* rowptr = blockIdx.y ? rowL : rowG;
    int* bs = bsum + blockIdx.y * 256;
    int i = blockIdx.x * 256 + threadIdx.x;
    int v = (i < n) ? deg[i] : 0;
    s[threadIdx.x] = v;
    __syncthreads();
    #pragma unroll
    for (int o = 1; o < 256; o <<= 1) {
        int t = (threadIdx.x >= o) ? s[threadIdx.x - o] : 0;
        __syncthreads();
        s[threadIdx.x] += t;
        __syncthreads();
    }
    if (i < n) rowptr[i] = s[threadIdx.x] - v;
    if (threadIdx.x == 255) bs[blockIdx.x] = s[255];
}
__global__ void scan_aux_kernel(int* bsum, int nb) {
    if (threadIdx.x == 0) {
        for (int y = 0; y < 2; y++) {
            int run = 0;
            int* b = bsum + y * 256;
            for (int i = 0; i < nb; i++) { int t = b[i]; b[i] = run; run += t; }
        }
    }
}
__global__ void scan_add_kernel(int* __restrict__ rowG, int* __restrict__ rowL,
                                int* __restrict__ fillG, int* __restrict__ fillL,
                                const int* __restrict__ bsum, int n, int EG, int EL) {
    int* rowptr = blockIdx.y ? rowL : rowG;
    int* fill = blockIdx.y ? fillL : fillG;
    const int* bs = bsum + blockIdx.y * 256;
    int E = blockIdx.y ? EL : EG;
    int i = blockIdx.x * 256 + threadIdx.x;
    if (i < n) {
        int v = rowptr[i] + bs[i >> 8];
        rowptr[i] = v;
        fill[i] = v;
    }
    if (i == 0) rowptr[n] = E;
}
__global__ void fill_csr_kernel(const int* __restrict__ Ge, int EG, const int* __restrict__ Le, int EL,
                                int* __restrict__ fillG, int* __restrict__ fillL,
                                int* __restrict__ colG, int* __restrict__ colL,
                                float* __restrict__ coefG, float* __restrict__ coefL,
                                const float* __restrict__ dinvG, const float* __restrict__ dinvL) {
    int e = blockIdx.x * blockDim.x + threadIdx.x;
    const int* src; const int* dst; int* fill; int* col; float* coef; const float* dinv; int E;
    if (blockIdx.y == 0) { src = Ge; dst = Ge + EG; fill = fillG; col = colG; coef = coefG; dinv = dinvG; E = EG; }
    else                 { src = Le; dst = Le + EL; fill = fillL; col = colL; coef = coefL; dinv = dinvL; E = EL; }
    if (e < E) {
        int s = src[e], d = dst[e];
        int p = atomicAdd(&fill[d], 1);
        col[p] = s;
        coef[p] = dinv[s] * dinv[d];
    }
}

// ================= bf16x3 GEMM: compile-time NOUT, 8 warps, 32x64 warp tiles ============
// Output modes: Ch0/Ch1 non-null -> write fp16 only. Else write fp32 C (+ optional bf16 split).
template <int NOUT>
__global__ __launch_bounds__(256, 2)
void gemm_bf16x3_kernel(const __nv_bfloat16* __restrict__ Ah, const __nv_bfloat16* __restrict__ Al,
                        int lda,
                        const __nv_bfloat16* __restrict__ Bh0, const __nv_bfloat16* __restrict__ Bl0,
                        const __nv_bfloat16* __restrict__ Bh1, const __nv_bfloat16* __restrict__ Bl1,
                        float* __restrict__ C0, float* __restrict__ C1,
                        __half* __restrict__ Ch0, __half* __restrict__ Ch1,
                        __nv_bfloat16* __restrict__ Csh, __nv_bfloat16* __restrict__ Csl,
                        const float* __restrict__ bias, int M, int K) {
    constexpr int HALFN = NOUT / 2;
    constexpr int NF = HALFN / 16;
    extern __shared__ __nv_bfloat16 sm[];
    const __nv_bfloat16* gBh = blockIdx.y ? Bh1 : Bh0;
    const __nv_bfloat16* gBl = blockIdx.y ? Bl1 : Bl0;
    float* C = blockIdx.y ? C1 : C0;
    __half* Ch = blockIdx.y ? Ch1 : Ch0;

    const int tid = threadIdx.x;
    const int wid = tid >> 5;
    const int lane = tid & 31;
    const int wr = wid >> 1;
    const int wc = wid & 1;
    const int row0 = blockIdx.x * 128;

    wmma::fragment<wmma::accumulator, 16, 16, 16, float> acc[2][NF];
    #pragma unroll
    for (int i = 0; i < 2; i++)
        #pragma unroll
        for (int j = 0; j < NF; j++)
            wmma::fill_fragment(acc[i][j], 0.0f);

    const int nc = K >> 5;

    auto load_stage = [&](int s, int kc) {
        __nv_bfloat16* base = sm + s * STAGE;
        #pragma unroll
        for (int c = tid; c < 512; c += 256) {
            int r = c >> 2;
            int ko = (c & 3) * 8;
            int gr = row0 + r;
            if (gr < M) {
                size_t go = (size_t)gr * lda + kc * 32 + ko;
                __pipeline_memcpy_async(&base[r * LDT + ko], &Ah[go], 16);
                __pipeline_memcpy_async(&base[TSZ + r * LDT + ko], &Al[go], 16);
            }
        }
        #pragma unroll
        for (int c = tid; c < NOUT * 4; c += 256) {
            int r = c >> 2;
            int ko = (c & 3) * 8;
            size_t go = (size_t)r * K + kc * 32 + ko;
            __pipeline_memcpy_async(&base[2 * TSZ + r * LDT + ko], &gBh[go], 16);
            __pipeline_memcpy_async(&base[3 * TSZ + r * LDT + ko], &gBl[go], 16);
        }
    };

    load_stage(0, 0);
    __pipeline_commit();

    for (int kc = 0; kc < nc; kc++) {
        if (kc + 1 < nc) {
            load_stage((kc + 1) & 1, kc + 1);
            __pipeline_commit();
            __pipeline_wait_prior(1);
        } else {
            __pipeline_wait_prior(0);
        }
        __syncthreads();

        __nv_bfloat16* Ahs = sm + (kc & 1) * STAGE;
        __nv_bfloat16* Als = Ahs + TSZ;
        __nv_bfloat16* Bhs = Ahs + 2 * TSZ;
        __nv_bfloat16* Bls = Ahs + 3 * TSZ;

        #pragma unroll
        for (int ks = 0; ks < 32; ks += 16) {
            wmma::fragment<wmma::matrix_a, 16, 16, 16, __nv_bfloat16, wmma::row_major> fah[2], fal[2];
            #pragma unroll
            for (int i = 0; i < 2; i++) {
                wmma::load_matrix_sync(fah[i], &Ahs[(wr * 32 + i * 16) * LDT + ks], LDT);
                wmma::load_matrix_sync(fal[i], &Als[(wr * 32 + i * 16) * LDT + ks], LDT);
            }
            wmma::fragment<wmma::matrix_b, 16, 16, 16, __nv_bfloat16, wmma::col_major> fb[NF];
            #pragma unroll
            for (int j = 0; j < NF; j++)
                wmma::load_matrix_sync(fb[j], &Bhs[(wc * HALFN + j * 16) * LDT + ks], LDT);
            #pragma unroll
            for (int i = 0; i < 2; i++)
                #pragma unroll
                for (int j = 0; j < NF; j++)
                    wmma::mma_sync(acc[i][j], fah[i], fb[j], acc[i][j]);
            #pragma unroll
            for (int i = 0; i < 2; i++)
                #pragma unroll
                for (int j = 0; j < NF; j++)
                    wmma::mma_sync(acc[i][j], fal[i], fb[j], acc[i][j]);
            #pragma unroll
            for (int j = 0; j < NF; j++)
                wmma::load_matrix_sync(fb[j], &Bls[(wc * HALFN + j * 16) * LDT + ks], LDT);
            #pragma unroll
            for (int i = 0; i < 2; i++)
                #pragma unroll
                for (int j = 0; j < NF; j++)
                    wmma::mma_sync(acc[i][j], fah[i], fb[j], acc[i][j]);
        }
        __syncthreads();
    }

    // epilogue via smem staging
    float* st = reinterpret_cast<float*>(sm) + wid * 320;
    #pragma unroll
    for (int i = 0; i < 2; i++)
        #pragma unroll
        for (int j = 0; j < NF; j++) {
            wmma::store_matrix_sync(st, acc[i][j], 20, wmma::mem_row_major);
            __syncwarp();
            #pragma unroll
            for (int e = 0; e < 8; e++) {
                int idx = lane + e * 32;
                int r = idx >> 4;
                int c = idx & 15;
                int grow = row0 + wr * 32 + i * 16 + r;
                int gcol = wc * HALFN + j * 16 + c;
                if (grow < M) {
                    float v = st[r * 20 + c];
                    if (bias) v += __ldg(&bias[gcol]);
                    if (Ch) {
                        Ch[(size_t)grow * NOUT + gcol] = __float2half(v);
                    } else {
                        C[(size_t)grow * NOUT + gcol] = v;
                        if (Csh) {
                            __nv_bfloat16 h = __float2bfloat16(v);
                            __nv_bfloat16 l = __float2bfloat16(v - __bfloat162float(h));
                            Csh[(size_t)grow * NOUT + gcol] = h;
                            Csl[(size_t)grow * NOUT + gcol] = l;
                        }
                    }
                }
            }
            __syncwarp();
        }
}

// ================= fused gather(fp16) + LN + ReLU + residual + concat (bf16-split out) ======
__global__ void gather_ln_kernel(const uint2* __restrict__ hG8, const uint2* __restrict__ hL8,
                                 const float4* __restrict__ x4,
                                 const int* __restrict__ rowG, const int* __restrict__ rowL,
                                 const int* __restrict__ colG, const int* __restrict__ colL,
                                 const float* __restrict__ coefG, const float* __restrict__ coefL,
                                 const float* __restrict__ dinvG, const float* __restrict__ dinvL,
                                 const float4* __restrict__ biasG4, const float4* __restrict__ biasL4,
                                 const float4* __restrict__ g4, const float4* __restrict__ b4,
                                 __nv_bfloat16* __restrict__ cath, __nv_bfloat16* __restrict__ catl,
                                 int residual) {
    int warp = (blockIdx.x * blockDim.x + threadIdx.x) >> 5;
    int lane = threadIdx.x & 31;
    if (warp >= NN) return;
    int n = warp;
    int half = blockIdx.y;

    const uint2* h8 = half ? hL8 : hG8;
    const int* rowptr = half ? rowL : rowG;
    const int* col = half ? colL : colG;
    const float* coef = half ? coefL : coefG;
    const float* dinv = half ? dinvL : dinvG;
    const float4* bias4 = half ? biasL4 : biasG4;

    auto h2f4 = [](uint2 u) -> float4 {
        __half2 a = *reinterpret_cast<__half2*>(&u.x);
        __half2 b = *reinterpret_cast<__half2*>(&u.y);
        float2 fa = __half22float2(a);
        float2 fb = __half22float2(b);
        return make_float4(fa.x, fa.y, fb.x, fb.y);
    };

    float dv = __ldg(&dinv[n]);
    float sl = 2.0f * dv * dv;
    float4 h = h2f4(h8[n * 32 + lane]);
    float4 bb = __ldg(&bias4[lane]);
    float4 acc;
    acc.x = h.x * sl + bb.x;
    acc.y = h.y * sl + bb.y;
    acc.z = h.z * sl + bb.z;
    acc.w = h.w * sl + bb.w;

    int e = __ldg(&rowptr[n]);
    int e1 = __ldg(&rowptr[n + 1]);
    for (; e + 1 < e1; e += 2) {
        int s0 = __ldg(&col[e]);
        int s1 = __ldg(&col[e + 1]);
        float c0 = __ldg(&coef[e]);
        float c1 = __ldg(&coef[e + 1]);
        float4 v0 = h2f4(h8[s0 * 32 + lane]);
        float4 v1 = h2f4(h8[s1 * 32 + lane]);
        acc.x += c0 * v0.x + c1 * v1.x;
        acc.y += c0 * v0.y + c1 * v1.y;
        acc.z += c0 * v0.z + c1 * v1.z;
        acc.w += c0 * v0.w + c1 * v1.w;
    }
    if (e < e1) {
        int s0 = __ldg(&col[e]);
        float c0 = __ldg(&coef[e]);
        float4 v0 = h2f4(h8[s0 * 32 + lane]);
        acc.x += c0 * v0.x; acc.y += c0 * v0.y; acc.z += c0 * v0.z; acc.w += c0 * v0.w;
    }

    float s1 = acc.x + acc.y + acc.z + acc.w;
    float s2 = acc.x * acc.x + acc.y * acc.y + acc.z * acc.z + acc.w * acc.w;
    #pragma unroll
    for (int o = 16; o > 0; o >>= 1) {
        s1 += __shfl_xor_sync(0xffffffffu, s1, o);
        s2 += __shfl_xor_sync(0xffffffffu, s2, o);
    }
    float mu = s1 * (1.0f / HH);
    float var = s2 * (1.0f / HH) - mu * mu;
    float rstd = rsqrtf(var + LN_EPS);

    float4 gg = __ldg(&g4[lane]);
    float4 be = __ldg(&b4[lane]);
    float4 y;
    y.x = fmaxf((acc.x - mu) * rstd * gg.x + be.x, 0.0f);
    y.y = fmaxf((acc.y - mu) * rstd * gg.y + be.y, 0.0f);
    y.z = fmaxf((acc.z - mu) * rstd * gg.z + be.z, 0.0f);
    y.w = fmaxf((acc.w - mu) * rstd * gg.w + be.w, 0.0f);
    if (residual) {
        float4 xv = x4[n * 32 + lane];
        y.x += xv.x; y.y += xv.y; y.z += xv.z; y.w += xv.w;
    }
    __nv_bfloat16 h0 = __float2bfloat16(y.x), h1 = __float2bfloat16(y.y);
    __nv_bfloat16 h2 = __float2bfloat16(y.z), h3 = __float2bfloat16(y.w);
    __nv_bfloat16 l0 = __float2bfloat16(y.x - __bfloat162float(h0));
    __nv_bfloat16 l1 = __float2bfloat16(y.y - __bfloat162float(h1));
    __nv_bfloat16 l2 = __float2bfloat16(y.z - __bfloat162float(h2));
    __nv_bfloat16 l3 = __float2bfloat16(y.w - __bfloat162float(h3));
    __nv_bfloat162 ph0(h0, h1), ph1(h2, h3), pl0(l0, l1), pl1(l2, l3);
    uint2 uh = { *(unsigned*)&ph0, *(unsigned*)&ph1 };
    uint2 ul = { *(unsigned*)&pl0, *(unsigned*)&pl1 };
    size_t o = (size_t)n * 256 + half * 128 + lane * 4;
    *reinterpret_cast<uint2*>(&cath[o]) = uh;
    *reinterpret_cast<uint2*>(&catl[o]) = ul;
}

// ================= launch =================
extern "C" void kernel_launch(void* const* d_in, const int* in_sizes, int n_in,
                              void* d_out, int out_size) {
    const float* x_in  = (const float*)d_in[0];
    const float* WL    = (const float*)d_in[1];
    const float* bL    = (const float*)d_in[2];
    const float* WG    = (const float*)d_in[3];
    const float* bG    = (const float*)d_in[4];
    const float* linW  = (const float*)d_in[5];
    const float* linb  = (const float*)d_in[6];
    const float* ln_g  = (const float*)d_in[7];
    const float* ln_b  = (const float*)d_in[8];
    const float* finW  = (const float*)d_in[9];
    const float* finb  = (const float*)d_in[10];
    const int*   Ge    = (const int*)d_in[11];
    const int*   Le    = (const int*)d_in[12];
    int E_G = in_sizes[11] / 2;
    int E_L = in_sizes[12] / 2;
    float* out = (float*)d_out;

    float *px, *pdinvG, *pdinvL, *pcoefG, *pcoefL;
    __half *phG, *phL;
    int *pdegG, *pdegL, *prowG, *prowL, *pfillG, *pfillL, *pcolG, *pcolL, *pbsum;
    __nv_bfloat16 *pxh, *pxl, *pcath, *pcatl;
    __nv_bfloat16 *pBGh, *pBGl, *pBLh, *pBLl, *pBlinh, *pBlinl, *pBfinh, *pBfinl;
    cudaGetSymbolAddress((void**)&px,     g_x);
    cudaGetSymbolAddress((void**)&phG,    g_hG);
    cudaGetSymbolAddress((void**)&phL,    g_hL);
    cudaGetSymbolAddress((void**)&pxh,    g_xh);
    cudaGetSymbolAddress((void**)&pxl,    g_xl);
    cudaGetSymbolAddress((void**)&pcath,  g_cath);
    cudaGetSymbolAddress((void**)&pcatl,  g_catl);
    cudaGetSymbolAddress((void**)&pdegG,  g_degG);
    cudaGetSymbolAddress((void**)&pdegL,  g_degL);
    cudaGetSymbolAddress((void**)&pdinvG, g_dinvG);
    cudaGetSymbolAddress((void**)&pdinvL, g_dinvL);
    cudaGetSymbolAddress((void**)&prowG,  g_rowptrG);
    cudaGetSymbolAddress((void**)&prowL,  g_rowptrL);
    cudaGetSymbolAddress((void**)&pfillG, g_fillG);
    cudaGetSymbolAddress((void**)&pfillL, g_fillL);
    cudaGetSymbolAddress((void**)&pcolG,  g_colG);
    cudaGetSymbolAddress((void**)&pcolL,  g_colL);
    cudaGetSymbolAddress((void**)&pcoefG, g_coefG);
    cudaGetSymbolAddress((void**)&pcoefL, g_coefL);
    cudaGetSymbolAddress((void**)&pbsum,  g_bsum);
    cudaGetSymbolAddress((void**)&pBGh,   g_BGh);
    cudaGetSymbolAddress((void**)&pBGl,   g_BGl);
    cudaGetSymbolAddress((void**)&pBLh,   g_BLh);
    cudaGetSymbolAddress((void**)&pBLl,   g_BLl);
    cudaGetSymbolAddress((void**)&pBlinh, g_Blinh);
    cudaGetSymbolAddress((void**)&pBlinl, g_Blinl);
    cudaGetSymbolAddress((void**)&pBfinh, g_Bfinh);
    cudaGetSymbolAddress((void**)&pBfinl, g_Bfinl);

    const int GEMM_SMEM = 2 * STAGE * 2;   // 81920 bytes
    static int attr_set = 0;
    if (!attr_set) {
        cudaFuncSetAttribute(gemm_bf16x3_kernel<128>, cudaFuncAttributeMaxDynamicSharedMemorySize, GEMM_SMEM);
        cudaFuncSetAttribute(gemm_bf16x3_kernel<64>,  cudaFuncAttributeMaxDynamicSharedMemorySize, GEMM_SMEM);
        attr_set = 1;
    }

    // ---- ordered so the 4th kernel is the first (dual-branch) GEMM ----
    zero_deg_kernel<<<NB196, 256>>>(pdegG, pdegL, NN);
    wsplit_all_kernel<<<dim3(4, 8, 10), dim3(32, 8)>>>(WG, WL, linW, finW,
        pBGh, pBGl, pBLh, pBLl, pBlinh, pBlinl, pBfinh, pBfinl);
    init_split_kernel<<<(NN * HH / 4 + 255) / 256, 256>>>((const float4*)x_in,
        (float4*)px, pxh, pxl);
    gemm_bf16x3_kernel<128><<<dim3(TILES, 2), 256, GEMM_SMEM>>>(
        pxh, pxl, HH, pBGh, pBGl, pBLh, pBLl, nullptr, nullptr,
        phG, phL, nullptr, nullptr, nullptr, NN, HH);
    // CSR setup
    count_deg_kernel<<<(E_G + E_L + 255) / 256, 256>>>(Ge + E_G, E_G, Le + E_L, E_L, pdegG, pdegL);
    make_dinv_kernel<<<NB196, 256>>>(pdegG, pdinvG, pdegL, pdinvL, NN);
    scan_block_kernel<<<dim3(NB196, 2), 256>>>(pdegG, pdegL, prowG, prowL, pbsum, NN);
    scan_aux_kernel<<<1, 32>>>(pbsum, NB196);
    scan_add_kernel<<<dim3(NB196, 2), 256>>>(prowG, prowL, pfillG, pfillL, pbsum, NN, E_G, E_L);
    int fe = (E_G > E_L ? E_G : E_L);
    fill_csr_kernel<<<dim3((fe + 255) / 256, 2), 256>>>(Ge, E_G, Le, E_L,
        pfillG, pfillL, pcolG, pcolL, pcoefG, pcoefL, pdinvG, pdinvL);

    int gatherBlocks = (NN * 32 + 255) / 256;

    for (int i = 0; i < DEPTH; i++) {
        if (i > 0) {
            size_t wo = (size_t)i * HH * HH;
            gemm_bf16x3_kernel<128><<<dim3(TILES, 2), 256, GEMM_SMEM>>>(
                pxh, pxl, HH, pBGh + wo, pBGl + wo, pBLh + wo, pBLl + wo,
                nullptr, nullptr, phG, phL, nullptr, nullptr, nullptr, NN, HH);
        }
        int res = (i > 0) ? 1 : 0;
        gather_ln_kernel<<<dim3(gatherBlocks, 2), 256>>>(
            (const uint2*)phG, (const uint2*)phL, (const float4*)px,
            prowG, prowL, pcolG, pcolL, pcoefG, pcoefL, pdinvG, pdinvL,
            (const float4*)(bG + (size_t)i * HH), (const float4*)(bL + (size_t)i * HH),
            (const float4*)ln_g, (const float4*)ln_b, pcath, pcatl, res);
        size_t lo = (size_t)i * HH * 2 * HH;
        gemm_bf16x3_kernel<128><<<dim3(TILES, 1), 256, GEMM_SMEM>>>(
            pcath, pcatl, 2 * HH, pBlinh + lo, pBlinl + lo, nullptr, nullptr,
            px, nullptr, nullptr, nullptr, pxh, pxl, linb + (size_t)i * HH, NN, 2 * HH);
    }

    gemm_bf16x3_kernel<64><<<dim3(TILES, 1), 256, GEMM_SMEM>>>(
        pxh, pxl, HH, pBfinh, pBfinl, nullptr, nullptr,
        out, nullptr, nullptr, nullptr, nullptr, nullptr, finb, NN, HH);
    cudaMemcpyAsync(out + (size_t)NN * OUTC, px, (size_t)NN * HH * sizeof(float),
                    cudaMemcpyDeviceToDevice);
}

// round 9
// speedup vs baseline: 4.6283x; 1.0408x over previous
#include <cuda_runtime.h>
#include <cuda_bf16.h>
#include <cuda_fp16.h>
#include <cuda_pipeline.h>
#include <mma.h>
#include <cstdint>

using namespace nvcuda;

#define NN 50000
#define HH 128
#define OUTC 64
#define DEPTH 3
#define LN_EPS 1e-5f
#define EGMAX 600000
#define ELMAX 400000
#define NB196 196
#define TILES 391          // ceil(NN/128)
#define LDT 40             // A smem leading dim (bf16): conflict-free LDSM
#define TSZ (128 * LDT)
#define STAGE (4 * TSZ)    // for K-streaming kernel (concat)

// ================= scratch =================
__device__ float g_x[NN * HH];
__device__ __half g_hG[NN * HH];
__device__ __half g_hL[NN * HH];
__device__ __nv_bfloat16 g_xh[NN * HH];
__device__ __nv_bfloat16 g_xl[NN * HH];
__device__ __nv_bfloat16 g_cath[NN * 2 * HH];
__device__ __nv_bfloat16 g_catl[NN * 2 * HH];
__device__ int   g_degG[NN];
__device__ int   g_degL[NN];
__device__ float g_dinvG[NN];
__device__ float g_dinvL[NN];
__device__ int   g_rowptrG[NN + 1];
__device__ int   g_rowptrL[NN + 1];
__device__ int   g_fillG[NN];
__device__ int   g_fillL[NN];
__device__ int   g_colG[EGMAX];
__device__ int   g_colL[ELMAX];
__device__ float g_coefG[EGMAX];
__device__ float g_coefL[ELMAX];
__device__ int   g_bsum[2][256];
__device__ __nv_bfloat16 g_BGh[DEPTH * HH * HH];
__device__ __nv_bfloat16 g_BGl[DEPTH * HH * HH];
__device__ __nv_bfloat16 g_BLh[DEPTH * HH * HH];
__device__ __nv_bfloat16 g_BLl[DEPTH * HH * HH];
__device__ __nv_bfloat16 g_Blinh[DEPTH * HH * 2 * HH];
__device__ __nv_bfloat16 g_Blinl[DEPTH * HH * 2 * HH];
__device__ __nv_bfloat16 g_Bfinh[OUTC * HH];
__device__ __nv_bfloat16 g_Bfinl[OUTC * HH];

// ================= setup kernels =================
__global__ void zero_deg_kernel(int* degG, int* degL, int n) {
    int i = blockIdx.x * blockDim.x + threadIdx.x;
    if (i < n) { degG[i] = 0; degL[i] = 0; }
}

__global__ void wsplit_all_kernel(const float* __restrict__ WG, const float* __restrict__ WLp,
                                  const float* __restrict__ linW, const float* __restrict__ finW,
                                  __nv_bfloat16* BGh, __nv_bfloat16* BGl,
                                  __nv_bfloat16* BLh, __nv_bfloat16* BLl,
                                  __nv_bfloat16* Blinh, __nv_bfloat16* Blinl,
                                  __nv_bfloat16* Bfinh, __nv_bfloat16* Bfinl) {
    int seg = blockIdx.z;
    const float* W;
    __nv_bfloat16 *Bh, *Bl;
    int K, N;
    if (seg < 3)      { K = HH;     N = HH;   W = WG  + (size_t)seg * HH * HH;           Bh = BGh  + (size_t)seg * HH * HH;           Bl = BGl  + (size_t)seg * HH * HH; }
    else if (seg < 6) { K = HH;     N = HH;   W = WLp + (size_t)(seg - 3) * HH * HH;     Bh = BLh  + (size_t)(seg - 3) * HH * HH;     Bl = BLl  + (size_t)(seg - 3) * HH * HH; }
    else if (seg < 9) { K = 2 * HH; N = HH;   W = linW + (size_t)(seg - 6) * 2 * HH * HH; Bh = Blinh + (size_t)(seg - 6) * 2 * HH * HH; Bl = Blinl + (size_t)(seg - 6) * 2 * HH * HH; }
    else              { K = HH;     N = OUTC; W = finW;                                   Bh = Bfinh;                                   Bl = Bfinl; }
    int n0 = blockIdx.x * 32, k0 = blockIdx.y * 32;
    if (n0 >= N || k0 >= K) return;
    __shared__ float t[32][33];
    int tx = threadIdx.x, ty = threadIdx.y;
    #pragma unroll
    for (int i = 0; i < 4; i++)
        t[ty + i * 8][tx] = W[(size_t)(k0 + ty + i * 8) * N + n0 + tx];
    __syncthreads();
    #pragma unroll
    for (int i = 0; i < 4; i++) {
        float v = t[tx][ty + i * 8];
        __nv_bfloat16 h = __float2bfloat16(v);
        __nv_bfloat16 l = __float2bfloat16(v - __bfloat162float(h));
        size_t o = (size_t)(n0 + ty + i * 8) * K + k0 + tx;
        Bh[o] = h;
        Bl[o] = l;
    }
}

__global__ void init_split_kernel(const float4* __restrict__ xin4, float4* __restrict__ px4,
                                  __nv_bfloat16* __restrict__ xh, __nv_bfloat16* __restrict__ xl) {
    int i = blockIdx.x * blockDim.x + threadIdx.x;
    if (i >= NN * HH / 4) return;
    float4 v = xin4[i];
    px4[i] = v;
    __nv_bfloat16 h0 = __float2bfloat16(v.x), h1 = __float2bfloat16(v.y);
    __nv_bfloat16 h2 = __float2bfloat16(v.z), h3 = __float2bfloat16(v.w);
    __nv_bfloat16 l0 = __float2bfloat16(v.x - __bfloat162float(h0));
    __nv_bfloat16 l1 = __float2bfloat16(v.y - __bfloat162float(h1));
    __nv_bfloat16 l2 = __float2bfloat16(v.z - __bfloat162float(h2));
    __nv_bfloat16 l3 = __float2bfloat16(v.w - __bfloat162float(h3));
    __nv_bfloat162 ph0(h0, h1), ph1(h2, h3), pl0(l0, l1), pl1(l2, l3);
    uint2 uh = { *(unsigned*)&ph0, *(unsigned*)&ph1 };
    uint2 ul = { *(unsigned*)&pl0, *(unsigned*)&pl1 };
    *reinterpret_cast<uint2*>(&xh[i * 4]) = uh;
    *reinterpret_cast<uint2*>(&xl[i * 4]) = ul;
}

__global__ void count_deg_kernel(const int* __restrict__ dstG, int EG,
                                 const int* __restrict__ dstL, int EL,
                                 int* __restrict__ degG, int* __restrict__ degL) {
    int i = blockIdx.x * blockDim.x + threadIdx.x;
    if (i < EG) atomicAdd(&degG[dstG[i]], 1);
    else if (i < EG + EL) atomicAdd(&degL[dstL[i - EG]], 1);
}
__global__ void make_dinv_kernel(const int* __restrict__ degG, float* __restrict__ dinvG,
                                 const int* __restrict__ degL, float* __restrict__ dinvL, int n) {
    int i = blockIdx.x * blockDim.x + threadIdx.x;
    if (i < n) {
        dinvG[i] = rsqrtf((float)degG[i] + 2.0f);
        dinvL[i] = rsqrtf((float)degL[i] + 2.0f);
    }
}
__global__ void scan_block_kernel(const int* __restrict__ degG, const int* __restrict__ degL,
                                  int* __restrict__ rowG, int* __restrict__ rowL,
                                  int* __restrict__ bsum, int n) {
    __shared__ int s[256];
    const int* deg = blockIdx.y ? degL : degG;
    int* rowptr = blockIdx.y ? rowL : rowG;
    int* bs = bsum + blockIdx.y * 256;
    int i = blockIdx.x * 256 + threadIdx.x;
    int v = (i < n) ? deg[i] : 0;
    s[threadIdx.x] = v;
    __syncthreads();
    #pragma unroll
    for (int o = 1; o < 256; o <<= 1) {
        int t = (threadIdx.x >= o) ? s[threadIdx.x - o] : 0;
        __syncthreads();
        s[threadIdx.x] += t;
        __syncthreads();
    }
    if (i < n) rowptr[i] = s[threadIdx.x] - v;
    if (threadIdx.x == 255) bs[blockIdx.x] = s[255];
}
__global__ void scan_aux_kernel(int* bsum, int nb) {
    if (threadIdx.x == 0) {
        for (int y = 0; y < 2; y++) {
            int run = 0;
            int* b = bsum + y * 256;
            for (int i = 0; i < nb; i++) { int t = b[i]; b[i] = run; run += t; }
        }
    }
}
__global__ void scan_add_kernel(int* __restrict__ rowG, int* __restrict__ rowL,
                                int* __restrict__ fillG, int* __restrict__ fillL,
                                const int* __restrict__ bsum, int n, int EG, int EL) {
    int* rowptr = blockIdx.y ? rowL : rowG;
    int* fill = blockIdx.y ? fillL : fillG;
    const int* bs = bsum + blockIdx.y * 256;
    int E = blockIdx.y ? EL : EG;
    int i = blockIdx.x * 256 + threadIdx.x;
    if (i < n) {
        int v = rowptr[i] + bs[i >> 8];
        rowptr[i] = v;
        fill[i] = v;
    }
    if (i == 0) rowptr[n] = E;
}
__global__ void fill_csr_kernel(const int* __restrict__ Ge, int EG, const int* __restrict__ Le, int EL,
                                int* __restrict__ fillG, int* __restrict__ fillL,
                                int* __restrict__ colG, int* __restrict__ colL,
                                float* __restrict__ coefG, float* __restrict__ coefL,
                                const float* __restrict__ dinvG, const float* __restrict__ dinvL) {
    int e = blockIdx.x * blockDim.x + threadIdx.x;
    const int* src; const int* dst; int* fill; int* col; float* coef; const float* dinv; int E;
    if (blockIdx.y == 0) { src = Ge; dst = Ge + EG; fill = fillG; col = colG; coef = coefG; dinv = dinvG; E = EG; }
    else                 { src = Le; dst = Le + EL; fill = fillL; col = colL; coef = coefL; dinv = dinvL; E = EL; }
    if (e < E) {
        int s = src[e], d = dst[e];
        int p = atomicAdd(&fill[d], 1);
        col[p] = s;
        coef[p] = dinv[s] * dinv[d];
    }
}

// ================= K=128 GEMM, B fully resident in smem, A double-buffered ============
// Outputs: Ch non-null -> fp16; else fp32 (+bias).
template <int NOUT>
__global__ __launch_bounds__(256, 2)
void gemm_k128_kernel(const __nv_bfloat16* __restrict__ Ah, const __nv_bfloat16* __restrict__ Al,
                      const __nv_bfloat16* __restrict__ Bh0, const __nv_bfloat16* __restrict__ Bl0,
                      const __nv_bfloat16* __restrict__ Bh1, const __nv_bfloat16* __restrict__ Bl1,
                      float* __restrict__ C0, float* __restrict__ C1,
                      __half* __restrict__ Ch0, __half* __restrict__ Ch1,
                      const float* __restrict__ bias, int M) {
    constexpr int K = 128;
    constexpr int HALFN = NOUT / 2;
    constexpr int NF = HALFN / 16;
    constexpr int LDB = 136;               // 272B rows: conflict-free LDSM
    constexpr int BTILE = NOUT * LDB;      // elems per B tile
    extern __shared__ __nv_bfloat16 sm[];
    __nv_bfloat16* Bhs = sm;
    __nv_bfloat16* Bls = sm + BTILE;
    __nv_bfloat16* Astg = sm + 2 * BTILE;  // stage s: Astg + s*2*TSZ (Ah tile, Al tile)

    const __nv_bfloat16* gBh = blockIdx.y ? Bh1 : Bh0;
    const __nv_bfloat16* gBl = blockIdx.y ? Bl1 : Bl0;
    float* C = blockIdx.y ? C1 : C0;
    __half* Ch = blockIdx.y ? Ch1 : Ch0;

    const int tid = threadIdx.x;
    const int wid = tid >> 5;
    const int lane = tid & 31;
    const int wr = wid >> 1;
    const int wc = wid & 1;
    const int row0 = blockIdx.x * 128;

    wmma::fragment<wmma::accumulator, 16, 16, 16, float> acc[2][NF];
    #pragma unroll
    for (int i = 0; i < 2; i++)
        #pragma unroll
        for (int j = 0; j < NF; j++)
            wmma::fill_fragment(acc[i][j], 0.0f);

    auto load_A = [&](int s, int kc) {
        __nv_bfloat16* base = Astg + s * (2 * TSZ);
        #pragma unroll
        for (int c = tid; c < 512; c += 256) {
            int r = c >> 2;
            int ko = (c & 3) * 8;
            int gr = row0 + r;
            if (gr < M) {
                size_t go = (size_t)gr * K + kc * 32 + ko;
                __pipeline_memcpy_async(&base[r * LDT + ko], &Ah[go], 16);
                __pipeline_memcpy_async(&base[TSZ + r * LDT + ko], &Al[go], 16);
            }
        }
    };

    // B full + A stage 0 in group 0
    #pragma unroll
    for (int c = tid; c < NOUT * 16; c += 256) {
        int r = c >> 4;
        int ko = (c & 15) * 8;
        size_t go = (size_t)r * K + ko;
        __pipeline_memcpy_async(&Bhs[r * LDB + ko], &gBh[go], 16);
        __pipeline_memcpy_async(&Bls[r * LDB + ko], &gBl[go], 16);
    }
    load_A(0, 0);
    __pipeline_commit();

    #pragma unroll
    for (int kc = 0; kc < 4; kc++) {
        if (kc + 1 < 4) {
            load_A((kc + 1) & 1, kc + 1);
            __pipeline_commit();
            __pipeline_wait_prior(1);
        } else {
            __pipeline_wait_prior(0);
        }
        __syncthreads();

        __nv_bfloat16* Ahs = Astg + (kc & 1) * (2 * TSZ);
        __nv_bfloat16* Als = Ahs + TSZ;

        #pragma unroll
        for (int ks = 0; ks < 32; ks += 16) {
            int kcol = kc * 32 + ks;
            wmma::fragment<wmma::matrix_a, 16, 16, 16, __nv_bfloat16, wmma::row_major> fah[2], fal[2];
            #pragma unroll
            for (int i = 0; i < 2; i++) {
                wmma::load_matrix_sync(fah[i], &Ahs[(wr * 32 + i * 16) * LDT + ks], LDT);
                wmma::load_matrix_sync(fal[i], &Als[(wr * 32 + i * 16) * LDT + ks], LDT);
            }
            wmma::fragment<wmma::matrix_b, 16, 16, 16, __nv_bfloat16, wmma::col_major> fb[NF];
            #pragma unroll
            for (int j = 0; j < NF; j++)
                wmma::load_matrix_sync(fb[j], &Bhs[(wc * HALFN + j * 16) * LDB + kcol], LDB);
            #pragma unroll
            for (int i = 0; i < 2; i++)
                #pragma unroll
                for (int j = 0; j < NF; j++)
                    wmma::mma_sync(acc[i][j], fah[i], fb[j], acc[i][j]);
            #pragma unroll
            for (int i = 0; i < 2; i++)
                #pragma unroll
                for (int j = 0; j < NF; j++)
                    wmma::mma_sync(acc[i][j], fal[i], fb[j], acc[i][j]);
            #pragma unroll
            for (int j = 0; j < NF; j++)
                wmma::load_matrix_sync(fb[j], &Bls[(wc * HALFN + j * 16) * LDB + kcol], LDB);
            #pragma unroll
            for (int i = 0; i < 2; i++)
                #pragma unroll
                for (int j = 0; j < NF; j++)
                    wmma::mma_sync(acc[i][j], fah[i], fb[j], acc[i][j]);
        }
        __syncthreads();
    }

    // epilogue via smem staging (reuses B region; safe after final sync)
    float* st = reinterpret_cast<float*>(sm) + wid * 320;
    #pragma unroll
    for (int i = 0; i < 2; i++)
        #pragma unroll
        for (int j = 0; j < NF; j++) {
            wmma::store_matrix_sync(st, acc[i][j], 20, wmma::mem_row_major);
            __syncwarp();
            #pragma unroll
            for (int e = 0; e < 8; e++) {
                int idx = lane + e * 32;
                int r = idx >> 4;
                int c = idx & 15;
                int grow = row0 + wr * 32 + i * 16 + r;
                int gcol = wc * HALFN + j * 16 + c;
                if (grow < M) {
                    float v = st[r * 20 + c];
                    if (bias) v += __ldg(&bias[gcol]);
                    if (Ch) Ch[(size_t)grow * NOUT + gcol] = __float2half(v);
                    else    C[(size_t)grow * NOUT + gcol] = v;
                }
            }
            __syncwarp();
        }
}

// ================= K-streaming GEMM (concat, K=256): as R8 ============
template <int NOUT>
__global__ __launch_bounds__(256, 2)
void gemm_bf16x3_kernel(const __nv_bfloat16* __restrict__ Ah, const __nv_bfloat16* __restrict__ Al,
                        int lda,
                        const __nv_bfloat16* __restrict__ Bh0, const __nv_bfloat16* __restrict__ Bl0,
                        float* __restrict__ C0,
                        __nv_bfloat16* __restrict__ Csh, __nv_bfloat16* __restrict__ Csl,
                        const float* __restrict__ bias, int M, int K) {
    constexpr int HALFN = NOUT / 2;
    constexpr int NF = HALFN / 16;
    extern __shared__ __nv_bfloat16 sm[];

    const int tid = threadIdx.x;
    const int wid = tid >> 5;
    const int lane = tid & 31;
    const int wr = wid >> 1;
    const int wc = wid & 1;
    const int row0 = blockIdx.x * 128;

    wmma::fragment<wmma::accumulator, 16, 16, 16, float> acc[2][NF];
    #pragma unroll
    for (int i = 0; i < 2; i++)
        #pragma unroll
        for (int j = 0; j < NF; j++)
            wmma::fill_fragment(acc[i][j], 0.0f);

    const int nc = K >> 5;

    auto load_stage = [&](int s, int kc) {
        __nv_bfloat16* base = sm + s * STAGE;
        #pragma unroll
        for (int c = tid; c < 512; c += 256) {
            int r = c >> 2;
            int ko = (c & 3) * 8;
            int gr = row0 + r;
            if (gr < M) {
                size_t go = (size_t)gr * lda + kc * 32 + ko;
                __pipeline_memcpy_async(&base[r * LDT + ko], &Ah[go], 16);
                __pipeline_memcpy_async(&base[TSZ + r * LDT + ko], &Al[go], 16);
            }
        }
        #pragma unroll
        for (int c = tid; c < NOUT * 4; c += 256) {
            int r = c >> 2;
            int ko = (c & 3) * 8;
            size_t go = (size_t)r * K + kc * 32 + ko;
            __pipeline_memcpy_async(&base[2 * TSZ + r * LDT + ko], &Bh0[go], 16);
            __pipeline_memcpy_async(&base[3 * TSZ + r * LDT + ko], &Bl0[go], 16);
        }
    };

    load_stage(0, 0);
    __pipeline_commit();

    for (int kc = 0; kc < nc; kc++) {
        if (kc + 1 < nc) {
            load_stage((kc + 1) & 1, kc + 1);
            __pipeline_commit();
            __pipeline_wait_prior(1);
        } else {
            __pipeline_wait_prior(0);
        }
        __syncthreads();

        __nv_bfloat16* Ahs = sm + (kc & 1) * STAGE;
        __nv_bfloat16* Als = Ahs + TSZ;
        __nv_bfloat16* Bhs = Ahs + 2 * TSZ;
        __nv_bfloat16* Bls = Ahs + 3 * TSZ;

        #pragma unroll
        for (int ks = 0; ks < 32; ks += 16) {
            wmma::fragment<wmma::matrix_a, 16, 16, 16, __nv_bfloat16, wmma::row_major> fah[2], fal[2];
            #pragma unroll
            for (int i = 0; i < 2; i++) {
                wmma::load_matrix_sync(fah[i], &Ahs[(wr * 32 + i * 16) * LDT + ks], LDT);
                wmma::load_matrix_sync(fal[i], &Als[(wr * 32 + i * 16) * LDT + ks], LDT);
            }
            wmma::fragment<wmma::matrix_b, 16, 16, 16, __nv_bfloat16, wmma::col_major> fb[NF];
            #pragma unroll
            for (int j = 0; j < NF; j++)
                wmma::load_matrix_sync(fb[j], &Bhs[(wc * HALFN + j * 16) * LDT + ks], LDT);
            #pragma unroll
            for (int i = 0; i < 2; i++)
                #pragma unroll
                for (int j = 0; j < NF; j++)
                    wmma::mma_sync(acc[i][j], fah[i], fb[j], acc[i][j]);
            #pragma unroll
            for (int i = 0; i < 2; i++)
                #pragma unroll
                for (int j = 0; j < NF; j++)
                    wmma::mma_sync(acc[i][j], fal[i], fb[j], acc[i][j]);
            #pragma unroll
            for (int j = 0; j < NF; j++)
                wmma::load_matrix_sync(fb[j], &Bls[(wc * HALFN + j * 16) * LDT + ks], LDT);
            #pragma unroll
            for (int i = 0; i < 2; i++)
                #pragma unroll
                for (int j = 0; j < NF; j++)
                    wmma::mma_sync(acc[i][j], fah[i], fb[j], acc[i][j]);
        }
        __syncthreads();
    }

    float* st = reinterpret_cast<float*>(sm) + wid * 320;
    #pragma unroll
    for (int i = 0; i < 2; i++)
        #pragma unroll
        for (int j = 0; j < NF; j++) {
            wmma::store_matrix_sync(st, acc[i][j], 20, wmma::mem_row_major);
            __syncwarp();
            #pragma unroll
            for (int e = 0; e < 8; e++) {
                int idx = lane + e * 32;
                int r = idx >> 4;
                int c = idx & 15;
                int grow = row0 + wr * 32 + i * 16 + r;
                int gcol = wc * HALFN + j * 16 + c;
                if (grow < M) {
                    float v = st[r * 20 + c];
                    if (bias) v += __ldg(&bias[gcol]);
                    C0[(size_t)grow * NOUT + gcol] = v;
                    __nv_bfloat16 h = __float2bfloat16(v);
                    __nv_bfloat16 l = __float2bfloat16(v - __bfloat162float(h));
                    Csh[(size_t)grow * NOUT + gcol] = h;
                    Csl[(size_t)grow * NOUT + gcol] = l;
                }
            }
            __syncwarp();
        }
}

// ================= fused gather(fp16, unroll 4) + LN + ReLU + residual + concat ======
__global__ void gather_ln_kernel(const uint2* __restrict__ hG8, const uint2* __restrict__ hL8,
                                 const float4* __restrict__ x4,
                                 const int* __restrict__ rowG, const int* __restrict__ rowL,
                                 const int* __restrict__ colG, const int* __restrict__ colL,
                                 const float* __restrict__ coefG, const float* __restrict__ coefL,
                                 const float* __restrict__ dinvG, const float* __restrict__ dinvL,
                                 const float4* __restrict__ biasG4, const float4* __restrict__ biasL4,
                                 const float4* __restrict__ g4, const float4* __restrict__ b4,
                                 __nv_bfloat16* __restrict__ cath, __nv_bfloat16* __restrict__ catl,
                                 int residual) {
    int warp = (blockIdx.x * blockDim.x + threadIdx.x) >> 5;
    int lane = threadIdx.x & 31;
    if (warp >= NN) return;
    int n = warp;
    int half = blockIdx.y;

    const uint2* h8 = half ? hL8 : hG8;
    const int* rowptr = half ? rowL : rowG;
    const int* col = half ? colL : colG;
    const float* coef = half ? coefL : coefG;
    const float* dinv = half ? dinvL : dinvG;
    const float4* bias4 = half ? biasL4 : biasG4;

    auto h2f4 = [](uint2 u) -> float4 {
        __half2 a = *reinterpret_cast<__half2*>(&u.x);
        __half2 b = *reinterpret_cast<__half2*>(&u.y);
        float2 fa = __half22float2(a);
        float2 fb = __half22float2(b);
        return make_float4(fa.x, fa.y, fb.x, fb.y);
    };

    float dv = __ldg(&dinv[n]);
    float sl = 2.0f * dv * dv;
    float4 h = h2f4(h8[n * 32 + lane]);
    float4 bb = __ldg(&bias4[lane]);
    float4 acc;
    acc.x = h.x * sl + bb.x;
    acc.y = h.y * sl + bb.y;
    acc.z = h.z * sl + bb.z;
    acc.w = h.w * sl + bb.w;

    int e = __ldg(&rowptr[n]);
    int e1 = __ldg(&rowptr[n + 1]);
    for (; e + 3 < e1; e += 4) {
        int s0 = __ldg(&col[e]);
        int s1 = __ldg(&col[e + 1]);
        int s2 = __ldg(&col[e + 2]);
        int s3 = __ldg(&col[e + 3]);
        float c0 = __ldg(&coef[e]);
        float c1 = __ldg(&coef[e + 1]);
        float c2 = __ldg(&coef[e + 2]);
        float c3 = __ldg(&coef[e + 3]);
        uint2 u0 = h8[s0 * 32 + lane];
        uint2 u1 = h8[s1 * 32 + lane];
        uint2 u2 = h8[s2 * 32 + lane];
        uint2 u3 = h8[s3 * 32 + lane];
        float4 v0 = h2f4(u0), v1 = h2f4(u1), v2 = h2f4(u2), v3 = h2f4(u3);
        acc.x += c0 * v0.x + c1 * v1.x + c2 * v2.x + c3 * v3.x;
        acc.y += c0 * v0.y + c1 * v1.y + c2 * v2.y + c3 * v3.y;
        acc.z += c0 * v0.z + c1 * v1.z + c2 * v2.z + c3 * v3.z;
        acc.w += c0 * v0.w + c1 * v1.w + c2 * v2.w + c3 * v3.w;
    }
    for (; e < e1; e++) {
        int s0 = __ldg(&col[e]);
        float c0 = __ldg(&coef[e]);
        float4 v0 = h2f4(h8[s0 * 32 + lane]);
        acc.x += c0 * v0.x; acc.y += c0 * v0.y; acc.z += c0 * v0.z; acc.w += c0 * v0.w;
    }

    float s1 = acc.x + acc.y + acc.z + acc.w;
    float s2 = acc.x * acc.x + acc.y * acc.y + acc.z * acc.z + acc.w * acc.w;
    #pragma unroll
    for (int o = 16; o > 0; o >>= 1) {
        s1 += __shfl_xor_sync(0xffffffffu, s1, o);
        s2 += __shfl_xor_sync(0xffffffffu, s2, o);
    }
    float mu = s1 * (1.0f / HH);
    float var = s2 * (1.0f / HH) - mu * mu;
    float rstd = rsqrtf(var + LN_EPS);

    float4 gg = __ldg(&g4[lane]);
    float4 be = __ldg(&b4[lane]);
    float4 y;
    y.x = fmaxf((acc.x - mu) * rstd * gg.x + be.x, 0.0f);
    y.y = fmaxf((acc.y - mu) * rstd * gg.y + be.y, 0.0f);
    y.z = fmaxf((acc.z - mu) * rstd * gg.z + be.z, 0.0f);
    y.w = fmaxf((acc.w - mu) * rstd * gg.w + be.w, 0.0f);
    if (residual) {
        float4 xv = x4[n * 32 + lane];
        y.x += xv.x; y.y += xv.y; y.z += xv.z; y.w += xv.w;
    }
    __nv_bfloat16 h0 = __float2bfloat16(y.x), h1 = __float2bfloat16(y.y);
    __nv_bfloat16 h2 = __float2bfloat16(y.z), h3 = __float2bfloat16(y.w);
    __nv_bfloat16 l0 = __float2bfloat16(y.x - __bfloat162float(h0));
    __nv_bfloat16 l1 = __float2bfloat16(y.y - __bfloat162float(h1));
    __nv_bfloat16 l2 = __float2bfloat16(y.z - __bfloat162float(h2));
    __nv_bfloat16 l3 = __float2bfloat16(y.w - __bfloat162float(h3));
    __nv_bfloat162 ph0(h0, h1), ph1(h2, h3), pl0(l0, l1), pl1(l2, l3);
    uint2 uh = { *(unsigned*)&ph0, *(unsigned*)&ph1 };
    uint2 ul = { *(unsigned*)&pl0, *(unsigned*)&pl1 };
    size_t o = (size_t)n * 256 + half * 128 + lane * 4;
    *reinterpret_cast<uint2*>(&cath[o]) = uh;
    *reinterpret_cast<uint2*>(&catl[o]) = ul;
}

// ================= launch =================
extern "C" void kernel_launch(void* const* d_in, const int* in_sizes, int n_in,
                              void* d_out, int out_size) {
    const float* x_in  = (const float*)d_in[0];
    const float* WL    = (const float*)d_in[1];
    const float* bL    = (const float*)d_in[2];
    const float* WG    = (const float*)d_in[3];
    const float* bG    = (const float*)d_in[4];
    const float* linW  = (const float*)d_in[5];
    const float* linb  = (const float*)d_in[6];
    const float* ln_g  = (const float*)d_in[7];
    const float* ln_b  = (const float*)d_in[8];
    const float* finW  = (const float*)d_in[9];
    const float* finb  = (const float*)d_in[10];
    const int*   Ge    = (const int*)d_in[11];
    const int*   Le    = (const int*)d_in[12];
    int E_G = in_sizes[11] / 2;
    int E_L = in_sizes[12] / 2;
    float* out = (float*)d_out;

    float *px, *pdinvG, *pdinvL, *pcoefG, *pcoefL;
    __half *phG, *phL;
    int *pdegG, *pdegL, *prowG, *prowL, *pfillG, *pfillL, *pcolG, *pcolL, *pbsum;
    __nv_bfloat16 *pxh, *pxl, *pcath, *pcatl;
    __nv_bfloat16 *pBGh, *pBGl, *pBLh, *pBLl, *pBlinh, *pBlinl, *pBfinh, *pBfinl;
    cudaGetSymbolAddress((void**)&px,     g_x);
    cudaGetSymbolAddress((void**)&phG,    g_hG);
    cudaGetSymbolAddress((void**)&phL,    g_hL);
    cudaGetSymbolAddress((void**)&pxh,    g_xh);
    cudaGetSymbolAddress((void**)&pxl,    g_xl);
    cudaGetSymbolAddress((void**)&pcath,  g_cath);
    cudaGetSymbolAddress((void**)&pcatl,  g_catl);
    cudaGetSymbolAddress((void**)&pdegG,  g_degG);
    cudaGetSymbolAddress((void**)&pdegL,  g_degL);
    cudaGetSymbolAddress((void**)&pdinvG, g_dinvG);
    cudaGetSymbolAddress((void**)&pdinvL, g_dinvL);
    cudaGetSymbolAddress((void**)&prowG,  g_rowptrG);
    cudaGetSymbolAddress((void**)&prowL,  g_rowptrL);
    cudaGetSymbolAddress((void**)&pfillG, g_fillG);
    cudaGetSymbolAddress((void**)&pfillL, g_fillL);
    cudaGetSymbolAddress((void**)&pcolG,  g_colG);
    cudaGetSymbolAddress((void**)&pcolL,  g_colL);
    cudaGetSymbolAddress((void**)&pcoefG, g_coefG);
    cudaGetSymbolAddress((void**)&pcoefL, g_coefL);
    cudaGetSymbolAddress((void**)&pbsum,  g_bsum);
    cudaGetSymbolAddress((void**)&pBGh,   g_BGh);
    cudaGetSymbolAddress((void**)&pBGl,   g_BGl);
    cudaGetSymbolAddress((void**)&pBLh,   g_BLh);
    cudaGetSymbolAddress((void**)&pBLl,   g_BLl);
    cudaGetSymbolAddress((void**)&pBlinh, g_Blinh);
    cudaGetSymbolAddress((void**)&pBlinl, g_Blinl);
    cudaGetSymbolAddress((void**)&pBfinh, g_Bfinh);
    cudaGetSymbolAddress((void**)&pBfinl, g_Bfinl);

    const int STREAM_SMEM = 2 * STAGE * 2;                       // 81920
    const int K128_SMEM_128 = 2 * 128 * 136 * 2 + 2 * 2 * TSZ * 2;   // 69632 + 40960 = 110592
    const int K128_SMEM_64  = 2 * 64 * 136 * 2 + 2 * 2 * TSZ * 2;    // 34816 + 40960 = 75776
    static int attr_set = 0;
    if (!attr_set) {
        cudaFuncSetAttribute(gemm_bf16x3_kernel<128>, cudaFuncAttributeMaxDynamicSharedMemorySize, STREAM_SMEM);
        cudaFuncSetAttribute(gemm_k128_kernel<128>, cudaFuncAttributeMaxDynamicSharedMemorySize, K128_SMEM_128);
        cudaFuncSetAttribute(gemm_k128_kernel<64>,  cudaFuncAttributeMaxDynamicSharedMemorySize, K128_SMEM_64);
        attr_set = 1;
    }

    // ---- ordered so the 4th kernel is the first (dual-branch) GEMM ----
    zero_deg_kernel<<<NB196, 256>>>(pdegG, pdegL, NN);
    wsplit_all_kernel<<<dim3(4, 8, 10), dim3(32, 8)>>>(WG, WL, linW, finW,
        pBGh, pBGl, pBLh, pBLl, pBlinh, pBlinl, pBfinh, pBfinl);
    init_split_kernel<<<(NN * HH / 4 + 255) / 256, 256>>>((const float4*)x_in,
        (float4*)px, pxh, pxl);
    gemm_k128_kernel<128><<<dim3(TILES, 2), 256, K128_SMEM_128>>>(
        pxh, pxl, pBGh, pBGl, pBLh, pBLl, nullptr, nullptr, phG, phL, nullptr, NN);
    // CSR setup
    count_deg_kernel<<<(E_G + E_L + 255) / 256, 256>>>(Ge + E_G, E_G, Le + E_L, E_L, pdegG, pdegL);
    make_dinv_kernel<<<NB196, 256>>>(pdegG, pdinvG, pdegL, pdinvL, NN);
    scan_block_kernel<<<dim3(NB196, 2), 256>>>(pdegG, pdegL, prowG, prowL, pbsum, NN);
    scan_aux_kernel<<<1, 32>>>(pbsum, NB196);
    scan_add_kernel<<<dim3(NB196, 2), 256>>>(prowG, prowL, pfillG, pfillL, pbsum, NN, E_G, E_L);
    int fe = (E_G > E_L ? E_G : E_L);
    fill_csr_kernel<<<dim3((fe + 255) / 256, 2), 256>>>(Ge, E_G, Le, E_L,
        pfillG, pfillL, pcolG, pcolL, pcoefG, pcoefL, pdinvG, pdinvL);

    int gatherBlocks = (NN * 32 + 255) / 256;

    for (int i = 0; i < DEPTH; i++) {
        if (i > 0) {
            size_t wo = (size_t)i * HH * HH;
            gemm_k128_kernel<128><<<dim3(TILES, 2), 256, K128_SMEM_128>>>(
                pxh, pxl, pBGh + wo, pBGl + wo, pBLh + wo, pBLl + wo,
                nullptr, nullptr, phG, phL, nullptr, NN);
        }
        int res = (i > 0) ? 1 : 0;
        gather_ln_kernel<<<dim3(gatherBlocks, 2), 256>>>(
            (const uint2*)phG, (const uint2*)phL, (const float4*)px,
            prowG, prowL, pcolG, pcolL, pcoefG, pcoefL, pdinvG, pdinvL,
            (const float4*)(bG + (size_t)i * HH), (const float4*)(bL + (size_t)i * HH),
            (const float4*)ln_g, (const float4*)ln_b, pcath, pcatl, res);
        size_t lo = (size_t)i * HH * 2 * HH;
        gemm_bf16x3_kernel<128><<<dim3(TILES, 1), 256, STREAM_SMEM>>>(
            pcath, pcatl, 2 * HH, pBlinh + lo, pBlinl + lo,
            px, pxh, pxl, linb + (size_t)i * HH, NN, 2 * HH);
    }

    gemm_k128_kernel<64><<<dim3(TILES, 1), 256, K128_SMEM_64>>>(
        pxh, pxl, pBfinh, pBfinl, nullptr, nullptr,
        out, nullptr, nullptr, nullptr, finb, NN);
    cudaMemcpyAsync(out + (size_t)NN * OUTC, px, (size_t)NN * HH * sizeof(float),
                    cudaMemcpyDeviceToDevice);
}

// round 10
// speedup vs baseline: 5.8741x; 1.2692x over previous
#include <cuda_runtime.h>
#include <cuda_bf16.h>
#include <cuda_fp16.h>
#include <cuda_pipeline.h>
#include <mma.h>
#include <cstdint>

using namespace nvcuda;

#define NN 50000
#define HH 128
#define OUTC 64
#define DEPTH 3
#define LN_EPS 1e-5f
#define EGMAX 600000
#define ELMAX 400000
#define NB196 196
#define TILES 391          // ceil(NN/128)
#define LDT 40             // A smem leading dim (fp16): 80B rows, conflict-free LDSM
#define ATSZ (128 * LDT)   // 5120 elems per A tile
#define STAGE3 (3 * ATSZ)  // stream-kernel stage: A + Bh + Bl

// ================= scratch =================
__device__ float g_x[NN * HH];
__device__ __half g_xh[NN * HH];           // fp16 copy of x (GEMM A operand)
__device__ __half g_hG[NN * HH];
__device__ __half g_hL[NN * HH];
__device__ __half g_cat[NN * 2 * HH];      // fp16 concat (A of concat GEMM)
__device__ int   g_degG[NN];
__device__ int   g_degL[NN];
__device__ float g_dinvG[NN];
__device__ float g_dinvL[NN];
__device__ int   g_rowptrG[NN + 1];
__device__ int   g_rowptrL[NN + 1];
__device__ int   g_fillG[NN];
__device__ int   g_fillL[NN];
__device__ int   g_colG[EGMAX];
__device__ int   g_colL[ELMAX];
__device__ float g_coefG[EGMAX];
__device__ float g_coefL[ELMAX];
__device__ int   g_bsum[2][256];
// fp16-split transposed weights [layer][N][K]
__device__ __half g_BGh[DEPTH * HH * HH];
__device__ __half g_BGl[DEPTH * HH * HH];
__device__ __half g_BLh[DEPTH * HH * HH];
__device__ __half g_BLl[DEPTH * HH * HH];
__device__ __half g_Blinh[DEPTH * HH * 2 * HH];
__device__ __half g_Blinl[DEPTH * HH * 2 * HH];
__device__ __half g_Bfinh[OUTC * HH];
__device__ __half g_Bfinl[OUTC * HH];

// ================= setup kernels =================
__global__ void zero_deg_kernel(int* degG, int* degL, int n) {
    int i = blockIdx.x * blockDim.x + threadIdx.x;
    if (i < n) { degG[i] = 0; degL[i] = 0; }
}

__global__ void wsplit_all_kernel(const float* __restrict__ WG, const float* __restrict__ WLp,
                                  const float* __restrict__ linW, const float* __restrict__ finW,
                                  __half* BGh, __half* BGl, __half* BLh, __half* BLl,
                                  __half* Blinh, __half* Blinl, __half* Bfinh, __half* Bfinl) {
    int seg = blockIdx.z;
    const float* W;
    __half *Bh, *Bl;
    int K, N;
    if (seg < 3)      { K = HH;     N = HH;   W = WG  + (size_t)seg * HH * HH;           Bh = BGh  + (size_t)seg * HH * HH;           Bl = BGl  + (size_t)seg * HH * HH; }
    else if (seg < 6) { K = HH;     N = HH;   W = WLp + (size_t)(seg - 3) * HH * HH;     Bh = BLh  + (size_t)(seg - 3) * HH * HH;     Bl = BLl  + (size_t)(seg - 3) * HH * HH; }
    else if (seg < 9) { K = 2 * HH; N = HH;   W = linW + (size_t)(seg - 6) * 2 * HH * HH; Bh = Blinh + (size_t)(seg - 6) * 2 * HH * HH; Bl = Blinl + (size_t)(seg - 6) * 2 * HH * HH; }
    else              { K = HH;     N = OUTC; W = finW;                                   Bh = Bfinh;                                   Bl = Bfinl; }
    int n0 = blockIdx.x * 32, k0 = blockIdx.y * 32;
    if (n0 >= N || k0 >= K) return;
    __shared__ float t[32][33];
    int tx = threadIdx.x, ty = threadIdx.y;
    #pragma unroll
    for (int i = 0; i < 4; i++)
        t[ty + i * 8][tx] = W[(size_t)(k0 + ty + i * 8) * N + n0 + tx];
    __syncthreads();
    #pragma unroll
    for (int i = 0; i < 4; i++) {
        float v = t[tx][ty + i * 8];
        __half h = __float2half(v);
        __half l = __float2half(v - __half2float(h));
        size_t o = (size_t)(n0 + ty + i * 8) * K + k0 + tx;
        Bh[o] = h;
        Bl[o] = l;
    }
}

__global__ void init_split_kernel(const float4* __restrict__ xin4, float4* __restrict__ px4,
                                  __half* __restrict__ xh) {
    int i = blockIdx.x * blockDim.x + threadIdx.x;
    if (i >= NN * HH / 4) return;
    float4 v = xin4[i];
    px4[i] = v;
    __half2 a = __floats2half2_rn(v.x, v.y);
    __half2 b = __floats2half2_rn(v.z, v.w);
    uint2 u = { *(unsigned*)&a, *(unsigned*)&b };
    *reinterpret_cast<uint2*>(&xh[i * 4]) = u;
}

__global__ void count_deg_kernel(const int* __restrict__ dstG, int EG,
                                 const int* __restrict__ dstL, int EL,
                                 int* __restrict__ degG, int* __restrict__ degL) {
    int i = blockIdx.x * blockDim.x + threadIdx.x;
    if (i < EG) atomicAdd(&degG[dstG[i]], 1);
    else if (i < EG + EL) atomicAdd(&degL[dstL[i - EG]], 1);
}
__global__ void make_dinv_kernel(const int* __restrict__ degG, float* __restrict__ dinvG,
                                 const int* __restrict__ degL, float* __restrict__ dinvL, int n) {
    int i = blockIdx.x * blockDim.x + threadIdx.x;
    if (i < n) {
        dinvG[i] = rsqrtf((float)degG[i] + 2.0f);
        dinvL[i] = rsqrtf((float)degL[i] + 2.0f);
    }
}
__global__ void scan_block_kernel(const int* __restrict__ degG, const int* __restrict__ degL,
                                  int* __restrict__ rowG, int* __restrict__ rowL,
                                  int* __restrict__ bsum, int n) {
    __shared__ int s[256];
    const int* deg = blockIdx.y ? degL : degG;
    int* rowptr = blockIdx.y ? rowL : rowG;
    int* bs = bsum + blockIdx.y * 256;
    int i = blockIdx.x * 256 + threadIdx.x;
    int v = (i < n) ? deg[i] : 0;
    s[threadIdx.x] = v;
    __syncthreads();
    #pragma unroll
    for (int o = 1; o < 256; o <<= 1) {
        int t = (threadIdx.x >= o) ? s[threadIdx.x - o] : 0;
        __syncthreads();
        s[threadIdx.x] += t;
        __syncthreads();
    }
    if (i < n) rowptr[i] = s[threadIdx.x] - v;
    if (threadIdx.x == 255) bs[blockIdx.x] = s[255];
}
__global__ void scan_aux_kernel(int* bsum, int nb) {
    if (threadIdx.x == 0) {
        for (int y = 0; y < 2; y++) {
            int run = 0;
            int* b = bsum + y * 256;
            for (int i = 0; i < nb; i++) { int t = b[i]; b[i] = run; run += t; }
        }
    }
}
__global__ void scan_add_kernel(int* __restrict__ rowG, int* __restrict__ rowL,
                                int* __restrict__ fillG, int* __restrict__ fillL,
                                const int* __restrict__ bsum, int n, int EG, int EL) {
    int* rowptr = blockIdx.y ? rowL : rowG;
    int* fill = blockIdx.y ? fillL : fillG;
    const int* bs = bsum + blockIdx.y * 256;
    int E = blockIdx.y ? EL : EG;
    int i = blockIdx.x * 256 + threadIdx.x;
    if (i < n) {
        int v = rowptr[i] + bs[i >> 8];
        rowptr[i] = v;
        fill[i] = v;
    }
    if (i == 0) rowptr[n] = E;
}
__global__ void fill_csr_kernel(const int* __restrict__ Ge, int EG, const int* __restrict__ Le, int EL,
                                int* __restrict__ fillG, int* __restrict__ fillL,
                                int* __restrict__ colG, int* __restrict__ colL,
                                float* __restrict__ coefG, float* __restrict__ coefL,
                                const float* __restrict__ dinvG, const float* __restrict__ dinvL) {
    int e = blockIdx.x * blockDim.x + threadIdx.x;
    const int* src; const int* dst; int* fill; int* col; float* coef; const float* dinv; int E;
    if (blockIdx.y == 0) { src = Ge; dst = Ge + EG; fill = fillG; col = colG; coef = coefG; dinv = dinvG; E = EG; }
    else                 { src = Le; dst = Le + EL; fill = fillL; col = colL; coef = coefL; dinv = dinvL; E = EL; }
    if (e < E) {
        int s = src[e], d = dst[e];
        int p = atomicAdd(&fill[d], 1);
        col[p] = s;
        coef[p] = dinv[s] * dinv[d];
    }
}

// ================= fp16 x2 GEMM, K=128, B resident, A double-buffered ============
// C = A @ (Bh + Bl)^T.  Ch non-null -> fp16 out; else fp32 (+bias).
template <int NOUT>
__global__ __launch_bounds__(256, 2)
void gemm_k128_kernel(const __half* __restrict__ A,
                      const __half* __restrict__ Bh0, const __half* __restrict__ Bl0,
                      const __half* __restrict__ Bh1, const __half* __restrict__ Bl1,
                      float* __restrict__ C0, float* __restrict__ C1,
                      __half* __restrict__ Ch0, __half* __restrict__ Ch1,
                      const float* __restrict__ bias, int M) {
    constexpr int K = 128;
    constexpr int HALFN = NOUT / 2;
    constexpr int NF = HALFN / 16;
    constexpr int LDB = 136;
    constexpr int BTILE = NOUT * LDB;
    extern __shared__ __half sm[];
    __half* Bhs = sm;
    __half* Bls = sm + BTILE;
    __half* Astg = sm + 2 * BTILE;

    const __half* gBh = blockIdx.y ? Bh1 : Bh0;
    const __half* gBl = blockIdx.y ? Bl1 : Bl0;
    float* C = blockIdx.y ? C1 : C0;
    __half* Ch = blockIdx.y ? Ch1 : Ch0;

    const int tid = threadIdx.x;
    const int wid = tid >> 5;
    const int lane = tid & 31;
    const int wr = wid >> 1;
    const int wc = wid & 1;
    const int row0 = blockIdx.x * 128;

    wmma::fragment<wmma::accumulator, 16, 16, 16, float> acc[2][NF];
    #pragma unroll
    for (int i = 0; i < 2; i++)
        #pragma unroll
        for (int j = 0; j < NF; j++)
            wmma::fill_fragment(acc[i][j], 0.0f);

    auto load_A = [&](int s, int kc) {
        __half* base = Astg + s * ATSZ;
        #pragma unroll
        for (int c = tid; c < 512; c += 256) {
            int r = c >> 2;
            int ko = (c & 3) * 8;
            int gr = row0 + r;
            if (gr < M)
                __pipeline_memcpy_async(&base[r * LDT + ko], &A[(size_t)gr * K + kc * 32 + ko], 16);
        }
    };

    #pragma unroll
    for (int c = tid; c < NOUT * 16; c += 256) {
        int r = c >> 4;
        int ko = (c & 15) * 8;
        size_t go = (size_t)r * K + ko;
        __pipeline_memcpy_async(&Bhs[r * LDB + ko], &gBh[go], 16);
        __pipeline_memcpy_async(&Bls[r * LDB + ko], &gBl[go], 16);
    }
    load_A(0, 0);
    __pipeline_commit();

    #pragma unroll
    for (int kc = 0; kc < 4; kc++) {
        if (kc + 1 < 4) {
            load_A((kc + 1) & 1, kc + 1);
            __pipeline_commit();
            __pipeline_wait_prior(1);
        } else {
            __pipeline_wait_prior(0);
        }
        __syncthreads();

        __half* Ahs = Astg + (kc & 1) * ATSZ;

        #pragma unroll
        for (int ks = 0; ks < 32; ks += 16) {
            int kcol = kc * 32 + ks;
            wmma::fragment<wmma::matrix_a, 16, 16, 16, __half, wmma::row_major> fa[2];
            #pragma unroll
            for (int i = 0; i < 2; i++)
                wmma::load_matrix_sync(fa[i], &Ahs[(wr * 32 + i * 16) * LDT + ks], LDT);
            wmma::fragment<wmma::matrix_b, 16, 16, 16, __half, wmma::col_major> fb[NF];
            #pragma unroll
            for (int j = 0; j < NF; j++)
                wmma::load_matrix_sync(fb[j], &Bhs[(wc * HALFN + j * 16) * LDB + kcol], LDB);
            #pragma unroll
            for (int i = 0; i < 2; i++)
                #pragma unroll
                for (int j = 0; j < NF; j++)
                    wmma::mma_sync(acc[i][j], fa[i], fb[j], acc[i][j]);
            #pragma unroll
            for (int j = 0; j < NF; j++)
                wmma::load_matrix_sync(fb[j], &Bls[(wc * HALFN + j * 16) * LDB + kcol], LDB);
            #pragma unroll
            for (int i = 0; i < 2; i++)
                #pragma unroll
                for (int j = 0; j < NF; j++)
                    wmma::mma_sync(acc[i][j], fa[i], fb[j], acc[i][j]);
        }
        __syncthreads();
    }

    float* st = reinterpret_cast<float*>(sm) + wid * 320;
    #pragma unroll
    for (int i = 0; i < 2; i++)
        #pragma unroll
        for (int j = 0; j < NF; j++) {
            wmma::store_matrix_sync(st, acc[i][j], 20, wmma::mem_row_major);
            __syncwarp();
            #pragma unroll
            for (int e = 0; e < 8; e++) {
                int idx = lane + e * 32;
                int r = idx >> 4;
                int c = idx & 15;
                int grow = row0 + wr * 32 + i * 16 + r;
                int gcol = wc * HALFN + j * 16 + c;
                if (grow < M) {
                    float v = st[r * 20 + c];
                    if (bias) v += __ldg(&bias[gcol]);
                    if (Ch) Ch[(size_t)grow * NOUT + gcol] = __float2half(v);
                    else    C[(size_t)grow * NOUT + gcol] = v;
                }
            }
            __syncwarp();
        }
}

// ================= fp16 x2 K-streaming GEMM (concat, K=256) ============
// Writes fp32 C + fp16 copy Ch (+bias).
template <int NOUT>
__global__ __launch_bounds__(256, 2)
void gemm_stream_kernel(const __half* __restrict__ A, int lda,
                        const __half* __restrict__ Bh, const __half* __restrict__ Bl,
                        float* __restrict__ C, __half* __restrict__ Chh,
                        const float* __restrict__ bias, int M, int K) {
    constexpr int HALFN = NOUT / 2;
    constexpr int NF = HALFN / 16;
    extern __shared__ __half sm[];

    const int tid = threadIdx.x;
    const int wid = tid >> 5;
    const int lane = tid & 31;
    const int wr = wid >> 1;
    const int wc = wid & 1;
    const int row0 = blockIdx.x * 128;

    wmma::fragment<wmma::accumulator, 16, 16, 16, float> acc[2][NF];
    #pragma unroll
    for (int i = 0; i < 2; i++)
        #pragma unroll
        for (int j = 0; j < NF; j++)
            wmma::fill_fragment(acc[i][j], 0.0f);

    const int nc = K >> 5;

    auto load_stage = [&](int s, int kc) {
        __half* base = sm + s * STAGE3;
        #pragma unroll
        for (int c = tid; c < 512; c += 256) {
            int r = c >> 2;
            int ko = (c & 3) * 8;
            int gr = row0 + r;
            if (gr < M)
                __pipeline_memcpy_async(&base[r * LDT + ko], &A[(size_t)gr * lda + kc * 32 + ko], 16);
        }
        #pragma unroll
        for (int c = tid; c < NOUT * 4; c += 256) {
            int r = c >> 2;
            int ko = (c & 3) * 8;
            size_t go = (size_t)r * K + kc * 32 + ko;
            __pipeline_memcpy_async(&base[ATSZ + r * LDT + ko], &Bh[go], 16);
            __pipeline_memcpy_async(&base[2 * ATSZ + r * LDT + ko], &Bl[go], 16);
        }
    };

    load_stage(0, 0);
    __pipeline_commit();

    for (int kc = 0; kc < nc; kc++) {
        if (kc + 1 < nc) {
            load_stage((kc + 1) & 1, kc + 1);
            __pipeline_commit();
            __pipeline_wait_prior(1);
        } else {
            __pipeline_wait_prior(0);
        }
        __syncthreads();

        __half* Ahs = sm + (kc & 1) * STAGE3;
        __half* Bhs = Ahs + ATSZ;
        __half* Bls = Ahs + 2 * ATSZ;

        #pragma unroll
        for (int ks = 0; ks < 32; ks += 16) {
            wmma::fragment<wmma::matrix_a, 16, 16, 16, __half, wmma::row_major> fa[2];
            #pragma unroll
            for (int i = 0; i < 2; i++)
                wmma::load_matrix_sync(fa[i], &Ahs[(wr * 32 + i * 16) * LDT + ks], LDT);
            wmma::fragment<wmma::matrix_b, 16, 16, 16, __half, wmma::col_major> fb[NF];
            #pragma unroll
            for (int j = 0; j < NF; j++)
                wmma::load_matrix_sync(fb[j], &Bhs[(wc * HALFN + j * 16) * LDT + ks], LDT);
            #pragma unroll
            for (int i = 0; i < 2; i++)
                #pragma unroll
                for (int j = 0; j < NF; j++)
                    wmma::mma_sync(acc[i][j], fa[i], fb[j], acc[i][j]);
            #pragma unroll
            for (int j = 0; j < NF; j++)
                wmma::load_matrix_sync(fb[j], &Bls[(wc * HALFN + j * 16) * LDT + ks], LDT);
            #pragma unroll
            for (int i = 0; i < 2; i++)
                #pragma unroll
                for (int j = 0; j < NF; j++)
                    wmma::mma_sync(acc[i][j], fa[i], fb[j], acc[i][j]);
        }
        __syncthreads();
    }

    float* st = reinterpret_cast<float*>(sm) + wid * 320;
    #pragma unroll
    for (int i = 0; i < 2; i++)
        #pragma unroll
        for (int j = 0; j < NF; j++) {
            wmma::store_matrix_sync(st, acc[i][j], 20, wmma::mem_row_major);
            __syncwarp();
            #pragma unroll
            for (int e = 0; e < 8; e++) {
                int idx = lane + e * 32;
                int r = idx >> 4;
                int c = idx & 15;
                int grow = row0 + wr * 32 + i * 16 + r;
                int gcol = wc * HALFN + j * 16 + c;
                if (grow < M) {
                    float v = st[r * 20 + c];
                    if (bias) v += __ldg(&bias[gcol]);
                    C[(size_t)grow * NOUT + gcol] = v;
                    Chh[(size_t)grow * NOUT + gcol] = __float2half(v);
                }
            }
            __syncwarp();
        }
}

// ================= fused gather(fp16, unroll 4) + LN + ReLU + residual + concat(fp16) ======
__global__ void gather_ln_kernel(const uint2* __restrict__ hG8, const uint2* __restrict__ hL8,
                                 const float4* __restrict__ x4,
                                 const int* __restrict__ rowG, const int* __restrict__ rowL,
                                 const int* __restrict__ colG, const int* __restrict__ colL,
                                 const float* __restrict__ coefG, const float* __restrict__ coefL,
                                 const float* __restrict__ dinvG, const float* __restrict__ dinvL,
                                 const float4* __restrict__ biasG4, const float4* __restrict__ biasL4,
                                 const float4* __restrict__ g4, const float4* __restrict__ b4,
                                 __half* __restrict__ cat, int residual) {
    int warp = (blockIdx.x * blockDim.x + threadIdx.x) >> 5;
    int lane = threadIdx.x & 31;
    if (warp >= NN) return;
    int n = warp;
    int half = blockIdx.y;

    const uint2* h8 = half ? hL8 : hG8;
    const int* rowptr = half ? rowL : rowG;
    const int* col = half ? colL : colG;
    const float* coef = half ? coefL : coefG;
    const float* dinv = half ? dinvL : dinvG;
    const float4* bias4 = half ? biasL4 : biasG4;

    auto h2f4 = [](uint2 u) -> float4 {
        __half2 a = *reinterpret_cast<__half2*>(&u.x);
        __half2 b = *reinterpret_cast<__half2*>(&u.y);
        float2 fa = __half22float2(a);
        float2 fb = __half22float2(b);
        return make_float4(fa.x, fa.y, fb.x, fb.y);
    };

    float dv = __ldg(&dinv[n]);
    float sl = 2.0f * dv * dv;
    float4 h = h2f4(h8[n * 32 + lane]);
    float4 bb = __ldg(&bias4[lane]);
    float4 acc;
    acc.x = h.x * sl + bb.x;
    acc.y = h.y * sl + bb.y;
    acc.z = h.z * sl + bb.z;
    acc.w = h.w * sl + bb.w;

    int e = __ldg(&rowptr[n]);
    int e1 = __ldg(&rowptr[n + 1]);
    for (; e + 3 < e1; e += 4) {
        int s0 = __ldg(&col[e]);
        int s1 = __ldg(&col[e + 1]);
        int s2 = __ldg(&col[e + 2]);
        int s3 = __ldg(&col[e + 3]);
        float c0 = __ldg(&coef[e]);
        float c1 = __ldg(&coef[e + 1]);
        float c2 = __ldg(&coef[e + 2]);
        float c3 = __ldg(&coef[e + 3]);
        uint2 u0 = h8[s0 * 32 + lane];
        uint2 u1 = h8[s1 * 32 + lane];
        uint2 u2 = h8[s2 * 32 + lane];
        uint2 u3 = h8[s3 * 32 + lane];
        float4 v0 = h2f4(u0), v1 = h2f4(u1), v2 = h2f4(u2), v3 = h2f4(u3);
        acc.x += c0 * v0.x + c1 * v1.x + c2 * v2.x + c3 * v3.x;
        acc.y += c0 * v0.y + c1 * v1.y + c2 * v2.y + c3 * v3.y;
        acc.z += c0 * v0.z + c1 * v1.z + c2 * v2.z + c3 * v3.z;
        acc.w += c0 * v0.w + c1 * v1.w + c2 * v2.w + c3 * v3.w;
    }
    for (; e < e1; e++) {
        int s0 = __ldg(&col[e]);
        float c0 = __ldg(&coef[e]);
        float4 v0 = h2f4(h8[s0 * 32 + lane]);
        acc.x += c0 * v0.x; acc.y += c0 * v0.y; acc.z += c0 * v0.z; acc.w += c0 * v0.w;
    }

    float s1 = acc.x + acc.y + acc.z + acc.w;
    float s2 = acc.x * acc.x + acc.y * acc.y + acc.z * acc.z + acc.w * acc.w;
    #pragma unroll
    for (int o = 16; o > 0; o >>= 1) {
        s1 += __shfl_xor_sync(0xffffffffu, s1, o);
        s2 += __shfl_xor_sync(0xffffffffu, s2, o);
    }
    float mu = s1 * (1.0f / HH);
    float var = s2 * (1.0f / HH) - mu * mu;
    float rstd = rsqrtf(var + LN_EPS);

    float4 gg = __ldg(&g4[lane]);
    float4 be = __ldg(&b4[lane]);
    float4 y;
    y.x = fmaxf((acc.x - mu) * rstd * gg.x + be.x, 0.0f);
    y.y = fmaxf((acc.y - mu) * rstd * gg.y + be.y, 0.0f);
    y.z = fmaxf((acc.z - mu) * rstd * gg.z + be.z, 0.0f);
    y.w = fmaxf((acc.w - mu) * rstd * gg.w + be.w, 0.0f);
    if (residual) {
        float4 xv = x4[n * 32 + lane];
        y.x += xv.x; y.y += xv.y; y.z += xv.z; y.w += xv.w;
    }
    __half2 ya = __floats2half2_rn(y.x, y.y);
    __half2 yb = __floats2half2_rn(y.z, y.w);
    uint2 u = { *(unsigned*)&ya, *(unsigned*)&yb };
    *reinterpret_cast<uint2*>(&cat[(size_t)n * 256 + half * 128 + lane * 4]) = u;
}

// ================= launch =================
extern "C" void kernel_launch(void* const* d_in, const int* in_sizes, int n_in,
                              void* d_out, int out_size) {
    const float* x_in  = (const float*)d_in[0];
    const float* WL    = (const float*)d_in[1];
    const float* bL    = (const float*)d_in[2];
    const float* WG    = (const float*)d_in[3];
    const float* bG    = (const float*)d_in[4];
    const float* linW  = (const float*)d_in[5];
    const float* linb  = (const float*)d_in[6];
    const float* ln_g  = (const float*)d_in[7];
    const float* ln_b  = (const float*)d_in[8];
    const float* finW  = (const float*)d_in[9];
    const float* finb  = (const float*)d_in[10];
    const int*   Ge    = (const int*)d_in[11];
    const int*   Le    = (const int*)d_in[12];
    int E_G = in_sizes[11] / 2;
    int E_L = in_sizes[12] / 2;
    float* out = (float*)d_out;

    float *px, *pdinvG, *pdinvL, *pcoefG, *pcoefL;
    __half *pxh, *phG, *phL, *pcat;
    int *pdegG, *pdegL, *prowG, *prowL, *pfillG, *pfillL, *pcolG, *pcolL, *pbsum;
    __half *pBGh, *pBGl, *pBLh, *pBLl, *pBlinh, *pBlinl, *pBfinh, *pBfinl;
    cudaGetSymbolAddress((void**)&px,     g_x);
    cudaGetSymbolAddress((void**)&pxh,    g_xh);
    cudaGetSymbolAddress((void**)&phG,    g_hG);
    cudaGetSymbolAddress((void**)&phL,    g_hL);
    cudaGetSymbolAddress((void**)&pcat,   g_cat);
    cudaGetSymbolAddress((void**)&pdegG,  g_degG);
    cudaGetSymbolAddress((void**)&pdegL,  g_degL);
    cudaGetSymbolAddress((void**)&pdinvG, g_dinvG);
    cudaGetSymbolAddress((void**)&pdinvL, g_dinvL);
    cudaGetSymbolAddress((void**)&prowG,  g_rowptrG);
    cudaGetSymbolAddress((void**)&prowL,  g_rowptrL);
    cudaGetSymbolAddress((void**)&pfillG, g_fillG);
    cudaGetSymbolAddress((void**)&pfillL, g_fillL);
    cudaGetSymbolAddress((void**)&pcolG,  g_colG);
    cudaGetSymbolAddress((void**)&pcolL,  g_colL);
    cudaGetSymbolAddress((void**)&pcoefG, g_coefG);
    cudaGetSymbolAddress((void**)&pcoefL, g_coefL);
    cudaGetSymbolAddress((void**)&pbsum,  g_bsum);
    cudaGetSymbolAddress((void**)&pBGh,   g_BGh);
    cudaGetSymbolAddress((void**)&pBGl,   g_BGl);
    cudaGetSymbolAddress((void**)&pBLh,   g_BLh);
    cudaGetSymbolAddress((void**)&pBLl,   g_BLl);
    cudaGetSymbolAddress((void**)&pBlinh, g_Blinh);
    cudaGetSymbolAddress((void**)&pBlinl, g_Blinl);
    cudaGetSymbolAddress((void**)&pBfinh, g_Bfinh);
    cudaGetSymbolAddress((void**)&pBfinl, g_Bfinl);

    const int STREAM_SMEM = 2 * STAGE3 * 2;                      // 61440
    const int K128_SMEM_128 = (2 * 128 * 136 + 2 * ATSZ) * 2;    // 90112
    const int K128_SMEM_64  = (2 * 64 * 136 + 2 * ATSZ) * 2;     // 55296
    static int attr_set = 0;
    if (!attr_set) {
        cudaFuncSetAttribute(gemm_stream_kernel<128>, cudaFuncAttributeMaxDynamicSharedMemorySize, STREAM_SMEM);
        cudaFuncSetAttribute(gemm_k128_kernel<128>, cudaFuncAttributeMaxDynamicSharedMemorySize, K128_SMEM_128);
        cudaFuncSetAttribute(gemm_k128_kernel<64>,  cudaFuncAttributeMaxDynamicSharedMemorySize, K128_SMEM_64);
        attr_set = 1;
    }

    // ---- ordered so the 4th kernel is the first (dual-branch) GEMM ----
    zero_deg_kernel<<<NB196, 256>>>(pdegG, pdegL, NN);
    wsplit_all_kernel<<<dim3(4, 8, 10), dim3(32, 8)>>>(WG, WL, linW, finW,
        pBGh, pBGl, pBLh, pBLl, pBlinh, pBlinl, pBfinh, pBfinl);
    init_split_kernel<<<(NN * HH / 4 + 255) / 256, 256>>>((const float4*)x_in, (float4*)px, pxh);
    gemm_k128_kernel<128><<<dim3(TILES, 2), 256, K128_SMEM_128>>>(
        pxh, pBGh, pBGl, pBLh, pBLl, nullptr, nullptr, phG, phL, nullptr, NN);
    // CSR setup
    count_deg_kernel<<<(E_G + E_L + 255) / 256, 256>>>(Ge + E_G, E_G, Le + E_L, E_L, pdegG, pdegL);
    make_dinv_kernel<<<NB196, 256>>>(pdegG, pdinvG, pdegL, pdinvL, NN);
    scan_block_kernel<<<dim3(NB196, 2), 256>>>(pdegG, pdegL, prowG, prowL, pbsum, NN);
    scan_aux_kernel<<<1, 32>>>(pbsum, NB196);
    scan_add_kernel<<<dim3(NB196, 2), 256>>>(prowG, prowL, pfillG, pfillL, pbsum, NN, E_G, E_L);
    int fe = (E_G > E_L ? E_G : E_L);
    fill_csr_kernel<<<dim3((fe + 255) / 256, 2), 256>>>(Ge, E_G, Le, E_L,
        pfillG, pfillL, pcolG, pcolL, pcoefG, pcoefL, pdinvG, pdinvL);

    int gatherBlocks = (NN * 32 + 255) / 256;

    for (int i = 0; i < DEPTH; i++) {
        if (i > 0) {
            size_t wo = (size_t)i * HH * HH;
            gemm_k128_kernel<128><<<dim3(TILES, 2), 256, K128_SMEM_128>>>(
                pxh, pBGh + wo, pBGl + wo, pBLh + wo, pBLl + wo,
                nullptr, nullptr, phG, phL, nullptr, NN);
        }
        int res = (i > 0) ? 1 : 0;
        gather_ln_kernel<<<dim3(gatherBlocks, 2), 256>>>(
            (const uint2*)phG, (const uint2*)phL, (const float4*)px,
            prowG, prowL, pcolG, pcolL, pcoefG, pcoefL, pdinvG, pdinvL,
            (const float4*)(bG + (size_t)i * HH), (const float4*)(bL + (size_t)i * HH),
            (const float4*)ln_g, (const float4*)ln_b, pcat, res);
        size_t lo = (size_t)i * HH * 2 * HH;
        gemm_stream_kernel<128><<<dim3(TILES, 1), 256, STREAM_SMEM>>>(
            pcat, 2 * HH, pBlinh + lo, pBlinl + lo,
            px, pxh, linb + (size_t)i * HH, NN, 2 * HH);
    }

    gemm_k128_kernel<64><<<dim3(TILES, 1), 256, K128_SMEM_64>>>(
        pxh, pBfinh, pBfinl, nullptr, nullptr,
        out, nullptr, nullptr, nullptr, finb, NN);
    cudaMemcpyAsync(out + (size_t)NN * OUTC, px, (size_t)NN * HH * sizeof(float),
                    cudaMemcpyDeviceToDevice);
}

// round 11
// speedup vs baseline: 5.8990x; 1.0042x over previous
#include <cuda_runtime.h>
#include <cuda_bf16.h>
#include <cuda_fp16.h>
#include <cuda_pipeline.h>
#include <mma.h>
#include <cstdint>

using namespace nvcuda;

#define NN 50000
#define HH 128
#define OUTC 64
#define DEPTH 3
#define LN_EPS 1e-5f
#define EGMAX 600000
#define ELMAX 400000
#define NB196 196
#define TILES 391          // ceil(NN/128)
#define LDT 40             // A smem leading dim (fp16): 80B rows, conflict-free LDSM
#define ATSZ (128 * LDT)   // 5120 elems per A tile
#define STAGE3 (3 * ATSZ)  // stream-kernel stage: A + Bh + Bl

// ================= scratch =================
__device__ float g_x[NN * HH];
__device__ __half g_xh[NN * HH];
__device__ __half g_hG[NN * HH];
__device__ __half g_hL[NN * HH];
__device__ __half g_cat[NN * 2 * HH];
__device__ int   g_degG[NN];
__device__ int   g_degL[NN];
__device__ float g_dinvG[NN];
__device__ float g_dinvL[NN];
__device__ int   g_rowptrG[NN + 1];
__device__ int   g_rowptrL[NN + 1];
__device__ int   g_fillG[NN];
__device__ int   g_fillL[NN];
__device__ int2  g_edgeG[EGMAX];     // (col, coef bits)
__device__ int2  g_edgeL[ELMAX];
__device__ int   g_bsum[2][256];
__device__ __half g_BGh[DEPTH * HH * HH];
__device__ __half g_BGl[DEPTH * HH * HH];
__device__ __half g_BLh[DEPTH * HH * HH];
__device__ __half g_BLl[DEPTH * HH * HH];
__device__ __half g_Blinh[DEPTH * HH * 2 * HH];
__device__ __half g_Blinl[DEPTH * HH * 2 * HH];
__device__ __half g_Bfinh[OUTC * HH];
__device__ __half g_Bfinl[OUTC * HH];

// ================= setup kernels =================
__global__ void zero_deg_kernel(int* degG, int* degL, int n) {
    int i = blockIdx.x * blockDim.x + threadIdx.x;
    if (i < n) { degG[i] = 0; degL[i] = 0; }
}

__global__ void wsplit_all_kernel(const float* __restrict__ WG, const float* __restrict__ WLp,
                                  const float* __restrict__ linW, const float* __restrict__ finW,
                                  __half* BGh, __half* BGl, __half* BLh, __half* BLl,
                                  __half* Blinh, __half* Blinl, __half* Bfinh, __half* Bfinl) {
    int seg = blockIdx.z;
    const float* W;
    __half *Bh, *Bl;
    int K, N;
    if (seg < 3)      { K = HH;     N = HH;   W = WG  + (size_t)seg * HH * HH;           Bh = BGh  + (size_t)seg * HH * HH;           Bl = BGl  + (size_t)seg * HH * HH; }
    else if (seg < 6) { K = HH;     N = HH;   W = WLp + (size_t)(seg - 3) * HH * HH;     Bh = BLh  + (size_t)(seg - 3) * HH * HH;     Bl = BLl  + (size_t)(seg - 3) * HH * HH; }
    else if (seg < 9) { K = 2 * HH; N = HH;   W = linW + (size_t)(seg - 6) * 2 * HH * HH; Bh = Blinh + (size_t)(seg - 6) * 2 * HH * HH; Bl = Blinl + (size_t)(seg - 6) * 2 * HH * HH; }
    else              { K = HH;     N = OUTC; W = finW;                                   Bh = Bfinh;                                   Bl = Bfinl; }
    int n0 = blockIdx.x * 32, k0 = blockIdx.y * 32;
    if (n0 >= N || k0 >= K) return;
    __shared__ float t[32][33];
    int tx = threadIdx.x, ty = threadIdx.y;
    #pragma unroll
    for (int i = 0; i < 4; i++)
        t[ty + i * 8][tx] = W[(size_t)(k0 + ty + i * 8) * N + n0 + tx];
    __syncthreads();
    #pragma unroll
    for (int i = 0; i < 4; i++) {
        float v = t[tx][ty + i * 8];
        __half h = __float2half(v);
        __half l = __float2half(v - __half2float(h));
        size_t o = (size_t)(n0 + ty + i * 8) * K + k0 + tx;
        Bh[o] = h;
        Bl[o] = l;
    }
}

__global__ void init_split_kernel(const float4* __restrict__ xin4, float4* __restrict__ px4,
                                  __half* __restrict__ xh) {
    int i = blockIdx.x * blockDim.x + threadIdx.x;
    if (i >= NN * HH / 4) return;
    float4 v = xin4[i];
    px4[i] = v;
    __half2 a = __floats2half2_rn(v.x, v.y);
    __half2 b = __floats2half2_rn(v.z, v.w);
    uint2 u = { *(unsigned*)&a, *(unsigned*)&b };
    *reinterpret_cast<uint2*>(&xh[i * 4]) = u;
}

__global__ void count_deg_kernel(const int* __restrict__ dstG, int EG,
                                 const int* __restrict__ dstL, int EL,
                                 int* __restrict__ degG, int* __restrict__ degL) {
    int i = blockIdx.x * blockDim.x + threadIdx.x;
    if (i < EG) atomicAdd(&degG[dstG[i]], 1);
    else if (i < EG + EL) atomicAdd(&degL[dstL[i - EG]], 1);
}
__global__ void make_dinv_kernel(const int* __restrict__ degG, float* __restrict__ dinvG,
                                 const int* __restrict__ degL, float* __restrict__ dinvL, int n) {
    int i = blockIdx.x * blockDim.x + threadIdx.x;
    if (i < n) {
        dinvG[i] = rsqrtf((float)degG[i] + 2.0f);
        dinvL[i] = rsqrtf((float)degL[i] + 2.0f);
    }
}
__global__ void scan_block_kernel(const int* __restrict__ degG, const int* __restrict__ degL,
                                  int* __restrict__ rowG, int* __restrict__ rowL,
                                  int* __restrict__ bsum, int n) {
    __shared__ int s[256];
    const int* deg = blockIdx.y ? degL : degG;
    int* rowptr = blockIdx.y ? rowL : rowG;
    int* bs = bsum + blockIdx.y * 256;
    int i = blockIdx.x * 256 + threadIdx.x;
    int v = (i < n) ? deg[i] : 0;
    s[threadIdx.x] = v;
    __syncthreads();
    #pragma unroll
    for (int o = 1; o < 256; o <<= 1) {
        int t = (threadIdx.x >= o) ? s[threadIdx.x - o] : 0;
        __syncthreads();
        s[threadIdx.x] += t;
        __syncthreads();
    }
    if (i < n) rowptr[i] = s[threadIdx.x] - v;
    if (threadIdx.x == 255) bs[blockIdx.x] = s[255];
}
__global__ void scan_aux_kernel(int* bsum, int nb) {
    if (threadIdx.x == 0) {
        for (int y = 0; y < 2; y++) {
            int run = 0;
            int* b = bsum + y * 256;
            for (int i = 0; i < nb; i++) { int t = b[i]; b[i] = run; run += t; }
        }
    }
}
__global__ void scan_add_kernel(int* __restrict__ rowG, int* __restrict__ rowL,
                                int* __restrict__ fillG, int* __restrict__ fillL,
                                const int* __restrict__ bsum, int n, int EG, int EL) {
    int* rowptr = blockIdx.y ? rowL : rowG;
    int* fill = blockIdx.y ? fillL : fillG;
    const int* bs = bsum + blockIdx.y * 256;
    int E = blockIdx.y ? EL : EG;
    int i = blockIdx.x * 256 + threadIdx.x;
    if (i < n) {
        int v = rowptr[i] + bs[i >> 8];
        rowptr[i] = v;
        fill[i] = v;
    }
    if (i == 0) rowptr[n] = E;
}
__global__ void fill_csr_kernel(const int* __restrict__ Ge, int EG, const int* __restrict__ Le, int EL,
                                int* __restrict__ fillG, int* __restrict__ fillL,
                                int2* __restrict__ edgeG, int2* __restrict__ edgeL,
                                const float* __restrict__ dinvG, const float* __restrict__ dinvL) {
    int e = blockIdx.x * blockDim.x + threadIdx.x;
    const int* src; const int* dst; int* fill; int2* edge; const float* dinv; int E;
    if (blockIdx.y == 0) { src = Ge; dst = Ge + EG; fill = fillG; edge = edgeG; dinv = dinvG; E = EG; }
    else                 { src = Le; dst = Le + EL; fill = fillL; edge = edgeL; dinv = dinvL; E = EL; }
    if (e < E) {
        int s = src[e], d = dst[e];
        int p = atomicAdd(&fill[d], 1);
        float c = dinv[s] * dinv[d];
        edge[p] = make_int2(s, __float_as_int(c));
    }
}

// ================= fp16 x2 GEMM, K=128, B resident, A double-buffered ============
template <int NOUT>
__global__ __launch_bounds__(256, 2)
void gemm_k128_kernel(const __half* __restrict__ A,
                      const __half* __restrict__ Bh0, const __half* __restrict__ Bl0,
                      const __half* __restrict__ Bh1, const __half* __restrict__ Bl1,
                      float* __restrict__ C0, float* __restrict__ C1,
                      __half* __restrict__ Ch0, __half* __restrict__ Ch1,
                      const float* __restrict__ bias, int M) {
    constexpr int K = 128;
    constexpr int HALFN = NOUT / 2;
    constexpr int NF = HALFN / 16;
    constexpr int LDB = 136;
    constexpr int BTILE = NOUT * LDB;
    extern __shared__ __half sm[];
    __half* Bhs = sm;
    __half* Bls = sm + BTILE;
    __half* Astg = sm + 2 * BTILE;

    const __half* gBh = blockIdx.y ? Bh1 : Bh0;
    const __half* gBl = blockIdx.y ? Bl1 : Bl0;
    float* C = blockIdx.y ? C1 : C0;
    __half* Ch = blockIdx.y ? Ch1 : Ch0;

    const int tid = threadIdx.x;
    const int wid = tid >> 5;
    const int lane = tid & 31;
    const int wr = wid >> 1;
    const int wc = wid & 1;
    const int row0 = blockIdx.x * 128;

    wmma::fragment<wmma::accumulator, 16, 16, 16, float> acc[2][NF];
    #pragma unroll
    for (int i = 0; i < 2; i++)
        #pragma unroll
        for (int j = 0; j < NF; j++)
            wmma::fill_fragment(acc[i][j], 0.0f);

    auto load_A = [&](int s, int kc) {
        __half* base = Astg + s * ATSZ;
        #pragma unroll
        for (int c = tid; c < 512; c += 256) {
            int r = c >> 2;
            int ko = (c & 3) * 8;
            int gr = row0 + r;
            if (gr < M)
                __pipeline_memcpy_async(&base[r * LDT + ko], &A[(size_t)gr * K + kc * 32 + ko], 16);
        }
    };

    #pragma unroll
    for (int c = tid; c < NOUT * 16; c += 256) {
        int r = c >> 4;
        int ko = (c & 15) * 8;
        size_t go = (size_t)r * K + ko;
        __pipeline_memcpy_async(&Bhs[r * LDB + ko], &gBh[go], 16);
        __pipeline_memcpy_async(&Bls[r * LDB + ko], &gBl[go], 16);
    }
    load_A(0, 0);
    __pipeline_commit();

    #pragma unroll
    for (int kc = 0; kc < 4; kc++) {
        if (kc + 1 < 4) {
            load_A((kc + 1) & 1, kc + 1);
            __pipeline_commit();
            __pipeline_wait_prior(1);
        } else {
            __pipeline_wait_prior(0);
        }
        __syncthreads();

        __half* Ahs = Astg + (kc & 1) * ATSZ;

        #pragma unroll
        for (int ks = 0; ks < 32; ks += 16) {
            int kcol = kc * 32 + ks;
            wmma::fragment<wmma::matrix_a, 16, 16, 16, __half, wmma::row_major> fa[2];
            #pragma unroll
            for (int i = 0; i < 2; i++)
                wmma::load_matrix_sync(fa[i], &Ahs[(wr * 32 + i * 16) * LDT + ks], LDT);
            wmma::fragment<wmma::matrix_b, 16, 16, 16, __half, wmma::col_major> fb[NF];
            #pragma unroll
            for (int j = 0; j < NF; j++)
                wmma::load_matrix_sync(fb[j], &Bhs[(wc * HALFN + j * 16) * LDB + kcol], LDB);
            #pragma unroll
            for (int i = 0; i < 2; i++)
                #pragma unroll
                for (int j = 0; j < NF; j++)
                    wmma::mma_sync(acc[i][j], fa[i], fb[j], acc[i][j]);
            #pragma unroll
            for (int j = 0; j < NF; j++)
                wmma::load_matrix_sync(fb[j], &Bls[(wc * HALFN + j * 16) * LDB + kcol], LDB);
            #pragma unroll
            for (int i = 0; i < 2; i++)
                #pragma unroll
                for (int j = 0; j < NF; j++)
                    wmma::mma_sync(acc[i][j], fa[i], fb[j], acc[i][j]);
        }
        __syncthreads();
    }

    float* st = reinterpret_cast<float*>(sm) + wid * 320;
    #pragma unroll
    for (int i = 0; i < 2; i++)
        #pragma unroll
        for (int j = 0; j < NF; j++) {
            wmma::store_matrix_sync(st, acc[i][j], 20, wmma::mem_row_major);
            __syncwarp();
            #pragma unroll
            for (int e = 0; e < 8; e++) {
                int idx = lane + e * 32;
                int r = idx >> 4;
                int c = idx & 15;
                int grow = row0 + wr * 32 + i * 16 + r;
                int gcol = wc * HALFN + j * 16 + c;
                if (grow < M) {
                    float v = st[r * 20 + c];
                    if (bias) v += __ldg(&bias[gcol]);
                    if (Ch) Ch[(size_t)grow * NOUT + gcol] = __float2half(v);
                    else    C[(size_t)grow * NOUT + gcol] = v;
                }
            }
            __syncwarp();
        }
}

// ================= fp16 x2 K-streaming GEMM (concat, K=256) ============
template <int NOUT>
__global__ __launch_bounds__(256, 2)
void gemm_stream_kernel(const __half* __restrict__ A, int lda,
                        const __half* __restrict__ Bh, const __half* __restrict__ Bl,
                        float* __restrict__ C, __half* __restrict__ Chh,
                        const float* __restrict__ bias, int M, int K) {
    constexpr int HALFN = NOUT / 2;
    constexpr int NF = HALFN / 16;
    extern __shared__ __half sm[];

    const int tid = threadIdx.x;
    const int wid = tid >> 5;
    const int lane = tid & 31;
    const int wr = wid >> 1;
    const int wc = wid & 1;
    const int row0 = blockIdx.x * 128;

    wmma::fragment<wmma::accumulator, 16, 16, 16, float> acc[2][NF];
    #pragma unroll
    for (int i = 0; i < 2; i++)
        #pragma unroll
        for (int j = 0; j < NF; j++)
            wmma::fill_fragment(acc[i][j], 0.0f);

    const int nc = K >> 5;

    auto load_stage = [&](int s, int kc) {
        __half* base = sm + s * STAGE3;
        #pragma unroll
        for (int c = tid; c < 512; c += 256) {
            int r = c >> 2;
            int ko = (c & 3) * 8;
            int gr = row0 + r;
            if (gr < M)
                __pipeline_memcpy_async(&base[r * LDT + ko], &A[(size_t)gr * lda + kc * 32 + ko], 16);
        }
        #pragma unroll
        for (int c = tid; c < NOUT * 4; c += 256) {
            int r = c >> 2;
            int ko = (c & 3) * 8;
            size_t go = (size_t)r * K + kc * 32 + ko;
            __pipeline_memcpy_async(&base[ATSZ + r * LDT + ko], &Bh[go], 16);
            __pipeline_memcpy_async(&base[2 * ATSZ + r * LDT + ko], &Bl[go], 16);
        }
    };

    load_stage(0, 0);
    __pipeline_commit();

    for (int kc = 0; kc < nc; kc++) {
        if (kc + 1 < nc) {
            load_stage((kc + 1) & 1, kc + 1);
            __pipeline_commit();
            __pipeline_wait_prior(1);
        } else {
            __pipeline_wait_prior(0);
        }
        __syncthreads();

        __half* Ahs = sm + (kc & 1) * STAGE3;
        __half* Bhs = Ahs + ATSZ;
        __half* Bls = Ahs + 2 * ATSZ;

        #pragma unroll
        for (int ks = 0; ks < 32; ks += 16) {
            wmma::fragment<wmma::matrix_a, 16, 16, 16, __half, wmma::row_major> fa[2];
            #pragma unroll
            for (int i = 0; i < 2; i++)
                wmma::load_matrix_sync(fa[i], &Ahs[(wr * 32 + i * 16) * LDT + ks], LDT);
            wmma::fragment<wmma::matrix_b, 16, 16, 16, __half, wmma::col_major> fb[NF];
            #pragma unroll
            for (int j = 0; j < NF; j++)
                wmma::load_matrix_sync(fb[j], &Bhs[(wc * HALFN + j * 16) * LDT + ks], LDT);
            #pragma unroll
            for (int i = 0; i < 2; i++)
                #pragma unroll
                for (int j = 0; j < NF; j++)
                    wmma::mma_sync(acc[i][j], fa[i], fb[j], acc[i][j]);
            #pragma unroll
            for (int j = 0; j < NF; j++)
                wmma::load_matrix_sync(fb[j], &Bls[(wc * HALFN + j * 16) * LDT + ks], LDT);
            #pragma unroll
            for (int i = 0; i < 2; i++)
                #pragma unroll
                for (int j = 0; j < NF; j++)
                    wmma::mma_sync(acc[i][j], fa[i], fb[j], acc[i][j]);
        }
        __syncthreads();
    }

    float* st = reinterpret_cast<float*>(sm) + wid * 320;
    #pragma unroll
    for (int i = 0; i < 2; i++)
        #pragma unroll
        for (int j = 0; j < NF; j++) {
            wmma::store_matrix_sync(st, acc[i][j], 20, wmma::mem_row_major);
            __syncwarp();
            #pragma unroll
            for (int e = 0; e < 8; e++) {
                int idx = lane + e * 32;
                int r = idx >> 4;
                int c = idx & 15;
                int grow = row0 + wr * 32 + i * 16 + r;
                int gcol = wc * HALFN + j * 16 + c;
                if (grow < M) {
                    float v = st[r * 20 + c];
                    if (bias) v += __ldg(&bias[gcol]);
                    C[(size_t)grow * NOUT + gcol] = v;
                    Chh[(size_t)grow * NOUT + gcol] = __float2half(v);
                }
            }
            __syncwarp();
        }
}

// ================= fused gather(fp16, int2 edges, unroll 4) + LN + ReLU + res + concat ======
__global__ void gather_ln_kernel(const uint2* __restrict__ hG8, const uint2* __restrict__ hL8,
                                 const float4* __restrict__ x4,
                                 const int* __restrict__ rowG, const int* __restrict__ rowL,
                                 const int2* __restrict__ edgeG, const int2* __restrict__ edgeL,
                                 const float* __restrict__ dinvG, const float* __restrict__ dinvL,
                                 const float4* __restrict__ biasG4, const float4* __restrict__ biasL4,
                                 const float4* __restrict__ g4, const float4* __restrict__ b4,
                                 __half* __restrict__ cat, int residual) {
    int warp = (blockIdx.x * blockDim.x + threadIdx.x) >> 5;
    int lane = threadIdx.x & 31;
    if (warp >= NN) return;
    int n = warp;
    int half = blockIdx.y;

    const uint2* h8 = half ? hL8 : hG8;
    const int* rowptr = half ? rowL : rowG;
    const int2* edge = half ? edgeL : edgeG;
    const float* dinv = half ? dinvL : dinvG;
    const float4* bias4 = half ? biasL4 : biasG4;

    auto h2f4 = [](uint2 u) -> float4 {
        __half2 a = *reinterpret_cast<__half2*>(&u.x);
        __half2 b = *reinterpret_cast<__half2*>(&u.y);
        float2 fa = __half22float2(a);
        float2 fb = __half22float2(b);
        return make_float4(fa.x, fa.y, fb.x, fb.y);
    };

    float dv = __ldg(&dinv[n]);
    float sl = 2.0f * dv * dv;
    float4 h = h2f4(h8[n * 32 + lane]);
    float4 bb = __ldg(&bias4[lane]);
    float4 acc;
    acc.x = h.x * sl + bb.x;
    acc.y = h.y * sl + bb.y;
    acc.z = h.z * sl + bb.z;
    acc.w = h.w * sl + bb.w;

    int e = __ldg(&rowptr[n]);
    int e1 = __ldg(&rowptr[n + 1]);
    for (; e + 3 < e1; e += 4) {
        int2 p0 = __ldg(&edge[e]);
        int2 p1 = __ldg(&edge[e + 1]);
        int2 p2 = __ldg(&edge[e + 2]);
        int2 p3 = __ldg(&edge[e + 3]);
        float c0 = __int_as_float(p0.y);
        float c1 = __int_as_float(p1.y);
        float c2 = __int_as_float(p2.y);
        float c3 = __int_as_float(p3.y);
        uint2 u0 = h8[p0.x * 32 + lane];
        uint2 u1 = h8[p1.x * 32 + lane];
        uint2 u2 = h8[p2.x * 32 + lane];
        uint2 u3 = h8[p3.x * 32 + lane];
        float4 v0 = h2f4(u0), v1 = h2f4(u1), v2 = h2f4(u2), v3 = h2f4(u3);
        acc.x += c0 * v0.x + c1 * v1.x + c2 * v2.x + c3 * v3.x;
        acc.y += c0 * v0.y + c1 * v1.y + c2 * v2.y + c3 * v3.y;
        acc.z += c0 * v0.z + c1 * v1.z + c2 * v2.z + c3 * v3.z;
        acc.w += c0 * v0.w + c1 * v1.w + c2 * v2.w + c3 * v3.w;
    }
    for (; e < e1; e++) {
        int2 p0 = __ldg(&edge[e]);
        float c0 = __int_as_float(p0.y);
        float4 v0 = h2f4(h8[p0.x * 32 + lane]);
        acc.x += c0 * v0.x; acc.y += c0 * v0.y; acc.z += c0 * v0.z; acc.w += c0 * v0.w;
    }

    float s1 = acc.x + acc.y + acc.z + acc.w;
    float s2 = acc.x * acc.x + acc.y * acc.y + acc.z * acc.z + acc.w * acc.w;
    #pragma unroll
    for (int o = 16; o > 0; o >>= 1) {
        s1 += __shfl_xor_sync(0xffffffffu, s1, o);
        s2 += __shfl_xor_sync(0xffffffffu, s2, o);
    }
    float mu = s1 * (1.0f / HH);
    float var = s2 * (1.0f / HH) - mu * mu;
    float rstd = rsqrtf(var + LN_EPS);

    float4 gg = __ldg(&g4[lane]);
    float4 be = __ldg(&b4[lane]);
    float4 y;
    y.x = fmaxf((acc.x - mu) * rstd * gg.x + be.x, 0.0f);
    y.y = fmaxf((acc.y - mu) * rstd * gg.y + be.y, 0.0f);
    y.z = fmaxf((acc.z - mu) * rstd * gg.z + be.z, 0.0f);
    y.w = fmaxf((acc.w - mu) * rstd * gg.w + be.w, 0.0f);
    if (residual) {
        float4 xv = x4[n * 32 + lane];
        y.x += xv.x; y.y += xv.y; y.z += xv.z; y.w += xv.w;
    }
    __half2 ya = __floats2half2_rn(y.x, y.y);
    __half2 yb = __floats2half2_rn(y.z, y.w);
    uint2 u = { *(unsigned*)&ya, *(unsigned*)&yb };
    *reinterpret_cast<uint2*>(&cat[(size_t)n * 256 + half * 128 + lane * 4]) = u;
}

// ================= launch =================
extern "C" void kernel_launch(void* const* d_in, const int* in_sizes, int n_in,
                              void* d_out, int out_size) {
    const float* x_in  = (const float*)d_in[0];
    const float* WL    = (const float*)d_in[1];
    const float* bL    = (const float*)d_in[2];
    const float* WG    = (const float*)d_in[3];
    const float* bG    = (const float*)d_in[4];
    const float* linW  = (const float*)d_in[5];
    const float* linb  = (const float*)d_in[6];
    const float* ln_g  = (const float*)d_in[7];
    const float* ln_b  = (const float*)d_in[8];
    const float* finW  = (const float*)d_in[9];
    const float* finb  = (const float*)d_in[10];
    const int*   Ge    = (const int*)d_in[11];
    const int*   Le    = (const int*)d_in[12];
    int E_G = in_sizes[11] / 2;
    int E_L = in_sizes[12] / 2;
    float* out = (float*)d_out;

    float *px, *pdinvG, *pdinvL;
    __half *pxh, *phG, *phL, *pcat;
    int *pdegG, *pdegL, *prowG, *prowL, *pfillG, *pfillL, *pbsum;
    int2 *pedgeG, *pedgeL;
    __half *pBGh, *pBGl, *pBLh, *pBLl, *pBlinh, *pBlinl, *pBfinh, *pBfinl;
    cudaGetSymbolAddress((void**)&px,     g_x);
    cudaGetSymbolAddress((void**)&pxh,    g_xh);
    cudaGetSymbolAddress((void**)&phG,    g_hG);
    cudaGetSymbolAddress((void**)&phL,    g_hL);
    cudaGetSymbolAddress((void**)&pcat,   g_cat);
    cudaGetSymbolAddress((void**)&pdegG,  g_degG);
    cudaGetSymbolAddress((void**)&pdegL,  g_degL);
    cudaGetSymbolAddress((void**)&pdinvG, g_dinvG);
    cudaGetSymbolAddress((void**)&pdinvL, g_dinvL);
    cudaGetSymbolAddress((void**)&prowG,  g_rowptrG);
    cudaGetSymbolAddress((void**)&prowL,  g_rowptrL);
    cudaGetSymbolAddress((void**)&pfillG, g_fillG);
    cudaGetSymbolAddress((void**)&pfillL, g_fillL);
    cudaGetSymbolAddress((void**)&pedgeG, g_edgeG);
    cudaGetSymbolAddress((void**)&pedgeL, g_edgeL);
    cudaGetSymbolAddress((void**)&pbsum,  g_bsum);
    cudaGetSymbolAddress((void**)&pBGh,   g_BGh);
    cudaGetSymbolAddress((void**)&pBGl,   g_BGl);
    cudaGetSymbolAddress((void**)&pBLh,   g_BLh);
    cudaGetSymbolAddress((void**)&pBLl,   g_BLl);
    cudaGetSymbolAddress((void**)&pBlinh, g_Blinh);
    cudaGetSymbolAddress((void**)&pBlinl, g_Blinl);
    cudaGetSymbolAddress((void**)&pBfinh, g_Bfinh);
    cudaGetSymbolAddress((void**)&pBfinl, g_Bfinl);

    const int STREAM_SMEM = 2 * STAGE3 * 2;                      // 61440
    const int K128_SMEM_128 = (2 * 128 * 136 + 2 * ATSZ) * 2;    // 90112
    const int K128_SMEM_64  = (2 * 64 * 136 + 2 * ATSZ) * 2;     // 55296

    static cudaStream_t s1 = nullptr;
    static cudaEvent_t evFork1, evJoin1, evFork2, evJoin2;
    static int attr_set = 0;
    if (!attr_set) {
        cudaFuncSetAttribute(gemm_stream_kernel<128>, cudaFuncAttributeMaxDynamicSharedMemorySize, STREAM_SMEM);
        cudaFuncSetAttribute(gemm_k128_kernel<128>, cudaFuncAttributeMaxDynamicSharedMemorySize, K128_SMEM_128);
        cudaFuncSetAttribute(gemm_k128_kernel<64>,  cudaFuncAttributeMaxDynamicSharedMemorySize, K128_SMEM_64);
        cudaStreamCreateWithFlags(&s1, cudaStreamNonBlocking);
        cudaEventCreateWithFlags(&evFork1, cudaEventDisableTiming);
        cudaEventCreateWithFlags(&evJoin1, cudaEventDisableTiming);
        cudaEventCreateWithFlags(&evFork2, cudaEventDisableTiming);
        cudaEventCreateWithFlags(&evJoin2, cudaEventDisableTiming);
        attr_set = 1;
    }

    // ---- fork: CSR build on side stream, weights/x-split + layer-0 GEMM on main ----
    cudaEventRecord(evFork1, 0);
    cudaStreamWaitEvent(s1, evFork1, 0);

    zero_deg_kernel<<<NB196, 256, 0, s1>>>(pdegG, pdegL, NN);
    count_deg_kernel<<<(E_G + E_L + 255) / 256, 256, 0, s1>>>(Ge + E_G, E_G, Le + E_L, E_L, pdegG, pdegL);
    make_dinv_kernel<<<NB196, 256, 0, s1>>>(pdegG, pdinvG, pdegL, pdinvL, NN);
    scan_block_kernel<<<dim3(NB196, 2), 256, 0, s1>>>(pdegG, pdegL, prowG, prowL, pbsum, NN);
    scan_aux_kernel<<<1, 32, 0, s1>>>(pbsum, NB196);
    scan_add_kernel<<<dim3(NB196, 2), 256, 0, s1>>>(prowG, prowL, pfillG, pfillL, pbsum, NN, E_G, E_L);
    int fe = (E_G > E_L ? E_G : E_L);
    fill_csr_kernel<<<dim3((fe + 255) / 256, 2), 256, 0, s1>>>(Ge, E_G, Le, E_L,
        pfillG, pfillL, pedgeG, pedgeL, pdinvG, pdinvL);
    cudaEventRecord(evJoin1, s1);

    wsplit_all_kernel<<<dim3(4, 8, 10), dim3(32, 8)>>>(WG, WL, linW, finW,
        pBGh, pBGl, pBLh, pBLl, pBlinh, pBlinl, pBfinh, pBfinl);
    init_split_kernel<<<(NN * HH / 4 + 255) / 256, 256>>>((const float4*)x_in, (float4*)px, pxh);
    gemm_k128_kernel<128><<<dim3(TILES, 2), 256, K128_SMEM_128>>>(
        pxh, pBGh, pBGl, pBLh, pBLl, nullptr, nullptr, phG, phL, nullptr, NN);

    cudaStreamWaitEvent(0, evJoin1, 0);   // gather needs CSR

    int gatherBlocks = (NN * 32 + 255) / 256;

    for (int i = 0; i < DEPTH; i++) {
        if (i > 0) {
            size_t wo = (size_t)i * HH * HH;
            gemm_k128_kernel<128><<<dim3(TILES, 2), 256, K128_SMEM_128>>>(
                pxh, pBGh + wo, pBGl + wo, pBLh + wo, pBLl + wo,
                nullptr, nullptr, phG, phL, nullptr, NN);
        }
        int res = (i > 0) ? 1 : 0;
        gather_ln_kernel<<<dim3(gatherBlocks, 2), 256>>>(
            (const uint2*)phG, (const uint2*)phL, (const float4*)px,
            prowG, prowL, pedgeG, pedgeL, pdinvG, pdinvL,
            (const float4*)(bG + (size_t)i * HH), (const float4*)(bL + (size_t)i * HH),
            (const float4*)ln_g, (const float4*)ln_b, pcat, res);
        size_t lo = (size_t)i * HH * 2 * HH;
        gemm_stream_kernel<128><<<dim3(TILES, 1), 256, STREAM_SMEM>>>(
            pcat, 2 * HH, pBlinh + lo, pBlinl + lo,
            px, pxh, linb + (size_t)i * HH, NN, 2 * HH);
    }

    // ---- fork: out2 = x copy on side stream, final GEMM on main ----
    cudaEventRecord(evFork2, 0);
    cudaStreamWaitEvent(s1, evFork2, 0);
    cudaMemcpyAsync(out + (size_t)NN * OUTC, px, (size_t)NN * HH * sizeof(float),
                    cudaMemcpyDeviceToDevice, s1);
    cudaEventRecord(evJoin2, s1);

    gemm_k128_kernel<64><<<dim3(TILES, 1), 256, K128_SMEM_64>>>(
        pxh, pBfinh, pBfinl, nullptr, nullptr,
        out, nullptr, nullptr, nullptr, finb, NN);

    cudaStreamWaitEvent(0, evJoin2, 0);   // join everything back to the capture stream
}

// round 12
// speedup vs baseline: 6.4175x; 1.0879x over previous
#include <cuda_runtime.h>
#include <cuda_bf16.h>
#include <cuda_fp16.h>
#include <cuda_pipeline.h>
#include <mma.h>
#include <cstdint>

using namespace nvcuda;

#define NN 50000
#define HH 128
#define OUTC 64
#define DEPTH 3
#define LN_EPS 1e-5f
#define EGMAX 600000
#define ELMAX 400000
#define NB196 196
#define TILES 391          // ceil(NN/128)
#define LDT 40             // A smem leading dim (fp16): 80B rows, conflict-free LDSM
#define ATSZ (128 * LDT)   // 5120 elems per A tile
#define STAGE2 (2 * ATSZ)  // stream-kernel stage: A + B

// ================= scratch =================
__device__ float g_x[NN * HH];
__device__ __half g_xh[NN * HH];
__device__ __half g_hG[NN * HH];
__device__ __half g_hL[NN * HH];
__device__ __half g_cat[NN * 2 * HH];
__device__ int   g_degG[NN];
__device__ int   g_degL[NN];
__device__ float g_dinvG[NN];
__device__ float g_dinvL[NN];
__device__ int   g_rowptrG[NN + 1];
__device__ int   g_rowptrL[NN + 1];
__device__ int   g_fillG[NN];
__device__ int   g_fillL[NN];
__device__ int2  g_edgeG[EGMAX];     // (col, coef bits)
__device__ int2  g_edgeL[ELMAX];
__device__ int   g_bsum[2][256];
// fp16 transposed weights [layer][N][K]
__device__ __half g_BG[DEPTH * HH * HH];
__device__ __half g_BL[DEPTH * HH * HH];
__device__ __half g_Blin[DEPTH * HH * 2 * HH];
__device__ __half g_Bfin[OUTC * HH];

// ================= setup kernels =================
__global__ void zero_deg_kernel(int* degG, int* degL, int n) {
    int i = blockIdx.x * blockDim.x + threadIdx.x;
    if (i < n) { degG[i] = 0; degL[i] = 0; }
}

__global__ void wsplit_all_kernel(const float* __restrict__ WG, const float* __restrict__ WLp,
                                  const float* __restrict__ linW, const float* __restrict__ finW,
                                  __half* BG, __half* BL, __half* Blin, __half* Bfin) {
    int seg = blockIdx.z;
    const float* W;
    __half* B;
    int K, N;
    if (seg < 3)      { K = HH;     N = HH;   W = WG  + (size_t)seg * HH * HH;           B = BG  + (size_t)seg * HH * HH; }
    else if (seg < 6) { K = HH;     N = HH;   W = WLp + (size_t)(seg - 3) * HH * HH;     B = BL  + (size_t)(seg - 3) * HH * HH; }
    else if (seg < 9) { K = 2 * HH; N = HH;   W = linW + (size_t)(seg - 6) * 2 * HH * HH; B = Blin + (size_t)(seg - 6) * 2 * HH * HH; }
    else              { K = HH;     N = OUTC; W = finW;                                   B = Bfin; }
    int n0 = blockIdx.x * 32, k0 = blockIdx.y * 32;
    if (n0 >= N || k0 >= K) return;
    __shared__ float t[32][33];
    int tx = threadIdx.x, ty = threadIdx.y;
    #pragma unroll
    for (int i = 0; i < 4; i++)
        t[ty + i * 8][tx] = W[(size_t)(k0 + ty + i * 8) * N + n0 + tx];
    __syncthreads();
    #pragma unroll
    for (int i = 0; i < 4; i++)
        B[(size_t)(n0 + ty + i * 8) * K + k0 + tx] = __float2half(t[tx][ty + i * 8]);
}

__global__ void init_split_kernel(const float4* __restrict__ xin4, float4* __restrict__ px4,
                                  __half* __restrict__ xh) {
    int i = blockIdx.x * blockDim.x + threadIdx.x;
    if (i >= NN * HH / 4) return;
    float4 v = xin4[i];
    px4[i] = v;
    __half2 a = __floats2half2_rn(v.x, v.y);
    __half2 b = __floats2half2_rn(v.z, v.w);
    uint2 u = { *(unsigned*)&a, *(unsigned*)&b };
    *reinterpret_cast<uint2*>(&xh[i * 4]) = u;
}

__global__ void count_deg_kernel(const int* __restrict__ dstG, int EG,
                                 const int* __restrict__ dstL, int EL,
                                 int* __restrict__ degG, int* __restrict__ degL) {
    int i = blockIdx.x * blockDim.x + threadIdx.x;
    if (i < EG) atomicAdd(&degG[dstG[i]], 1);
    else if (i < EG + EL) atomicAdd(&degL[dstL[i - EG]], 1);
}
__global__ void make_dinv_kernel(const int* __restrict__ degG, float* __restrict__ dinvG,
                                 const int* __restrict__ degL, float* __restrict__ dinvL, int n) {
    int i = blockIdx.x * blockDim.x + threadIdx.x;
    if (i < n) {
        dinvG[i] = rsqrtf((float)degG[i] + 2.0f);
        dinvL[i] = rsqrtf((float)degL[i] + 2.0f);
    }
}
__global__ void scan_block_kernel(const int* __restrict__ degG, const int* __restrict__ degL,
                                  int* __restrict__ rowG, int* __restrict__ rowL,
                                  int* __restrict__ bsum, int n) {
    __shared__ int s[256];
    const int* deg = blockIdx.y ? degL : degG;
    int* rowptr = blockIdx.y ? rowL : rowG;
    int* bs = bsum + blockIdx.y * 256;
    int i = blockIdx.x * 256 + threadIdx.x;
    int v = (i < n) ? deg[i] : 0;
    s[threadIdx.x] = v;
    __syncthreads();
    #pragma unroll
    for (int o = 1; o < 256; o <<= 1) {
        int t = (threadIdx.x >= o) ? s[threadIdx.x - o] : 0;
        __syncthreads();
        s[threadIdx.x] += t;
        __syncthreads();
    }
    if (i < n) rowptr[i] = s[threadIdx.x] - v;
    if (threadIdx.x == 255) bs[blockIdx.x] = s[255];
}
__global__ void scan_aux_kernel(int* bsum, int nb) {
    if (threadIdx.x == 0) {
        for (int y = 0; y < 2; y++) {
            int run = 0;
            int* b = bsum + y * 256;
            for (int i = 0; i < nb; i++) { int t = b[i]; b[i] = run; run += t; }
        }
    }
}
__global__ void scan_add_kernel(int* __restrict__ rowG, int* __restrict__ rowL,
                                int* __restrict__ fillG, int* __restrict__ fillL,
                                const int* __restrict__ bsum, int n, int EG, int EL) {
    int* rowptr = blockIdx.y ? rowL : rowG;
    int* fill = blockIdx.y ? fillL : fillG;
    const int* bs = bsum + blockIdx.y * 256;
    int E = blockIdx.y ? EL : EG;
    int i = blockIdx.x * 256 + threadIdx.x;
    if (i < n) {
        int v = rowptr[i] + bs[i >> 8];
        rowptr[i] = v;
        fill[i] = v;
    }
    if (i == 0) rowptr[n] = E;
}
__global__ void fill_csr_kernel(const int* __restrict__ Ge, int EG, const int* __restrict__ Le, int EL,
                                int* __restrict__ fillG, int* __restrict__ fillL,
                                int2* __restrict__ edgeG, int2* __restrict__ edgeL,
                                const float* __restrict__ dinvG, const float* __restrict__ dinvL) {
    int e = blockIdx.x * blockDim.x + threadIdx.x;
    const int* src; const int* dst; int* fill; int2* edge; const float* dinv; int E;
    if (blockIdx.y == 0) { src = Ge; dst = Ge + EG; fill = fillG; edge = edgeG; dinv = dinvG; E = EG; }
    else                 { src = Le; dst = Le + EL; fill = fillL; edge = edgeL; dinv = dinvL; E = EL; }
    if (e < E) {
        int s = src[e], d = dst[e];
        int p = atomicAdd(&fill[d], 1);
        float c = dinv[s] * dinv[d];
        edge[p] = make_int2(s, __float_as_int(c));
    }
}

// ================= fp16 GEMM, K=128, B resident, A double-buffered ============
template <int NOUT>
__global__ __launch_bounds__(256, 2)
void gemm_k128_kernel(const __half* __restrict__ A,
                      const __half* __restrict__ B0, const __half* __restrict__ B1,
                      float* __restrict__ C0, float* __restrict__ C1,
                      __half* __restrict__ Ch0, __half* __restrict__ Ch1,
                      const float* __restrict__ bias, int M) {
    constexpr int K = 128;
    constexpr int HALFN = NOUT / 2;
    constexpr int NF = HALFN / 16;
    constexpr int LDB = 136;
    constexpr int BTILE = NOUT * LDB;
    extern __shared__ __half sm[];
    __half* Bs = sm;
    __half* Astg = sm + BTILE;

    const __half* gB = blockIdx.y ? B1 : B0;
    float* C = blockIdx.y ? C1 : C0;
    __half* Ch = blockIdx.y ? Ch1 : Ch0;

    const int tid = threadIdx.x;
    const int wid = tid >> 5;
    const int lane = tid & 31;
    const int wr = wid >> 1;
    const int wc = wid & 1;
    const int row0 = blockIdx.x * 128;

    wmma::fragment<wmma::accumulator, 16, 16, 16, float> acc[2][NF];
    #pragma unroll
    for (int i = 0; i < 2; i++)
        #pragma unroll
        for (int j = 0; j < NF; j++)
            wmma::fill_fragment(acc[i][j], 0.0f);

    auto load_A = [&](int s, int kc) {
        __half* base = Astg + s * ATSZ;
        #pragma unroll
        for (int c = tid; c < 512; c += 256) {
            int r = c >> 2;
            int ko = (c & 3) * 8;
            int gr = row0 + r;
            if (gr < M)
                __pipeline_memcpy_async(&base[r * LDT + ko], &A[(size_t)gr * K + kc * 32 + ko], 16);
        }
    };

    #pragma unroll
    for (int c = tid; c < NOUT * 16; c += 256) {
        int r = c >> 4;
        int ko = (c & 15) * 8;
        __pipeline_memcpy_async(&Bs[r * LDB + ko], &gB[(size_t)r * K + ko], 16);
    }
    load_A(0, 0);
    __pipeline_commit();

    #pragma unroll
    for (int kc = 0; kc < 4; kc++) {
        if (kc + 1 < 4) {
            load_A((kc + 1) & 1, kc + 1);
            __pipeline_commit();
            __pipeline_wait_prior(1);
        } else {
            __pipeline_wait_prior(0);
        }
        __syncthreads();

        __half* Ahs = Astg + (kc & 1) * ATSZ;

        #pragma unroll
        for (int ks = 0; ks < 32; ks += 16) {
            int kcol = kc * 32 + ks;
            wmma::fragment<wmma::matrix_a, 16, 16, 16, __half, wmma::row_major> fa[2];
            #pragma unroll
            for (int i = 0; i < 2; i++)
                wmma::load_matrix_sync(fa[i], &Ahs[(wr * 32 + i * 16) * LDT + ks], LDT);
            wmma::fragment<wmma::matrix_b, 16, 16, 16, __half, wmma::col_major> fb[NF];
            #pragma unroll
            for (int j = 0; j < NF; j++)
                wmma::load_matrix_sync(fb[j], &Bs[(wc * HALFN + j * 16) * LDB + kcol], LDB);
            #pragma unroll
            for (int i = 0; i < 2; i++)
                #pragma unroll
                for (int j = 0; j < NF; j++)
                    wmma::mma_sync(acc[i][j], fa[i], fb[j], acc[i][j]);
        }
        __syncthreads();
    }

    float* st = reinterpret_cast<float*>(sm) + wid * 320;
    #pragma unroll
    for (int i = 0; i < 2; i++)
        #pragma unroll
        for (int j = 0; j < NF; j++) {
            wmma::store_matrix_sync(st, acc[i][j], 20, wmma::mem_row_major);
            __syncwarp();
            #pragma unroll
            for (int e = 0; e < 8; e++) {
                int idx = lane + e * 32;
                int r = idx >> 4;
                int c = idx & 15;
                int grow = row0 + wr * 32 + i * 16 + r;
                int gcol = wc * HALFN + j * 16 + c;
                if (grow < M) {
                    float v = st[r * 20 + c];
                    if (bias) v += __ldg(&bias[gcol]);
                    if (Ch) Ch[(size_t)grow * NOUT + gcol] = __float2half(v);
                    else    C[(size_t)grow * NOUT + gcol] = v;
                }
            }
            __syncwarp();
        }
}

// ================= fp16 K-streaming GEMM (concat, K=256) ============
template <int NOUT>
__global__ __launch_bounds__(256, 2)
void gemm_stream_kernel(const __half* __restrict__ A, int lda,
                        const __half* __restrict__ B,
                        float* __restrict__ C, __half* __restrict__ Chh,
                        const float* __restrict__ bias, int M, int K) {
    constexpr int HALFN = NOUT / 2;
    constexpr int NF = HALFN / 16;
    extern __shared__ __half sm[];

    const int tid = threadIdx.x;
    const int wid = tid >> 5;
    const int lane = tid & 31;
    const int wr = wid >> 1;
    const int wc = wid & 1;
    const int row0 = blockIdx.x * 128;

    wmma::fragment<wmma::accumulator, 16, 16, 16, float> acc[2][NF];
    #pragma unroll
    for (int i = 0; i < 2; i++)
        #pragma unroll
        for (int j = 0; j < NF; j++)
            wmma::fill_fragment(acc[i][j], 0.0f);

    const int nc = K >> 5;

    auto load_stage = [&](int s, int kc) {
        __half* base = sm + s * STAGE2;
        #pragma unroll
        for (int c = tid; c < 512; c += 256) {
            int r = c >> 2;
            int ko = (c & 3) * 8;
            int gr = row0 + r;
            if (gr < M)
                __pipeline_memcpy_async(&base[r * LDT + ko], &A[(size_t)gr * lda + kc * 32 + ko], 16);
        }
        #pragma unroll
        for (int c = tid; c < NOUT * 4; c += 256) {
            int r = c >> 2;
            int ko = (c & 3) * 8;
            __pipeline_memcpy_async(&base[ATSZ + r * LDT + ko], &B[(size_t)r * K + kc * 32 + ko], 16);
        }
    };

    load_stage(0, 0);
    __pipeline_commit();

    for (int kc = 0; kc < nc; kc++) {
        if (kc + 1 < nc) {
            load_stage((kc + 1) & 1, kc + 1);
            __pipeline_commit();
            __pipeline_wait_prior(1);
        } else {
            __pipeline_wait_prior(0);
        }
        __syncthreads();

        __half* Ahs = sm + (kc & 1) * STAGE2;
        __half* Bhs = Ahs + ATSZ;

        #pragma unroll
        for (int ks = 0; ks < 32; ks += 16) {
            wmma::fragment<wmma::matrix_a, 16, 16, 16, __half, wmma::row_major> fa[2];
            #pragma unroll
            for (int i = 0; i < 2; i++)
                wmma::load_matrix_sync(fa[i], &Ahs[(wr * 32 + i * 16) * LDT + ks], LDT);
            wmma::fragment<wmma::matrix_b, 16, 16, 16, __half, wmma::col_major> fb[NF];
            #pragma unroll
            for (int j = 0; j < NF; j++)
                wmma::load_matrix_sync(fb[j], &Bhs[(wc * HALFN + j * 16) * LDT + ks], LDT);
            #pragma unroll
            for (int i = 0; i < 2; i++)
                #pragma unroll
                for (int j = 0; j < NF; j++)
                    wmma::mma_sync(acc[i][j], fa[i], fb[j], acc[i][j]);
        }
        __syncthreads();
    }

    float* st = reinterpret_cast<float*>(sm) + wid * 320;
    #pragma unroll
    for (int i = 0; i < 2; i++)
        #pragma unroll
        for (int j = 0; j < NF; j++) {
            wmma::store_matrix_sync(st, acc[i][j], 20, wmma::mem_row_major);
            __syncwarp();
            #pragma unroll
            for (int e = 0; e < 8; e++) {
                int idx = lane + e * 32;
                int r = idx >> 4;
                int c = idx & 15;
                int grow = row0 + wr * 32 + i * 16 + r;
                int gcol = wc * HALFN + j * 16 + c;
                if (grow < M) {
                    float v = st[r * 20 + c];
                    if (bias) v += __ldg(&bias[gcol]);
                    C[(size_t)grow * NOUT + gcol] = v;
                    Chh[(size_t)grow * NOUT + gcol] = __float2half(v);
                }
            }
            __syncwarp();
        }
}

// ================= fused gather(fp16, int2 edges, unroll 4) + LN + ReLU + res + concat ======
__global__ void gather_ln_kernel(const uint2* __restrict__ hG8, const uint2* __restrict__ hL8,
                                 const float4* __restrict__ x4,
                                 const int* __restrict__ rowG, const int* __restrict__ rowL,
                                 const int2* __restrict__ edgeG, const int2* __restrict__ edgeL,
                                 const float* __restrict__ dinvG, const float* __restrict__ dinvL,
                                 const float4* __restrict__ biasG4, const float4* __restrict__ biasL4,
                                 const float4* __restrict__ g4, const float4* __restrict__ b4,
                                 __half* __restrict__ cat, int residual) {
    int warp = (blockIdx.x * blockDim.x + threadIdx.x) >> 5;
    int lane = threadIdx.x & 31;
    if (warp >= NN) return;
    int n = warp;
    int half = blockIdx.y;

    const uint2* h8 = half ? hL8 : hG8;
    const int* rowptr = half ? rowL : rowG;
    const int2* edge = half ? edgeL : edgeG;
    const float* dinv = half ? dinvL : dinvG;
    const float4* bias4 = half ? biasL4 : biasG4;

    auto h2f4 = [](uint2 u) -> float4 {
        __half2 a = *reinterpret_cast<__half2*>(&u.x);
        __half2 b = *reinterpret_cast<__half2*>(&u.y);
        float2 fa = __half22float2(a);
        float2 fb = __half22float2(b);
        return make_float4(fa.x, fa.y, fb.x, fb.y);
    };

    float dv = __ldg(&dinv[n]);
    float sl = 2.0f * dv * dv;
    float4 h = h2f4(h8[n * 32 + lane]);
    float4 bb = __ldg(&bias4[lane]);
    float4 acc;
    acc.x = h.x * sl + bb.x;
    acc.y = h.y * sl + bb.y;
    acc.z = h.z * sl + bb.z;
    acc.w = h.w * sl + bb.w;

    int e = __ldg(&rowptr[n]);
    int e1 = __ldg(&rowptr[n + 1]);
    for (; e + 3 < e1; e += 4) {
        int2 p0 = __ldg(&edge[e]);
        int2 p1 = __ldg(&edge[e + 1]);
        int2 p2 = __ldg(&edge[e + 2]);
        int2 p3 = __ldg(&edge[e + 3]);
        float c0 = __int_as_float(p0.y);
        float c1 = __int_as_float(p1.y);
        float c2 = __int_as_float(p2.y);
        float c3 = __int_as_float(p3.y);
        uint2 u0 = h8[p0.x * 32 + lane];
        uint2 u1 = h8[p1.x * 32 + lane];
        uint2 u2 = h8[p2.x * 32 + lane];
        uint2 u3 = h8[p3.x * 32 + lane];
        float4 v0 = h2f4(u0), v1 = h2f4(u1), v2 = h2f4(u2), v3 = h2f4(u3);
        acc.x += c0 * v0.x + c1 * v1.x + c2 * v2.x + c3 * v3.x;
        acc.y += c0 * v0.y + c1 * v1.y + c2 * v2.y + c3 * v3.y;
        acc.z += c0 * v0.z + c1 * v1.z + c2 * v2.z + c3 * v3.z;
        acc.w += c0 * v0.w + c1 * v1.w + c2 * v2.w + c3 * v3.w;
    }
    for (; e < e1; e++) {
        int2 p0 = __ldg(&edge[e]);
        float c0 = __int_as_float(p0.y);
        float4 v0 = h2f4(h8[p0.x * 32 + lane]);
        acc.x += c0 * v0.x; acc.y += c0 * v0.y; acc.z += c0 * v0.z; acc.w += c0 * v0.w;
    }

    float s1 = acc.x + acc.y + acc.z + acc.w;
    float s2 = acc.x * acc.x + acc.y * acc.y + acc.z * acc.z + acc.w * acc.w;
    #pragma unroll
    for (int o = 16; o > 0; o >>= 1) {
        s1 += __shfl_xor_sync(0xffffffffu, s1, o);
        s2 += __shfl_xor_sync(0xffffffffu, s2, o);
    }
    float mu = s1 * (1.0f / HH);
    float var = s2 * (1.0f / HH) - mu * mu;
    float rstd = rsqrtf(var + LN_EPS);

    float4 gg = __ldg(&g4[lane]);
    float4 be = __ldg(&b4[lane]);
    float4 y;
    y.x = fmaxf((acc.x - mu) * rstd * gg.x + be.x, 0.0f);
    y.y = fmaxf((acc.y - mu) * rstd * gg.y + be.y, 0.0f);
    y.z = fmaxf((acc.z - mu) * rstd * gg.z + be.z, 0.0f);
    y.w = fmaxf((acc.w - mu) * rstd * gg.w + be.w, 0.0f);
    if (residual) {
        float4 xv = x4[n * 32 + lane];
        y.x += xv.x; y.y += xv.y; y.z += xv.z; y.w += xv.w;
    }
    __half2 ya = __floats2half2_rn(y.x, y.y);
    __half2 yb = __floats2half2_rn(y.z, y.w);
    uint2 u = { *(unsigned*)&ya, *(unsigned*)&yb };
    *reinterpret_cast<uint2*>(&cat[(size_t)n * 256 + half * 128 + lane * 4]) = u;
}

// ================= launch =================
extern "C" void kernel_launch(void* const* d_in, const int* in_sizes, int n_in,
                              void* d_out, int out_size) {
    const float* x_in  = (const float*)d_in[0];
    const float* WL    = (const float*)d_in[1];
    const float* bL    = (const float*)d_in[2];
    const float* WG    = (const float*)d_in[3];
    const float* bG    = (const float*)d_in[4];
    const float* linW  = (const float*)d_in[5];
    const float* linb  = (const float*)d_in[6];
    const float* ln_g  = (const float*)d_in[7];
    const float* ln_b  = (const float*)d_in[8];
    const float* finW  = (const float*)d_in[9];
    const float* finb  = (const float*)d_in[10];
    const int*   Ge    = (const int*)d_in[11];
    const int*   Le    = (const int*)d_in[12];
    int E_G = in_sizes[11] / 2;
    int E_L = in_sizes[12] / 2;
    float* out = (float*)d_out;

    float *px, *pdinvG, *pdinvL;
    __half *pxh, *phG, *phL, *pcat;
    int *pdegG, *pdegL, *prowG, *prowL, *pfillG, *pfillL, *pbsum;
    int2 *pedgeG, *pedgeL;
    __half *pBG, *pBL, *pBlin, *pBfin;
    cudaGetSymbolAddress((void**)&px,     g_x);
    cudaGetSymbolAddress((void**)&pxh,    g_xh);
    cudaGetSymbolAddress((void**)&phG,    g_hG);
    cudaGetSymbolAddress((void**)&phL,    g_hL);
    cudaGetSymbolAddress((void**)&pcat,   g_cat);
    cudaGetSymbolAddress((void**)&pdegG,  g_degG);
    cudaGetSymbolAddress((void**)&pdegL,  g_degL);
    cudaGetSymbolAddress((void**)&pdinvG, g_dinvG);
    cudaGetSymbolAddress((void**)&pdinvL, g_dinvL);
    cudaGetSymbolAddress((void**)&prowG,  g_rowptrG);
    cudaGetSymbolAddress((void**)&prowL,  g_rowptrL);
    cudaGetSymbolAddress((void**)&pfillG, g_fillG);
    cudaGetSymbolAddress((void**)&pfillL, g_fillL);
    cudaGetSymbolAddress((void**)&pedgeG, g_edgeG);
    cudaGetSymbolAddress((void**)&pedgeL, g_edgeL);
    cudaGetSymbolAddress((void**)&pbsum,  g_bsum);
    cudaGetSymbolAddress((void**)&pBG,    g_BG);
    cudaGetSymbolAddress((void**)&pBL,    g_BL);
    cudaGetSymbolAddress((void**)&pBlin,  g_Blin);
    cudaGetSymbolAddress((void**)&pBfin,  g_Bfin);

    const int STREAM_SMEM = 2 * STAGE2 * 2;                  // 40960
    const int K128_SMEM_128 = (128 * 136 + 2 * ATSZ) * 2;    // 55296
    const int K128_SMEM_64  = (64 * 136 + 2 * ATSZ) * 2;     // 37888

    static cudaStream_t s1 = nullptr;
    static cudaEvent_t evFork1, evJoin1, evFork2, evJoin2;
    static int attr_set = 0;
    if (!attr_set) {
        cudaFuncSetAttribute(gemm_stream_kernel<128>, cudaFuncAttributeMaxDynamicSharedMemorySize, STREAM_SMEM);
        cudaFuncSetAttribute(gemm_k128_kernel<128>, cudaFuncAttributeMaxDynamicSharedMemorySize, K128_SMEM_128);
        cudaFuncSetAttribute(gemm_k128_kernel<64>,  cudaFuncAttributeMaxDynamicSharedMemorySize, K128_SMEM_64);
        cudaStreamCreateWithFlags(&s1, cudaStreamNonBlocking);
        cudaEventCreateWithFlags(&evFork1, cudaEventDisableTiming);
        cudaEventCreateWithFlags(&evJoin1, cudaEventDisableTiming);
        cudaEventCreateWithFlags(&evFork2, cudaEventDisableTiming);
        cudaEventCreateWithFlags(&evJoin2, cudaEventDisableTiming);
        attr_set = 1;
    }

    // ---- fork: CSR build on side stream ----
    cudaEventRecord(evFork1, 0);
    cudaStreamWaitEvent(s1, evFork1, 0);

    zero_deg_kernel<<<NB196, 256, 0, s1>>>(pdegG, pdegL, NN);
    count_deg_kernel<<<(E_G + E_L + 255) / 256, 256, 0, s1>>>(Ge + E_G, E_G, Le + E_L, E_L, pdegG, pdegL);
    make_dinv_kernel<<<NB196, 256, 0, s1>>>(pdegG, pdinvG, pdegL, pdinvL, NN);
    scan_block_kernel<<<dim3(NB196, 2), 256, 0, s1>>>(pdegG, pdegL, prowG, prowL, pbsum, NN);
    scan_aux_kernel<<<1, 32, 0, s1>>>(pbsum, NB196);
    scan_add_kernel<<<dim3(NB196, 2), 256, 0, s1>>>(prowG, prowL, pfillG, pfillL, pbsum, NN, E_G, E_L);
    int fe = (E_G > E_L ? E_G : E_L);
    fill_csr_kernel<<<dim3((fe + 255) / 256, 2), 256, 0, s1>>>(Ge, E_G, Le, E_L,
        pfillG, pfillL, pedgeG, pedgeL, pdinvG, pdinvL);
    cudaEventRecord(evJoin1, s1);

    wsplit_all_kernel<<<dim3(4, 8, 10), dim3(32, 8)>>>(WG, WL, linW, finW, pBG, pBL, pBlin, pBfin);
    init_split_kernel<<<(NN * HH / 4 + 255) / 256, 256>>>((const float4*)x_in, (float4*)px, pxh);
    gemm_k128_kernel<128><<<dim3(TILES, 2), 256, K128_SMEM_128>>>(
        pxh, pBG, pBL, nullptr, nullptr, phG, phL, nullptr, NN);

    cudaStreamWaitEvent(0, evJoin1, 0);   // gather needs CSR

    int gatherBlocks = (NN * 32 + 255) / 256;

    for (int i = 0; i < DEPTH; i++) {
        if (i > 0) {
            size_t wo = (size_t)i * HH * HH;
            gemm_k128_kernel<128><<<dim3(TILES, 2), 256, K128_SMEM_128>>>(
                pxh, pBG + wo, pBL + wo, nullptr, nullptr, phG, phL, nullptr, NN);
        }
        int res = (i > 0) ? 1 : 0;
        gather_ln_kernel<<<dim3(gatherBlocks, 2), 256>>>(
            (const uint2*)phG, (const uint2*)phL, (const float4*)px,
            prowG, prowL, pedgeG, pedgeL, pdinvG, pdinvL,
            (const float4*)(bG + (size_t)i * HH), (const float4*)(bL + (size_t)i * HH),
            (const float4*)ln_g, (const float4*)ln_b, pcat, res);
        size_t lo = (size_t)i * HH * 2 * HH;
        gemm_stream_kernel<128><<<dim3(TILES, 1), 256, STREAM_SMEM>>>(
            pcat, 2 * HH, pBlin + lo, px, pxh, linb + (size_t)i * HH, NN, 2 * HH);
    }

    // ---- fork: out2 = x copy on side stream, final GEMM on main ----
    cudaEventRecord(evFork2, 0);
    cudaStreamWaitEvent(s1, evFork2, 0);
    cudaMemcpyAsync(out + (size_t)NN * OUTC, px, (size_t)NN * HH * sizeof(float),
                    cudaMemcpyDeviceToDevice, s1);
    cudaEventRecord(evJoin2, s1);

    gemm_k128_kernel<64><<<dim3(TILES, 1), 256, K128_SMEM_64>>>(
        pxh, pBfin, nullptr, out, nullptr, nullptr, nullptr, finb, NN);

    cudaStreamWaitEvent(0, evJoin2, 0);
}

// round 13
// speedup vs baseline: 6.5953x; 1.0277x over previous
#include <cuda_runtime.h>
#include <cuda_bf16.h>
#include <cuda_fp16.h>
#include <cuda_pipeline.h>
#include <mma.h>
#include <cstdint>

using namespace nvcuda;

#define NN 50000
#define HH 128
#define OUTC 64
#define DEPTH 3
#define LN_EPS 1e-5f
#define EGMAX 600000
#define ELMAX 400000
#define NB196 196
#define TILES 391          // ceil(NN/128)
#define LDT 40             // A smem leading dim (fp16): 80B rows, conflict-free LDSM
#define ATSZ (128 * LDT)   // 5120 elems per A tile
#define STAGE2 (2 * ATSZ)  // stream-kernel stage: A + B

// ================= scratch =================
__device__ float g_x[NN * HH];
__device__ __half g_xh[NN * HH];
__device__ __half g_hG[NN * HH];
__device__ __half g_hL[NN * HH];
__device__ __half g_cat[NN * 2 * HH];
__device__ int   g_degG[NN];
__device__ int   g_degL[NN];
__device__ float g_dinvG[NN];
__device__ float g_dinvL[NN];
__device__ int   g_rowptrG[NN + 1];
__device__ int   g_rowptrL[NN + 1];
__device__ int   g_fillG[NN];
__device__ int   g_fillL[NN];
__device__ int2  g_edgeG[EGMAX];     // (col, coef bits)
__device__ int2  g_edgeL[ELMAX];
__device__ int   g_bsum[2][256];
// fp16 transposed weights [layer][N][K]
__device__ __half g_BG[DEPTH * HH * HH];
__device__ __half g_BL[DEPTH * HH * HH];
__device__ __half g_Blin[DEPTH * HH * 2 * HH];
__device__ __half g_Bfin[OUTC * HH];

// ================= setup kernels =================
__global__ void zero_deg_kernel(int* degG, int* degL, int n) {
    int i = blockIdx.x * blockDim.x + threadIdx.x;
    if (i < n) { degG[i] = 0; degL[i] = 0; }
}

__global__ void wsplit_all_kernel(const float* __restrict__ WG, const float* __restrict__ WLp,
                                  const float* __restrict__ linW, const float* __restrict__ finW,
                                  __half* BG, __half* BL, __half* Blin, __half* Bfin) {
    int seg = blockIdx.z;
    const float* W;
    __half* B;
    int K, N;
    if (seg < 3)      { K = HH;     N = HH;   W = WG  + (size_t)seg * HH * HH;           B = BG  + (size_t)seg * HH * HH; }
    else if (seg < 6) { K = HH;     N = HH;   W = WLp + (size_t)(seg - 3) * HH * HH;     B = BL  + (size_t)(seg - 3) * HH * HH; }
    else if (seg < 9) { K = 2 * HH; N = HH;   W = linW + (size_t)(seg - 6) * 2 * HH * HH; B = Blin + (size_t)(seg - 6) * 2 * HH * HH; }
    else              { K = HH;     N = OUTC; W = finW;                                   B = Bfin; }
    int n0 = blockIdx.x * 32, k0 = blockIdx.y * 32;
    if (n0 >= N || k0 >= K) return;
    __shared__ float t[32][33];
    int tx = threadIdx.x, ty = threadIdx.y;
    #pragma unroll
    for (int i = 0; i < 4; i++)
        t[ty + i * 8][tx] = W[(size_t)(k0 + ty + i * 8) * N + n0 + tx];
    __syncthreads();
    #pragma unroll
    for (int i = 0; i < 4; i++)
        B[(size_t)(n0 + ty + i * 8) * K + k0 + tx] = __float2half(t[tx][ty + i * 8]);
}

__global__ void init_split_kernel(const float4* __restrict__ xin4, float4* __restrict__ px4,
                                  __half* __restrict__ xh) {
    int i = blockIdx.x * blockDim.x + threadIdx.x;
    if (i >= NN * HH / 4) return;
    float4 v = xin4[i];
    px4[i] = v;
    __half2 a = __floats2half2_rn(v.x, v.y);
    __half2 b = __floats2half2_rn(v.z, v.w);
    uint2 u = { *(unsigned*)&a, *(unsigned*)&b };
    *reinterpret_cast<uint2*>(&xh[i * 4]) = u;
}

__global__ void count_deg_kernel(const int* __restrict__ dstG, int EG,
                                 const int* __restrict__ dstL, int EL,
                                 int* __restrict__ degG, int* __restrict__ degL) {
    int i = blockIdx.x * blockDim.x + threadIdx.x;
    if (i < EG) atomicAdd(&degG[dstG[i]], 1);
    else if (i < EG + EL) atomicAdd(&degL[dstL[i - EG]], 1);
}
__global__ void make_dinv_kernel(const int* __restrict__ degG, float* __restrict__ dinvG,
                                 const int* __restrict__ degL, float* __restrict__ dinvL, int n) {
    int i = blockIdx.x * blockDim.x + threadIdx.x;
    if (i < n) {
        dinvG[i] = rsqrtf((float)degG[i] + 2.0f);
        dinvL[i] = rsqrtf((float)degL[i] + 2.0f);
    }
}
__global__ void scan_block_kernel(const int* __restrict__ degG, const int* __restrict__ degL,
                                  int* __restrict__ rowG, int* __restrict__ rowL,
                                  int* __restrict__ bsum, int n) {
    __shared__ int s[256];
    const int* deg = blockIdx.y ? degL : degG;
    int* rowptr = blockIdx.y ? rowL : rowG;
    int* bs = bsum + blockIdx.y * 256;
    int i = blockIdx.x * 256 + threadIdx.x;
    int v = (i < n) ? deg[i] : 0;
    s[threadIdx.x] = v;
    __syncthreads();
    #pragma unroll
    for (int o = 1; o < 256; o <<= 1) {
        int t = (threadIdx.x >= o) ? s[threadIdx.x - o] : 0;
        __syncthreads();
        s[threadIdx.x] += t;
        __syncthreads();
    }
    if (i < n) rowptr[i] = s[threadIdx.x] - v;
    if (threadIdx.x == 255) bs[blockIdx.x] = s[255];
}
__global__ void scan_aux_kernel(int* bsum, int nb) {
    if (threadIdx.x == 0) {
        for (int y = 0; y < 2; y++) {
            int run = 0;
            int* b = bsum + y * 256;
            for (int i = 0; i < nb; i++) { int t = b[i]; b[i] = run; run += t; }
        }
    }
}
__global__ void scan_add_kernel(int* __restrict__ rowG, int* __restrict__ rowL,
                                int* __restrict__ fillG, int* __restrict__ fillL,
                                const int* __restrict__ bsum, int n, int EG, int EL) {
    int* rowptr = blockIdx.y ? rowL : rowG;
    int* fill = blockIdx.y ? fillL : fillG;
    const int* bs = bsum + blockIdx.y * 256;
    int E = blockIdx.y ? EL : EG;
    int i = blockIdx.x * 256 + threadIdx.x;
    if (i < n) {
        int v = rowptr[i] + bs[i >> 8];
        rowptr[i] = v;
        fill[i] = v;
    }
    if (i == 0) rowptr[n] = E;
}
__global__ void fill_csr_kernel(const int* __restrict__ Ge, int EG, const int* __restrict__ Le, int EL,
                                int* __restrict__ fillG, int* __restrict__ fillL,
                                int2* __restrict__ edgeG, int2* __restrict__ edgeL,
                                const float* __restrict__ dinvG, const float* __restrict__ dinvL) {
    int e = blockIdx.x * blockDim.x + threadIdx.x;
    const int* src; const int* dst; int* fill; int2* edge; const float* dinv; int E;
    if (blockIdx.y == 0) { src = Ge; dst = Ge + EG; fill = fillG; edge = edgeG; dinv = dinvG; E = EG; }
    else                 { src = Le; dst = Le + EL; fill = fillL; edge = edgeL; dinv = dinvL; E = EL; }
    if (e < E) {
        int s = src[e], d = dst[e];
        int p = atomicAdd(&fill[d], 1);
        float c = dinv[s] * dinv[d];
        edge[p] = make_int2(s, __float_as_int(c));
    }
}

// ================= fp16 GEMM, K=128, B resident, A double-buffered ============
template <int NOUT>
__global__ __launch_bounds__(256, 2)
void gemm_k128_kernel(const __half* __restrict__ A,
                      const __half* __restrict__ B0, const __half* __restrict__ B1,
                      float* __restrict__ C0, float* __restrict__ C1,
                      __half* __restrict__ Ch0, __half* __restrict__ Ch1,
                      const float* __restrict__ bias, int M) {
    constexpr int K = 128;
    constexpr int HALFN = NOUT / 2;
    constexpr int NF = HALFN / 16;
    constexpr int LDB = 136;
    constexpr int BTILE = NOUT * LDB;
    extern __shared__ __half sm[];
    __half* Bs = sm;
    __half* Astg = sm + BTILE;

    const __half* gB = blockIdx.y ? B1 : B0;
    float* C = blockIdx.y ? C1 : C0;
    __half* Ch = blockIdx.y ? Ch1 : Ch0;

    const int tid = threadIdx.x;
    const int wid = tid >> 5;
    const int lane = tid & 31;
    const int wr = wid >> 1;
    const int wc = wid & 1;
    const int row0 = blockIdx.x * 128;

    wmma::fragment<wmma::accumulator, 16, 16, 16, float> acc[2][NF];
    #pragma unroll
    for (int i = 0; i < 2; i++)
        #pragma unroll
        for (int j = 0; j < NF; j++)
            wmma::fill_fragment(acc[i][j], 0.0f);

    auto load_A = [&](int s, int kc) {
        __half* base = Astg + s * ATSZ;
        #pragma unroll
        for (int c = tid; c < 512; c += 256) {
            int r = c >> 2;
            int ko = (c & 3) * 8;
            int gr = row0 + r;
            if (gr < M)
                __pipeline_memcpy_async(&base[r * LDT + ko], &A[(size_t)gr * K + kc * 32 + ko], 16);
        }
    };

    #pragma unroll
    for (int c = tid; c < NOUT * 16; c += 256) {
        int r = c >> 4;
        int ko = (c & 15) * 8;
        __pipeline_memcpy_async(&Bs[r * LDB + ko], &gB[(size_t)r * K + ko], 16);
    }
    load_A(0, 0);
    __pipeline_commit();

    #pragma unroll
    for (int kc = 0; kc < 4; kc++) {
        if (kc + 1 < 4) {
            load_A((kc + 1) & 1, kc + 1);
            __pipeline_commit();
            __pipeline_wait_prior(1);
        } else {
            __pipeline_wait_prior(0);
        }
        __syncthreads();

        __half* Ahs = Astg + (kc & 1) * ATSZ;

        #pragma unroll
        for (int ks = 0; ks < 32; ks += 16) {
            int kcol = kc * 32 + ks;
            wmma::fragment<wmma::matrix_a, 16, 16, 16, __half, wmma::row_major> fa[2];
            #pragma unroll
            for (int i = 0; i < 2; i++)
                wmma::load_matrix_sync(fa[i], &Ahs[(wr * 32 + i * 16) * LDT + ks], LDT);
            wmma::fragment<wmma::matrix_b, 16, 16, 16, __half, wmma::col_major> fb[NF];
            #pragma unroll
            for (int j = 0; j < NF; j++)
                wmma::load_matrix_sync(fb[j], &Bs[(wc * HALFN + j * 16) * LDB + kcol], LDB);
            #pragma unroll
            for (int i = 0; i < 2; i++)
                #pragma unroll
                for (int j = 0; j < NF; j++)
                    wmma::mma_sync(acc[i][j], fa[i], fb[j], acc[i][j]);
        }
        __syncthreads();
    }

    float* st = reinterpret_cast<float*>(sm) + wid * 320;
    #pragma unroll
    for (int i = 0; i < 2; i++)
        #pragma unroll
        for (int j = 0; j < NF; j++) {
            wmma::store_matrix_sync(st, acc[i][j], 20, wmma::mem_row_major);
            __syncwarp();
            #pragma unroll
            for (int e = 0; e < 8; e++) {
                int idx = lane + e * 32;
                int r = idx >> 4;
                int c = idx & 15;
                int grow = row0 + wr * 32 + i * 16 + r;
                int gcol = wc * HALFN + j * 16 + c;
                if (grow < M) {
                    float v = st[r * 20 + c];
                    if (bias) v += __ldg(&bias[gcol]);
                    if (Ch) Ch[(size_t)grow * NOUT + gcol] = __float2half(v);
                    else    C[(size_t)grow * NOUT + gcol] = v;
                }
            }
            __syncwarp();
        }
}

// ================= fp16 K-streaming GEMM (concat, K=256) ============
template <int NOUT>
__global__ __launch_bounds__(256, 2)
void gemm_stream_kernel(const __half* __restrict__ A, int lda,
                        const __half* __restrict__ B,
                        float* __restrict__ C, __half* __restrict__ Chh,
                        const float* __restrict__ bias, int M, int K) {
    constexpr int HALFN = NOUT / 2;
    constexpr int NF = HALFN / 16;
    extern __shared__ __half sm[];

    const int tid = threadIdx.x;
    const int wid = tid >> 5;
    const int lane = tid & 31;
    const int wr = wid >> 1;
    const int wc = wid & 1;
    const int row0 = blockIdx.x * 128;

    wmma::fragment<wmma::accumulator, 16, 16, 16, float> acc[2][NF];
    #pragma unroll
    for (int i = 0; i < 2; i++)
        #pragma unroll
        for (int j = 0; j < NF; j++)
            wmma::fill_fragment(acc[i][j], 0.0f);

    const int nc = K >> 5;

    auto load_stage = [&](int s, int kc) {
        __half* base = sm + s * STAGE2;
        #pragma unroll
        for (int c = tid; c < 512; c += 256) {
            int r = c >> 2;
            int ko = (c & 3) * 8;
            int gr = row0 + r;
            if (gr < M)
                __pipeline_memcpy_async(&base[r * LDT + ko], &A[(size_t)gr * lda + kc * 32 + ko], 16);
        }
        #pragma unroll
        for (int c = tid; c < NOUT * 4; c += 256) {
            int r = c >> 2;
            int ko = (c & 3) * 8;
            __pipeline_memcpy_async(&base[ATSZ + r * LDT + ko], &B[(size_t)r * K + kc * 32 + ko], 16);
        }
    };

    load_stage(0, 0);
    __pipeline_commit();

    for (int kc = 0; kc < nc; kc++) {
        if (kc + 1 < nc) {
            load_stage((kc + 1) & 1, kc + 1);
            __pipeline_commit();
            __pipeline_wait_prior(1);
        } else {
            __pipeline_wait_prior(0);
        }
        __syncthreads();

        __half* Ahs = sm + (kc & 1) * STAGE2;
        __half* Bhs = Ahs + ATSZ;

        #pragma unroll
        for (int ks = 0; ks < 32; ks += 16) {
            wmma::fragment<wmma::matrix_a, 16, 16, 16, __half, wmma::row_major> fa[2];
            #pragma unroll
            for (int i = 0; i < 2; i++)
                wmma::load_matrix_sync(fa[i], &Ahs[(wr * 32 + i * 16) * LDT + ks], LDT);
            wmma::fragment<wmma::matrix_b, 16, 16, 16, __half, wmma::col_major> fb[NF];
            #pragma unroll
            for (int j = 0; j < NF; j++)
                wmma::load_matrix_sync(fb[j], &Bhs[(wc * HALFN + j * 16) * LDT + ks], LDT);
            #pragma unroll
            for (int i = 0; i < 2; i++)
                #pragma unroll
                for (int j = 0; j < NF; j++)
                    wmma::mma_sync(acc[i][j], fa[i], fb[j], acc[i][j]);
        }
        __syncthreads();
    }

    float* st = reinterpret_cast<float*>(sm) + wid * 320;
    #pragma unroll
    for (int i = 0; i < 2; i++)
        #pragma unroll
        for (int j = 0; j < NF; j++) {
            wmma::store_matrix_sync(st, acc[i][j], 20, wmma::mem_row_major);
            __syncwarp();
            #pragma unroll
            for (int e = 0; e < 8; e++) {
                int idx = lane + e * 32;
                int r = idx >> 4;
                int c = idx & 15;
                int grow = row0 + wr * 32 + i * 16 + r;
                int gcol = wc * HALFN + j * 16 + c;
                if (grow < M) {
                    float v = st[r * 20 + c];
                    if (bias) v += __ldg(&bias[gcol]);
                    C[(size_t)grow * NOUT + gcol] = v;
                    Chh[(size_t)grow * NOUT + gcol] = __float2half(v);
                }
            }
            __syncwarp();
        }
}

// ================= fused gather(fp16, int2 edges, unroll 8) + LN + ReLU + res + concat ======
__global__ void gather_ln_kernel(const uint2* __restrict__ hG8, const uint2* __restrict__ hL8,
                                 const float4* __restrict__ x4,
                                 const int* __restrict__ rowG, const int* __restrict__ rowL,
                                 const int2* __restrict__ edgeG, const int2* __restrict__ edgeL,
                                 const float* __restrict__ dinvG, const float* __restrict__ dinvL,
                                 const float4* __restrict__ biasG4, const float4* __restrict__ biasL4,
                                 const float4* __restrict__ g4, const float4* __restrict__ b4,
                                 __half* __restrict__ cat, int residual) {
    int warp = (blockIdx.x * blockDim.x + threadIdx.x) >> 5;
    int lane = threadIdx.x & 31;
    if (warp >= NN) return;
    int n = warp;
    int half = blockIdx.y;

    const uint2* h8 = half ? hL8 : hG8;
    const int* rowptr = half ? rowL : rowG;
    const int2* edge = half ? edgeL : edgeG;
    const float* dinv = half ? dinvL : dinvG;
    const float4* bias4 = half ? biasL4 : biasG4;

    auto h2f4 = [](uint2 u) -> float4 {
        __half2 a = *reinterpret_cast<__half2*>(&u.x);
        __half2 b = *reinterpret_cast<__half2*>(&u.y);
        float2 fa = __half22float2(a);
        float2 fb = __half22float2(b);
        return make_float4(fa.x, fa.y, fb.x, fb.y);
    };

    float dv = __ldg(&dinv[n]);
    float sl = 2.0f * dv * dv;
    float4 h = h2f4(h8[n * 32 + lane]);
    float4 bb = __ldg(&bias4[lane]);
    float4 acc;
    acc.x = h.x * sl + bb.x;
    acc.y = h.y * sl + bb.y;
    acc.z = h.z * sl + bb.z;
    acc.w = h.w * sl + bb.w;

    int e = __ldg(&rowptr[n]);
    int e1 = __ldg(&rowptr[n + 1]);

    // unroll 8: load 8 edge descriptors, then 8 rows in flight
    for (; e + 7 < e1; e += 8) {
        int2 p[8];
        #pragma unroll
        for (int q = 0; q < 8; q++) p[q] = __ldg(&edge[e + q]);
        uint2 u[8];
        #pragma unroll
        for (int q = 0; q < 8; q++) u[q] = h8[p[q].x * 32 + lane];
        #pragma unroll
        for (int q = 0; q < 8; q++) {
            float c = __int_as_float(p[q].y);
            float4 v = h2f4(u[q]);
            acc.x += c * v.x;
            acc.y += c * v.y;
            acc.z += c * v.z;
            acc.w += c * v.w;
        }
    }
    if (e + 3 < e1) {
        int2 p[4];
        #pragma unroll
        for (int q = 0; q < 4; q++) p[q] = __ldg(&edge[e + q]);
        uint2 u[4];
        #pragma unroll
        for (int q = 0; q < 4; q++) u[q] = h8[p[q].x * 32 + lane];
        #pragma unroll
        for (int q = 0; q < 4; q++) {
            float c = __int_as_float(p[q].y);
            float4 v = h2f4(u[q]);
            acc.x += c * v.x;
            acc.y += c * v.y;
            acc.z += c * v.z;
            acc.w += c * v.w;
        }
        e += 4;
    }
    for (; e < e1; e++) {
        int2 p0 = __ldg(&edge[e]);
        float c0 = __int_as_float(p0.y);
        float4 v0 = h2f4(h8[p0.x * 32 + lane]);
        acc.x += c0 * v0.x; acc.y += c0 * v0.y; acc.z += c0 * v0.z; acc.w += c0 * v0.w;
    }

    float s1 = acc.x + acc.y + acc.z + acc.w;
    float s2 = acc.x * acc.x + acc.y * acc.y + acc.z * acc.z + acc.w * acc.w;
    #pragma unroll
    for (int o = 16; o > 0; o >>= 1) {
        s1 += __shfl_xor_sync(0xffffffffu, s1, o);
        s2 += __shfl_xor_sync(0xffffffffu, s2, o);
    }
    float mu = s1 * (1.0f / HH);
    float var = s2 * (1.0f / HH) - mu * mu;
    float rstd = rsqrtf(var + LN_EPS);

    float4 gg = __ldg(&g4[lane]);
    float4 be = __ldg(&b4[lane]);
    float4 y;
    y.x = fmaxf((acc.x - mu) * rstd * gg.x + be.x, 0.0f);
    y.y = fmaxf((acc.y - mu) * rstd * gg.y + be.y, 0.0f);
    y.z = fmaxf((acc.z - mu) * rstd * gg.z + be.z, 0.0f);
    y.w = fmaxf((acc.w - mu) * rstd * gg.w + be.w, 0.0f);
    if (residual) {
        float4 xv = x4[n * 32 + lane];
        y.x += xv.x; y.y += xv.y; y.z += xv.z; y.w += xv.w;
    }
    __half2 ya = __floats2half2_rn(y.x, y.y);
    __half2 yb = __floats2half2_rn(y.z, y.w);
    uint2 u = { *(unsigned*)&ya, *(unsigned*)&yb };
    *reinterpret_cast<uint2*>(&cat[(size_t)n * 256 + half * 128 + lane * 4]) = u;
}

// ================= launch =================
extern "C" void kernel_launch(void* const* d_in, const int* in_sizes, int n_in,
                              void* d_out, int out_size) {
    const float* x_in  = (const float*)d_in[0];
    const float* WL    = (const float*)d_in[1];
    const float* bL    = (const float*)d_in[2];
    const float* WG    = (const float*)d_in[3];
    const float* bG    = (const float*)d_in[4];
    const float* linW  = (const float*)d_in[5];
    const float* linb  = (const float*)d_in[6];
    const float* ln_g  = (const float*)d_in[7];
    const float* ln_b  = (const float*)d_in[8];
    const float* finW  = (const float*)d_in[9];
    const float* finb  = (const float*)d_in[10];
    const int*   Ge    = (const int*)d_in[11];
    const int*   Le    = (const int*)d_in[12];
    int E_G = in_sizes[11] / 2;
    int E_L = in_sizes[12] / 2;
    float* out = (float*)d_out;

    float *px, *pdinvG, *pdinvL;
    __half *pxh, *phG, *phL, *pcat;
    int *pdegG, *pdegL, *prowG, *prowL, *pfillG, *pfillL, *pbsum;
    int2 *pedgeG, *pedgeL;
    __half *pBG, *pBL, *pBlin, *pBfin;
    cudaGetSymbolAddress((void**)&px,     g_x);
    cudaGetSymbolAddress((void**)&pxh,    g_xh);
    cudaGetSymbolAddress((void**)&phG,    g_hG);
    cudaGetSymbolAddress((void**)&phL,    g_hL);
    cudaGetSymbolAddress((void**)&pcat,   g_cat);
    cudaGetSymbolAddress((void**)&pdegG,  g_degG);
    cudaGetSymbolAddress((void**)&pdegL,  g_degL);
    cudaGetSymbolAddress((void**)&pdinvG, g_dinvG);
    cudaGetSymbolAddress((void**)&pdinvL, g_dinvL);
    cudaGetSymbolAddress((void**)&prowG,  g_rowptrG);
    cudaGetSymbolAddress((void**)&prowL,  g_rowptrL);
    cudaGetSymbolAddress((void**)&pfillG, g_fillG);
    cudaGetSymbolAddress((void**)&pfillL, g_fillL);
    cudaGetSymbolAddress((void**)&pedgeG, g_edgeG);
    cudaGetSymbolAddress((void**)&pedgeL, g_edgeL);
    cudaGetSymbolAddress((void**)&pbsum,  g_bsum);
    cudaGetSymbolAddress((void**)&pBG,    g_BG);
    cudaGetSymbolAddress((void**)&pBL,    g_BL);
    cudaGetSymbolAddress((void**)&pBlin,  g_Blin);
    cudaGetSymbolAddress((void**)&pBfin,  g_Bfin);

    const int STREAM_SMEM = 2 * STAGE2 * 2;                  // 40960
    const int K128_SMEM_128 = (128 * 136 + 2 * ATSZ) * 2;    // 55296
    const int K128_SMEM_64  = (64 * 136 + 2 * ATSZ) * 2;     // 37888

    static cudaStream_t s1 = nullptr;
    static cudaEvent_t evFork1, evJoin1, evFork2, evJoin2;
    static int attr_set = 0;
    if (!attr_set) {
        cudaFuncSetAttribute(gemm_stream_kernel<128>, cudaFuncAttributeMaxDynamicSharedMemorySize, STREAM_SMEM);
        cudaFuncSetAttribute(gemm_k128_kernel<128>, cudaFuncAttributeMaxDynamicSharedMemorySize, K128_SMEM_128);
        cudaFuncSetAttribute(gemm_k128_kernel<64>,  cudaFuncAttributeMaxDynamicSharedMemorySize, K128_SMEM_64);
        cudaStreamCreateWithFlags(&s1, cudaStreamNonBlocking);
        cudaEventCreateWithFlags(&evFork1, cudaEventDisableTiming);
        cudaEventCreateWithFlags(&evJoin1, cudaEventDisableTiming);
        cudaEventCreateWithFlags(&evFork2, cudaEventDisableTiming);
        cudaEventCreateWithFlags(&evJoin2, cudaEventDisableTiming);
        attr_set = 1;
    }

    // ---- fork: CSR build on side stream ----
    cudaEventRecord(evFork1, 0);
    cudaStreamWaitEvent(s1, evFork1, 0);

    zero_deg_kernel<<<NB196, 256, 0, s1>>>(pdegG, pdegL, NN);
    count_deg_kernel<<<(E_G + E_L + 255) / 256, 256, 0, s1>>>(Ge + E_G, E_G, Le + E_L, E_L, pdegG, pdegL);
    make_dinv_kernel<<<NB196, 256, 0, s1>>>(pdegG, pdinvG, pdegL, pdinvL, NN);
    scan_block_kernel<<<dim3(NB196, 2), 256, 0, s1>>>(pdegG, pdegL, prowG, prowL, pbsum, NN);
    scan_aux_kernel<<<1, 32, 0, s1>>>(pbsum, NB196);
    scan_add_kernel<<<dim3(NB196, 2), 256, 0, s1>>>(prowG, prowL, pfillG, pfillL, pbsum, NN, E_G, E_L);
    int fe = (E_G > E_L ? E_G : E_L);
    fill_csr_kernel<<<dim3((fe + 255) / 256, 2), 256, 0, s1>>>(Ge, E_G, Le, E_L,
        pfillG, pfillL, pedgeG, pedgeL, pdinvG, pdinvL);
    cudaEventRecord(evJoin1, s1);

    wsplit_all_kernel<<<dim3(4, 8, 10), dim3(32, 8)>>>(WG, WL, linW, finW, pBG, pBL, pBlin, pBfin);
    init_split_kernel<<<(NN * HH / 4 + 255) / 256, 256>>>((const float4*)x_in, (float4*)px, pxh);
    gemm_k128_kernel<128><<<dim3(TILES, 2), 256, K128_SMEM_128>>>(
        pxh, pBG, pBL, nullptr, nullptr, phG, phL, nullptr, NN);

    cudaStreamWaitEvent(0, evJoin1, 0);   // gather needs CSR

    int gatherBlocks = (NN * 32 + 255) / 256;

    for (int i = 0; i < DEPTH; i++) {
        if (i > 0) {
            size_t wo = (size_t)i * HH * HH;
            gemm_k128_kernel<128><<<dim3(TILES, 2), 256, K128_SMEM_128>>>(
                pxh, pBG + wo, pBL + wo, nullptr, nullptr, phG, phL, nullptr, NN);
        }
        int res = (i > 0) ? 1 : 0;
        gather_ln_kernel<<<dim3(gatherBlocks, 2), 256>>>(
            (const uint2*)phG, (const uint2*)phL, (const float4*)px,
            prowG, prowL, pedgeG, pedgeL, pdinvG, pdinvL,
            (const float4*)(bG + (size_t)i * HH), (const float4*)(bL + (size_t)i * HH),
            (const float4*)ln_g, (const float4*)ln_b, pcat, res);
        size_t lo = (size_t)i * HH * 2 * HH;
        gemm_stream_kernel<128><<<dim3(TILES, 1), 256, STREAM_SMEM>>>(
            pcat, 2 * HH, pBlin + lo, px, pxh, linb + (size_t)i * HH, NN, 2 * HH);
    }

    // ---- fork: out2 = x copy on side stream, final GEMM on main ----
    cudaEventRecord(evFork2, 0);
    cudaStreamWaitEvent(s1, evFork2, 0);
    cudaMemcpyAsync(out + (size_t)NN * OUTC, px, (size_t)NN * HH * sizeof(float),
                    cudaMemcpyDeviceToDevice, s1);
    cudaEventRecord(evJoin2, s1);

    gemm_k128_kernel<64><<<dim3(TILES, 1), 256, K128_SMEM_64>>>(
        pxh, pBfin, nullptr, out, nullptr, nullptr, nullptr, finb, NN);

    cudaStreamWaitEvent(0, evJoin2, 0);
}

// round 14
// speedup vs baseline: 6.7468x; 1.0230x over previous
#include <cuda_runtime.h>
#include <cuda_bf16.h>
#include <cuda_fp16.h>
#include <cuda_pipeline.h>
#include <mma.h>
#include <cstdint>

using namespace nvcuda;

#define NN 50000
#define HH 128
#define OUTC 64
#define DEPTH 3
#define LN_EPS 1e-5f
#define EGMAX 600000
#define ELMAX 400000
#define NB196 196
#define TILES 391          // ceil(NN/128)
#define LDT 40             // A smem leading dim (fp16): 80B rows, conflict-free LDSM
#define ATSZ (128 * LDT)   // 5120 elems per A tile

// ================= scratch =================
__device__ float g_x[NN * HH];
__device__ __half g_xh[NN * HH];
__device__ __half g_hG[NN * HH];
__device__ __half g_hL[NN * HH];
__device__ __half g_cat[NN * 2 * HH];
__device__ int   g_degG[NN];
__device__ int   g_degL[NN];
__device__ float g_dinvG[NN];
__device__ float g_dinvL[NN];
__device__ int   g_rowptrG[NN + 1];
__device__ int   g_rowptrL[NN + 1];
__device__ int   g_fillG[NN];
__device__ int   g_fillL[NN];
__device__ int2  g_edgeG[EGMAX];     // (col, coef bits)
__device__ int2  g_edgeL[ELMAX];
__device__ int   g_bsum[2][256];
// fp16 transposed weights [layer][N][K]
__device__ __half g_BG[DEPTH * HH * HH];
__device__ __half g_BL[DEPTH * HH * HH];
__device__ __half g_Blin[DEPTH * HH * 2 * HH];
__device__ __half g_Bfin[OUTC * HH];

// ================= setup kernels =================
__global__ void zero_deg_kernel(int* degG, int* degL, int n) {
    int i = blockIdx.x * blockDim.x + threadIdx.x;
    if (i < n) { degG[i] = 0; degL[i] = 0; }
}

__global__ void wsplit_all_kernel(const float* __restrict__ WG, const float* __restrict__ WLp,
                                  const float* __restrict__ linW, const float* __restrict__ finW,
                                  __half* BG, __half* BL, __half* Blin, __half* Bfin) {
    int seg = blockIdx.z;
    const float* W;
    __half* B;
    int K, N;
    if (seg < 3)      { K = HH;     N = HH;   W = WG  + (size_t)seg * HH * HH;           B = BG  + (size_t)seg * HH * HH; }
    else if (seg < 6) { K = HH;     N = HH;   W = WLp + (size_t)(seg - 3) * HH * HH;     B = BL  + (size_t)(seg - 3) * HH * HH; }
    else if (seg < 9) { K = 2 * HH; N = HH;   W = linW + (size_t)(seg - 6) * 2 * HH * HH; B = Blin + (size_t)(seg - 6) * 2 * HH * HH; }
    else              { K = HH;     N = OUTC; W = finW;                                   B = Bfin; }
    int n0 = blockIdx.x * 32, k0 = blockIdx.y * 32;
    if (n0 >= N || k0 >= K) return;
    __shared__ float t[32][33];
    int tx = threadIdx.x, ty = threadIdx.y;
    #pragma unroll
    for (int i = 0; i < 4; i++)
        t[ty + i * 8][tx] = W[(size_t)(k0 + ty + i * 8) * N + n0 + tx];
    __syncthreads();
    #pragma unroll
    for (int i = 0; i < 4; i++)
        B[(size_t)(n0 + ty + i * 8) * K + k0 + tx] = __float2half(t[tx][ty + i * 8]);
}

__global__ void init_split_kernel(const float4* __restrict__ xin4, float4* __restrict__ px4,
                                  __half* __restrict__ xh) {
    int i = blockIdx.x * blockDim.x + threadIdx.x;
    if (i >= NN * HH / 4) return;
    float4 v = xin4[i];
    px4[i] = v;
    __half2 a = __floats2half2_rn(v.x, v.y);
    __half2 b = __floats2half2_rn(v.z, v.w);
    uint2 u = { *(unsigned*)&a, *(unsigned*)&b };
    *reinterpret_cast<uint2*>(&xh[i * 4]) = u;
}

__global__ void count_deg_kernel(const int* __restrict__ dstG, int EG,
                                 const int* __restrict__ dstL, int EL,
                                 int* __restrict__ degG, int* __restrict__ degL) {
    int i = blockIdx.x * blockDim.x + threadIdx.x;
    if (i < EG) atomicAdd(&degG[dstG[i]], 1);
    else if (i < EG + EL) atomicAdd(&degL[dstL[i - EG]], 1);
}
__global__ void make_dinv_kernel(const int* __restrict__ degG, float* __restrict__ dinvG,
                                 const int* __restrict__ degL, float* __restrict__ dinvL, int n) {
    int i = blockIdx.x * blockDim.x + threadIdx.x;
    if (i < n) {
        dinvG[i] = rsqrtf((float)degG[i] + 2.0f);
        dinvL[i] = rsqrtf((float)degL[i] + 2.0f);
    }
}
__global__ void scan_block_kernel(const int* __restrict__ degG, const int* __restrict__ degL,
                                  int* __restrict__ rowG, int* __restrict__ rowL,
                                  int* __restrict__ bsum, int n) {
    __shared__ int s[256];
    const int* deg = blockIdx.y ? degL : degG;
    int* rowptr = blockIdx.y ? rowL : rowG;
    int* bs = bsum + blockIdx.y * 256;
    int i = blockIdx.x * 256 + threadIdx.x;
    int v = (i < n) ? deg[i] : 0;
    s[threadIdx.x] = v;
    __syncthreads();
    #pragma unroll
    for (int o = 1; o < 256; o <<= 1) {
        int t = (threadIdx.x >= o) ? s[threadIdx.x - o] : 0;
        __syncthreads();
        s[threadIdx.x] += t;
        __syncthreads();
    }
    if (i < n) rowptr[i] = s[threadIdx.x] - v;
    if (threadIdx.x == 255) bs[blockIdx.x] = s[255];
}
__global__ void scan_aux_kernel(int* bsum, int nb) {
    if (threadIdx.x == 0) {
        for (int y = 0; y < 2; y++) {
            int run = 0;
            int* b = bsum + y * 256;
            for (int i = 0; i < nb; i++) { int t = b[i]; b[i] = run; run += t; }
        }
    }
}
__global__ void scan_add_kernel(int* __restrict__ rowG, int* __restrict__ rowL,
                                int* __restrict__ fillG, int* __restrict__ fillL,
                                const int* __restrict__ bsum, int n, int EG, int EL) {
    int* rowptr = blockIdx.y ? rowL : rowG;
    int* fill = blockIdx.y ? fillL : fillG;
    const int* bs = bsum + blockIdx.y * 256;
    int E = blockIdx.y ? EL : EG;
    int i = blockIdx.x * 256 + threadIdx.x;
    if (i < n) {
        int v = rowptr[i] + bs[i >> 8];
        rowptr[i] = v;
        fill[i] = v;
    }
    if (i == 0) rowptr[n] = E;
}
__global__ void fill_csr_kernel(const int* __restrict__ Ge, int EG, const int* __restrict__ Le, int EL,
                                int* __restrict__ fillG, int* __restrict__ fillL,
                                int2* __restrict__ edgeG, int2* __restrict__ edgeL,
                                const float* __restrict__ dinvG, const float* __restrict__ dinvL) {
    int e = blockIdx.x * blockDim.x + threadIdx.x;
    const int* src; const int* dst; int* fill; int2* edge; const float* dinv; int E;
    if (blockIdx.y == 0) { src = Ge; dst = Ge + EG; fill = fillG; edge = edgeG; dinv = dinvG; E = EG; }
    else                 { src = Le; dst = Le + EL; fill = fillL; edge = edgeL; dinv = dinvL; E = EL; }
    if (e < E) {
        int s = src[e], d = dst[e];
        int p = atomicAdd(&fill[d], 1);
        float c = dinv[s] * dinv[d];
        edge[p] = make_int2(s, __float_as_int(c));
    }
}

// ================= fp16 GEMM, B resident in smem, A double-buffered ============
// Branch select via blockIdx.y: (B, C, Ch, bias) pointer pairs. ldc passed (col offset
// folded into pointers by caller). Ch non-null -> fp16 out; else fp32 out.
// Cc non-null alongside Ch -> write BOTH fp32 (Cc) and fp16 (Ch).
template <int NOUT, int KK>
__global__ __launch_bounds__(256, 2)
void gemm_bres_kernel(const __half* __restrict__ A, int lda,
                      const __half* __restrict__ B0, const __half* __restrict__ B1,
                      float* __restrict__ C0, float* __restrict__ C1, int ldc,
                      __half* __restrict__ Ch0, __half* __restrict__ Ch1,
                      const float* __restrict__ bias0, const float* __restrict__ bias1,
                      int M) {
    constexpr int HALFN = NOUT / 2;
    constexpr int NF = HALFN / 16;
    constexpr int LDB = KK + 8;
    constexpr int BTILE = NOUT * LDB;
    constexpr int NC = KK / 32;
    extern __shared__ __half sm[];
    __half* Bs = sm;
    __half* Astg = sm + BTILE;

    const __half* gB = blockIdx.y ? B1 : B0;
    float* C = blockIdx.y ? C1 : C0;
    __half* Ch = blockIdx.y ? Ch1 : Ch0;
    const float* bias = blockIdx.y ? bias1 : bias0;

    const int tid = threadIdx.x;
    const int wid = tid >> 5;
    const int lane = tid & 31;
    const int wr = wid >> 1;
    const int wc = wid & 1;
    const int row0 = blockIdx.x * 128;

    wmma::fragment<wmma::accumulator, 16, 16, 16, float> acc[2][NF];
    #pragma unroll
    for (int i = 0; i < 2; i++)
        #pragma unroll
        for (int j = 0; j < NF; j++)
            wmma::fill_fragment(acc[i][j], 0.0f);

    auto load_A = [&](int s, int kc) {
        __half* base = Astg + s * ATSZ;
        #pragma unroll
        for (int c = tid; c < 512; c += 256) {
            int r = c >> 2;
            int ko = (c & 3) * 8;
            int gr = row0 + r;
            if (gr < M)
                __pipeline_memcpy_async(&base[r * LDT + ko], &A[(size_t)gr * lda + kc * 32 + ko], 16);
        }
    };

    #pragma unroll
    for (int c = tid; c < NOUT * (KK / 8); c += 256) {
        int r = c / (KK / 8);
        int ko = (c % (KK / 8)) * 8;
        __pipeline_memcpy_async(&Bs[r * LDB + ko], &gB[(size_t)r * KK + ko], 16);
    }
    load_A(0, 0);
    __pipeline_commit();

    #pragma unroll
    for (int kc = 0; kc < NC; kc++) {
        if (kc + 1 < NC) {
            load_A((kc + 1) & 1, kc + 1);
            __pipeline_commit();
            __pipeline_wait_prior(1);
        } else {
            __pipeline_wait_prior(0);
        }
        __syncthreads();

        __half* Ahs = Astg + (kc & 1) * ATSZ;

        #pragma unroll
        for (int ks = 0; ks < 32; ks += 16) {
            int kcol = kc * 32 + ks;
            wmma::fragment<wmma::matrix_a, 16, 16, 16, __half, wmma::row_major> fa[2];
            #pragma unroll
            for (int i = 0; i < 2; i++)
                wmma::load_matrix_sync(fa[i], &Ahs[(wr * 32 + i * 16) * LDT + ks], LDT);
            wmma::fragment<wmma::matrix_b, 16, 16, 16, __half, wmma::col_major> fb[NF];
            #pragma unroll
            for (int j = 0; j < NF; j++)
                wmma::load_matrix_sync(fb[j], &Bs[(wc * HALFN + j * 16) * LDB + kcol], LDB);
            #pragma unroll
            for (int i = 0; i < 2; i++)
                #pragma unroll
                for (int j = 0; j < NF; j++)
                    wmma::mma_sync(acc[i][j], fa[i], fb[j], acc[i][j]);
        }
        __syncthreads();
    }

    float* st = reinterpret_cast<float*>(sm) + wid * 320;
    #pragma unroll
    for (int i = 0; i < 2; i++)
        #pragma unroll
        for (int j = 0; j < NF; j++) {
            wmma::store_matrix_sync(st, acc[i][j], 20, wmma::mem_row_major);
            __syncwarp();
            #pragma unroll
            for (int e = 0; e < 8; e++) {
                int idx = lane + e * 32;
                int r = idx >> 4;
                int c = idx & 15;
                int grow = row0 + wr * 32 + i * 16 + r;
                int gcol = wc * HALFN + j * 16 + c;
                if (grow < M) {
                    float v = st[r * 20 + c];
                    if (bias) v += __ldg(&bias[gcol]);
                    if (C)  C[(size_t)grow * ldc + gcol] = v;
                    if (Ch) Ch[(size_t)grow * ldc + gcol] = __float2half(v);
                }
            }
            __syncwarp();
        }
}

// ================= fused gather(fp16, int2 edges, unroll 8) + LN + ReLU + res + concat ======
__global__ void gather_ln_kernel(const uint2* __restrict__ hG8, const uint2* __restrict__ hL8,
                                 const float4* __restrict__ x4,
                                 const int* __restrict__ rowG, const int* __restrict__ rowL,
                                 const int2* __restrict__ edgeG, const int2* __restrict__ edgeL,
                                 const float* __restrict__ dinvG, const float* __restrict__ dinvL,
                                 const float4* __restrict__ biasG4, const float4* __restrict__ biasL4,
                                 const float4* __restrict__ g4, const float4* __restrict__ b4,
                                 __half* __restrict__ cat, int residual) {
    int warp = (blockIdx.x * blockDim.x + threadIdx.x) >> 5;
    int lane = threadIdx.x & 31;
    if (warp >= NN) return;
    int n = warp;
    int half = blockIdx.y;

    const uint2* h8 = half ? hL8 : hG8;
    const int* rowptr = half ? rowL : rowG;
    const int2* edge = half ? edgeL : edgeG;
    const float* dinv = half ? dinvL : dinvG;
    const float4* bias4 = half ? biasL4 : biasG4;

    auto h2f4 = [](uint2 u) -> float4 {
        __half2 a = *reinterpret_cast<__half2*>(&u.x);
        __half2 b = *reinterpret_cast<__half2*>(&u.y);
        float2 fa = __half22float2(a);
        float2 fb = __half22float2(b);
        return make_float4(fa.x, fa.y, fb.x, fb.y);
    };

    float dv = __ldg(&dinv[n]);
    float sl = 2.0f * dv * dv;
    float4 h = h2f4(h8[n * 32 + lane]);
    float4 bb = __ldg(&bias4[lane]);
    float4 acc;
    acc.x = h.x * sl + bb.x;
    acc.y = h.y * sl + bb.y;
    acc.z = h.z * sl + bb.z;
    acc.w = h.w * sl + bb.w;

    int e = __ldg(&rowptr[n]);
    int e1 = __ldg(&rowptr[n + 1]);

    for (; e + 7 < e1; e += 8) {
        int2 p[8];
        #pragma unroll
        for (int q = 0; q < 8; q++) p[q] = __ldg(&edge[e + q]);
        uint2 u[8];
        #pragma unroll
        for (int q = 0; q < 8; q++) u[q] = h8[p[q].x * 32 + lane];
        #pragma unroll
        for (int q = 0; q < 8; q++) {
            float c = __int_as_float(p[q].y);
            float4 v = h2f4(u[q]);
            acc.x += c * v.x;
            acc.y += c * v.y;
            acc.z += c * v.z;
            acc.w += c * v.w;
        }
    }
    if (e + 3 < e1) {
        int2 p[4];
        #pragma unroll
        for (int q = 0; q < 4; q++) p[q] = __ldg(&edge[e + q]);
        uint2 u[4];
        #pragma unroll
        for (int q = 0; q < 4; q++) u[q] = h8[p[q].x * 32 + lane];
        #pragma unroll
        for (int q = 0; q < 4; q++) {
            float c = __int_as_float(p[q].y);
            float4 v = h2f4(u[q]);
            acc.x += c * v.x;
            acc.y += c * v.y;
            acc.z += c * v.z;
            acc.w += c * v.w;
        }
        e += 4;
    }
    for (; e < e1; e++) {
        int2 p0 = __ldg(&edge[e]);
        float c0 = __int_as_float(p0.y);
        float4 v0 = h2f4(h8[p0.x * 32 + lane]);
        acc.x += c0 * v0.x; acc.y += c0 * v0.y; acc.z += c0 * v0.z; acc.w += c0 * v0.w;
    }

    float s1 = acc.x + acc.y + acc.z + acc.w;
    float s2 = acc.x * acc.x + acc.y * acc.y + acc.z * acc.z + acc.w * acc.w;
    #pragma unroll
    for (int o = 16; o > 0; o >>= 1) {
        s1 += __shfl_xor_sync(0xffffffffu, s1, o);
        s2 += __shfl_xor_sync(0xffffffffu, s2, o);
    }
    float mu = s1 * (1.0f / HH);
    float var = s2 * (1.0f / HH) - mu * mu;
    float rstd = rsqrtf(var + LN_EPS);

    float4 gg = __ldg(&g4[lane]);
    float4 be = __ldg(&b4[lane]);
    float4 y;
    y.x = fmaxf((acc.x - mu) * rstd * gg.x + be.x, 0.0f);
    y.y = fmaxf((acc.y - mu) * rstd * gg.y + be.y, 0.0f);
    y.z = fmaxf((acc.z - mu) * rstd * gg.z + be.z, 0.0f);
    y.w = fmaxf((acc.w - mu) * rstd * gg.w + be.w, 0.0f);
    if (residual) {
        float4 xv = x4[n * 32 + lane];
        y.x += xv.x; y.y += xv.y; y.z += xv.z; y.w += xv.w;
    }
    __half2 ya = __floats2half2_rn(y.x, y.y);
    __half2 yb = __floats2half2_rn(y.z, y.w);
    uint2 u = { *(unsigned*)&ya, *(unsigned*)&yb };
    *reinterpret_cast<uint2*>(&cat[(size_t)n * 256 + half * 128 + lane * 4]) = u;
}

// ================= launch =================
extern "C" void kernel_launch(void* const* d_in, const int* in_sizes, int n_in,
                              void* d_out, int out_size) {
    const float* x_in  = (const float*)d_in[0];
    const float* WL    = (const float*)d_in[1];
    const float* bL    = (const float*)d_in[2];
    const float* WG    = (const float*)d_in[3];
    const float* bG    = (const float*)d_in[4];
    const float* linW  = (const float*)d_in[5];
    const float* linb  = (const float*)d_in[6];
    const float* ln_g  = (const float*)d_in[7];
    const float* ln_b  = (const float*)d_in[8];
    const float* finW  = (const float*)d_in[9];
    const float* finb  = (const float*)d_in[10];
    const int*   Ge    = (const int*)d_in[11];
    const int*   Le    = (const int*)d_in[12];
    int E_G = in_sizes[11] / 2;
    int E_L = in_sizes[12] / 2;
    float* out = (float*)d_out;

    float *px, *pdinvG, *pdinvL;
    __half *pxh, *phG, *phL, *pcat;
    int *pdegG, *pdegL, *prowG, *prowL, *pfillG, *pfillL, *pbsum;
    int2 *pedgeG, *pedgeL;
    __half *pBG, *pBL, *pBlin, *pBfin;
    cudaGetSymbolAddress((void**)&px,     g_x);
    cudaGetSymbolAddress((void**)&pxh,    g_xh);
    cudaGetSymbolAddress((void**)&phG,    g_hG);
    cudaGetSymbolAddress((void**)&phL,    g_hL);
    cudaGetSymbolAddress((void**)&pcat,   g_cat);
    cudaGetSymbolAddress((void**)&pdegG,  g_degG);
    cudaGetSymbolAddress((void**)&pdegL,  g_degL);
    cudaGetSymbolAddress((void**)&pdinvG, g_dinvG);
    cudaGetSymbolAddress((void**)&pdinvL, g_dinvL);
    cudaGetSymbolAddress((void**)&prowG,  g_rowptrG);
    cudaGetSymbolAddress((void**)&prowL,  g_rowptrL);
    cudaGetSymbolAddress((void**)&pfillG, g_fillG);
    cudaGetSymbolAddress((void**)&pfillL, g_fillL);
    cudaGetSymbolAddress((void**)&pedgeG, g_edgeG);
    cudaGetSymbolAddress((void**)&pedgeL, g_edgeL);
    cudaGetSymbolAddress((void**)&pbsum,  g_bsum);
    cudaGetSymbolAddress((void**)&pBG,    g_BG);
    cudaGetSymbolAddress((void**)&pBL,    g_BL);
    cudaGetSymbolAddress((void**)&pBlin,  g_Blin);
    cudaGetSymbolAddress((void**)&pBfin,  g_Bfin);

    const int SM_DUAL   = (128 * 136 + 2 * ATSZ) * 2;    // 55296
    const int SM_CONCAT = (64 * 264 + 2 * ATSZ) * 2;     // 54272
    const int SM_FINAL  = (64 * 136 + 2 * ATSZ) * 2;     // 37888

    static cudaStream_t s1 = nullptr;
    static cudaEvent_t evFork1, evJoin1, evFork2, evJoin2;
    static int attr_set = 0;
    if (!attr_set) {
        cudaFuncSetAttribute((const void*)gemm_bres_kernel<128, 128>, cudaFuncAttributeMaxDynamicSharedMemorySize, SM_DUAL);
        cudaFuncSetAttribute((const void*)gemm_bres_kernel<64, 256>,  cudaFuncAttributeMaxDynamicSharedMemorySize, SM_CONCAT);
        cudaFuncSetAttribute((const void*)gemm_bres_kernel<64, 128>,  cudaFuncAttributeMaxDynamicSharedMemorySize, SM_FINAL);
        cudaStreamCreateWithFlags(&s1, cudaStreamNonBlocking);
        cudaEventCreateWithFlags(&evFork1, cudaEventDisableTiming);
        cudaEventCreateWithFlags(&evJoin1, cudaEventDisableTiming);
        cudaEventCreateWithFlags(&evFork2, cudaEventDisableTiming);
        cudaEventCreateWithFlags(&evJoin2, cudaEventDisableTiming);
        attr_set = 1;
    }

    // ---- fork: CSR build on side stream ----
    cudaEventRecord(evFork1, 0);
    cudaStreamWaitEvent(s1, evFork1, 0);

    zero_deg_kernel<<<NB196, 256, 0, s1>>>(pdegG, pdegL, NN);
    count_deg_kernel<<<(E_G + E_L + 255) / 256, 256, 0, s1>>>(Ge + E_G, E_G, Le + E_L, E_L, pdegG, pdegL);
    make_dinv_kernel<<<NB196, 256, 0, s1>>>(pdegG, pdinvG, pdegL, pdinvL, NN);
    scan_block_kernel<<<dim3(NB196, 2), 256, 0, s1>>>(pdegG, pdegL, prowG, prowL, pbsum, NN);
    scan_aux_kernel<<<1, 32, 0, s1>>>(pbsum, NB196);
    scan_add_kernel<<<dim3(NB196, 2), 256, 0, s1>>>(prowG, prowL, pfillG, pfillL, pbsum, NN, E_G, E_L);
    int fe = (E_G > E_L ? E_G : E_L);
    fill_csr_kernel<<<dim3((fe + 255) / 256, 2), 256, 0, s1>>>(Ge, E_G, Le, E_L,
        pfillG, pfillL, pedgeG, pedgeL, pdinvG, pdinvL);
    cudaEventRecord(evJoin1, s1);

    wsplit_all_kernel<<<dim3(4, 8, 10), dim3(32, 8)>>>(WG, WL, linW, finW, pBG, pBL, pBlin, pBfin);
    init_split_kernel<<<(NN * HH / 4 + 255) / 256, 256>>>((const float4*)x_in, (float4*)px, pxh);
    gemm_bres_kernel<128, 128><<<dim3(TILES, 2), 256, SM_DUAL>>>(
        pxh, HH, pBG, pBL, nullptr, nullptr, HH, phG, phL, nullptr, nullptr, NN);

    cudaStreamWaitEvent(0, evJoin1, 0);   // gather needs CSR

    int gatherBlocks = (NN * 32 + 255) / 256;

    for (int i = 0; i < DEPTH; i++) {
        if (i > 0) {
            size_t wo = (size_t)i * HH * HH;
            gemm_bres_kernel<128, 128><<<dim3(TILES, 2), 256, SM_DUAL>>>(
                pxh, HH, pBG + wo, pBL + wo, nullptr, nullptr, HH, phG, phL, nullptr, nullptr, NN);
        }
        int res = (i > 0) ? 1 : 0;
        gather_ln_kernel<<<dim3(gatherBlocks, 2), 256>>>(
            (const uint2*)phG, (const uint2*)phL, (const float4*)px,
            prowG, prowL, pedgeG, pedgeL, pdinvG, pdinvL,
            (const float4*)(bG + (size_t)i * HH), (const float4*)(bL + (size_t)i * HH),
            (const float4*)ln_g, (const float4*)ln_b, pcat, res);
        // concat linear, N-split into two 64-col halves via grid.y
        const __half* Bl0 = pBlin + (size_t)i * HH * 2 * HH;
        const __half* Bl1 = Bl0 + (size_t)64 * 2 * HH;
        const float* lb = linb + (size_t)i * HH;
        gemm_bres_kernel<64, 256><<<dim3(TILES, 2), 256, SM_CONCAT>>>(
            pcat, 2 * HH, Bl0, Bl1, px, px + 64, HH, pxh, pxh + 64, lb, lb + 64, NN);
    }

    // ---- fork: out2 = x copy on side stream, final GEMM on main ----
    cudaEventRecord(evFork2, 0);
    cudaStreamWaitEvent(s1, evFork2, 0);
    cudaMemcpyAsync(out + (size_t)NN * OUTC, px, (size_t)NN * HH * sizeof(float),
                    cudaMemcpyDeviceToDevice, s1);
    cudaEventRecord(evJoin2, s1);

    gemm_bres_kernel<64, 128><<<dim3(TILES, 1), 256, SM_FINAL>>>(
        pxh, HH, pBfin, nullptr, out, nullptr, OUTC, nullptr, nullptr, finb, nullptr, NN);

    cudaStreamWaitEvent(0, evJoin2, 0);
}

// round 15
// speedup vs baseline: 6.9392x; 1.0285x over previous
#include <cuda_runtime.h>
#include <cuda_bf16.h>
#include <cuda_fp16.h>
#include <cuda_pipeline.h>
#include <mma.h>
#include <cstdint>

using namespace nvcuda;

#define NN 50000
#define HH 128
#define OUTC 64
#define DEPTH 3
#define LN_EPS 1e-5f
#define EGMAX 600000
#define ELMAX 400000
#define NB196 196
#define TILES 391          // ceil(NN/128)
#define LDT 40             // A smem leading dim (fp16): 80B rows, conflict-free LDSM
#define ATSZ (128 * LDT)   // 5120 elems per A tile

// ================= scratch =================
__device__ float g_x[NN * HH];
__device__ __half g_xh[NN * HH];
__device__ __half g_hG[NN * HH];
__device__ __half g_hL[NN * HH];
__device__ __half g_cat[NN * 2 * HH];
__device__ int   g_degG[NN];
__device__ int   g_degL[NN];
__device__ float g_dinvG[NN];
__device__ float g_dinvL[NN];
__device__ int   g_rowptrG[NN + 1];
__device__ int   g_rowptrL[NN + 1];
__device__ int   g_fillG[NN];
__device__ int   g_fillL[NN];
__device__ int2  g_edgeG[EGMAX];     // (col, coef bits)
__device__ int2  g_edgeL[ELMAX];
__device__ int   g_bsum[2][256];
// fp16 transposed weights [layer][N][K]
__device__ __half g_BG[DEPTH * HH * HH];
__device__ __half g_BL[DEPTH * HH * HH];
__device__ __half g_Blin[DEPTH * HH * 2 * HH];
__device__ __half g_Bfin[OUTC * HH];

// ================= setup kernels =================
__global__ void zero_deg_kernel(int* degG, int* degL, int n) {
    int i = blockIdx.x * blockDim.x + threadIdx.x;
    if (i < n) { degG[i] = 0; degL[i] = 0; }
}

__global__ void wsplit_all_kernel(const float* __restrict__ WG, const float* __restrict__ WLp,
                                  const float* __restrict__ linW, const float* __restrict__ finW,
                                  __half* BG, __half* BL, __half* Blin, __half* Bfin) {
    int seg = blockIdx.z;
    const float* W;
    __half* B;
    int K, N;
    if (seg < 3)      { K = HH;     N = HH;   W = WG  + (size_t)seg * HH * HH;           B = BG  + (size_t)seg * HH * HH; }
    else if (seg < 6) { K = HH;     N = HH;   W = WLp + (size_t)(seg - 3) * HH * HH;     B = BL  + (size_t)(seg - 3) * HH * HH; }
    else if (seg < 9) { K = 2 * HH; N = HH;   W = linW + (size_t)(seg - 6) * 2 * HH * HH; B = Blin + (size_t)(seg - 6) * 2 * HH * HH; }
    else              { K = HH;     N = OUTC; W = finW;                                   B = Bfin; }
    int n0 = blockIdx.x * 32, k0 = blockIdx.y * 32;
    if (n0 >= N || k0 >= K) return;
    __shared__ float t[32][33];
    int tx = threadIdx.x, ty = threadIdx.y;
    #pragma unroll
    for (int i = 0; i < 4; i++)
        t[ty + i * 8][tx] = W[(size_t)(k0 + ty + i * 8) * N + n0 + tx];
    __syncthreads();
    #pragma unroll
    for (int i = 0; i < 4; i++)
        B[(size_t)(n0 + ty + i * 8) * K + k0 + tx] = __float2half(t[tx][ty + i * 8]);
}

__global__ void init_split_kernel(const float4* __restrict__ xin4, float4* __restrict__ px4,
                                  __half* __restrict__ xh) {
    int i = blockIdx.x * blockDim.x + threadIdx.x;
    if (i >= NN * HH / 4) return;
    float4 v = xin4[i];
    px4[i] = v;
    __half2 a = __floats2half2_rn(v.x, v.y);
    __half2 b = __floats2half2_rn(v.z, v.w);
    uint2 u = { *(unsigned*)&a, *(unsigned*)&b };
    *reinterpret_cast<uint2*>(&xh[i * 4]) = u;
}

__global__ void count_deg_kernel(const int* __restrict__ dstG, int EG,
                                 const int* __restrict__ dstL, int EL,
                                 int* __restrict__ degG, int* __restrict__ degL) {
    int i = blockIdx.x * blockDim.x + threadIdx.x;
    if (i < EG) atomicAdd(&degG[dstG[i]], 1);
    else if (i < EG + EL) atomicAdd(&degL[dstL[i - EG]], 1);
}
__global__ void make_dinv_kernel(const int* __restrict__ degG, float* __restrict__ dinvG,
                                 const int* __restrict__ degL, float* __restrict__ dinvL, int n) {
    int i = blockIdx.x * blockDim.x + threadIdx.x;
    if (i < n) {
        dinvG[i] = rsqrtf((float)degG[i] + 2.0f);
        dinvL[i] = rsqrtf((float)degL[i] + 2.0f);
    }
}
__global__ void scan_block_kernel(const int* __restrict__ degG, const int* __restrict__ degL,
                                  int* __restrict__ rowG, int* __restrict__ rowL,
                                  int* __restrict__ bsum, int n) {
    __shared__ int s[256];
    const int* deg = blockIdx.y ? degL : degG;
    int* rowptr = blockIdx.y ? rowL : rowG;
    int* bs = bsum + blockIdx.y * 256;
    int i = blockIdx.x * 256 + threadIdx.x;
    int v = (i < n) ? deg[i] : 0;
    s[threadIdx.x] = v;
    __syncthreads();
    #pragma unroll
    for (int o = 1; o < 256; o <<= 1) {
        int t = (threadIdx.x >= o) ? s[threadIdx.x - o] : 0;
        __syncthreads();
        s[threadIdx.x] += t;
        __syncthreads();
    }
    if (i < n) rowptr[i] = s[threadIdx.x] - v;
    if (threadIdx.x == 255) bs[blockIdx.x] = s[255];
}
__global__ void scan_aux_kernel(int* bsum, int nb) {
    if (threadIdx.x == 0) {
        for (int y = 0; y < 2; y++) {
            int run = 0;
            int* b = bsum + y * 256;
            for (int i = 0; i < nb; i++) { int t = b[i]; b[i] = run; run += t; }
        }
    }
}
__global__ void scan_add_kernel(int* __restrict__ rowG, int* __restrict__ rowL,
                                int* __restrict__ fillG, int* __restrict__ fillL,
                                const int* __restrict__ bsum, int n, int EG, int EL) {
    int* rowptr = blockIdx.y ? rowL : rowG;
    int* fill = blockIdx.y ? fillL : fillG;
    const int* bs = bsum + blockIdx.y * 256;
    int E = blockIdx.y ? EL : EG;
    int i = blockIdx.x * 256 + threadIdx.x;
    if (i < n) {
        int v = rowptr[i] + bs[i >> 8];
        rowptr[i] = v;
        fill[i] = v;
    }
    if (i == 0) rowptr[n] = E;
}
__global__ void fill_csr_kernel(const int* __restrict__ Ge, int EG, const int* __restrict__ Le, int EL,
                                int* __restrict__ fillG, int* __restrict__ fillL,
                                int2* __restrict__ edgeG, int2* __restrict__ edgeL,
                                const float* __restrict__ dinvG, const float* __restrict__ dinvL) {
    int e = blockIdx.x * blockDim.x + threadIdx.x;
    const int* src; const int* dst; int* fill; int2* edge; const float* dinv; int E;
    if (blockIdx.y == 0) { src = Ge; dst = Ge + EG; fill = fillG; edge = edgeG; dinv = dinvG; E = EG; }
    else                 { src = Le; dst = Le + EL; fill = fillL; edge = edgeL; dinv = dinvL; E = EL; }
    if (e < E) {
        int s = src[e], d = dst[e];
        int p = atomicAdd(&fill[d], 1);
        float c = dinv[s] * dinv[d];
        edge[p] = make_int2(s, __float_as_int(c));
    }
}

// ===== dual-branch GEMM K=128 NOUT=128: 4 warps, 64x64 warp tiles, B resident, fp16 out ====
__global__ __launch_bounds__(128, 2)
void gemm_dual64_kernel(const __half* __restrict__ A,
                        const __half* __restrict__ B0, const __half* __restrict__ B1,
                        __half* __restrict__ Ch0, __half* __restrict__ Ch1, int M) {
    constexpr int K = 128;
    constexpr int LDB = 136;
    constexpr int BTILE = 128 * LDB;
    extern __shared__ __half sm[];
    __half* Bs = sm;
    __half* Astg = sm + BTILE;

    const __half* gB = blockIdx.y ? B1 : B0;
    __half* Ch = blockIdx.y ? Ch1 : Ch0;

    const int tid = threadIdx.x;
    const int wid = tid >> 5;
    const int lane = tid & 31;
    const int wr = wid >> 1;        // 0..1, 64 rows
    const int wc = wid & 1;         // 0..1, 64 cols
    const int row0 = blockIdx.x * 128;

    wmma::fragment<wmma::accumulator, 16, 16, 16, float> acc[4][4];
    #pragma unroll
    for (int i = 0; i < 4; i++)
        #pragma unroll
        for (int j = 0; j < 4; j++)
            wmma::fill_fragment(acc[i][j], 0.0f);

    auto load_A = [&](int s, int kc) {
        __half* base = Astg + s * ATSZ;
        #pragma unroll
        for (int c = tid; c < 512; c += 128) {
            int r = c >> 2;
            int ko = (c & 3) * 8;
            int gr = row0 + r;
            if (gr < M)
                __pipeline_memcpy_async(&base[r * LDT + ko], &A[(size_t)gr * K + kc * 32 + ko], 16);
        }
    };

    #pragma unroll
    for (int c = tid; c < 128 * 16; c += 128) {
        int r = c >> 4;
        int ko = (c & 15) * 8;
        __pipeline_memcpy_async(&Bs[r * LDB + ko], &gB[(size_t)r * K + ko], 16);
    }
    load_A(0, 0);
    __pipeline_commit();

    #pragma unroll
    for (int kc = 0; kc < 4; kc++) {
        if (kc + 1 < 4) {
            load_A((kc + 1) & 1, kc + 1);
            __pipeline_commit();
            __pipeline_wait_prior(1);
        } else {
            __pipeline_wait_prior(0);
        }
        __syncthreads();

        __half* Ahs = Astg + (kc & 1) * ATSZ;

        #pragma unroll
        for (int ks = 0; ks < 32; ks += 16) {
            int kcol = kc * 32 + ks;
            wmma::fragment<wmma::matrix_a, 16, 16, 16, __half, wmma::row_major> fa[4];
            #pragma unroll
            for (int i = 0; i < 4; i++)
                wmma::load_matrix_sync(fa[i], &Ahs[(wr * 64 + i * 16) * LDT + ks], LDT);
            wmma::fragment<wmma::matrix_b, 16, 16, 16, __half, wmma::col_major> fb[4];
            #pragma unroll
            for (int j = 0; j < 4; j++)
                wmma::load_matrix_sync(fb[j], &Bs[(wc * 64 + j * 16) * LDB + kcol], LDB);
            #pragma unroll
            for (int i = 0; i < 4; i++)
                #pragma unroll
                for (int j = 0; j < 4; j++)
                    wmma::mma_sync(acc[i][j], fa[i], fb[j], acc[i][j]);
        }
        __syncthreads();
    }

    float* st = reinterpret_cast<float*>(sm) + wid * 320;
    #pragma unroll
    for (int i = 0; i < 4; i++)
        #pragma unroll
        for (int j = 0; j < 4; j++) {
            wmma::store_matrix_sync(st, acc[i][j], 20, wmma::mem_row_major);
            __syncwarp();
            #pragma unroll
            for (int e = 0; e < 8; e++) {
                int idx = lane + e * 32;
                int r = idx >> 4;
                int c = idx & 15;
                int grow = row0 + wr * 64 + i * 16 + r;
                int gcol = wc * 64 + j * 16 + c;
                if (grow < M)
                    Ch[(size_t)grow * 128 + gcol] = __float2half(st[r * 20 + c]);
            }
            __syncwarp();
        }
}

// ================= fp16 GEMM, B resident, A double-buffered (8 warps, 32xHALFN tiles) =======
template <int NOUT, int KK>
__global__ __launch_bounds__(256, 2)
void gemm_bres_kernel(const __half* __restrict__ A, int lda,
                      const __half* __restrict__ B0, const __half* __restrict__ B1,
                      float* __restrict__ C0, float* __restrict__ C1, int ldc,
                      __half* __restrict__ Ch0, __half* __restrict__ Ch1,
                      const float* __restrict__ bias0, const float* __restrict__ bias1,
                      int M) {
    constexpr int HALFN = NOUT / 2;
    constexpr int NF = HALFN / 16;
    constexpr int LDB = KK + 8;
    constexpr int BTILE = NOUT * LDB;
    constexpr int NC = KK / 32;
    extern __shared__ __half sm[];
    __half* Bs = sm;
    __half* Astg = sm + BTILE;

    const __half* gB = blockIdx.y ? B1 : B0;
    float* C = blockIdx.y ? C1 : C0;
    __half* Ch = blockIdx.y ? Ch1 : Ch0;
    const float* bias = blockIdx.y ? bias1 : bias0;

    const int tid = threadIdx.x;
    const int wid = tid >> 5;
    const int lane = tid & 31;
    const int wr = wid >> 1;
    const int wc = wid & 1;
    const int row0 = blockIdx.x * 128;

    wmma::fragment<wmma::accumulator, 16, 16, 16, float> acc[2][NF];
    #pragma unroll
    for (int i = 0; i < 2; i++)
        #pragma unroll
        for (int j = 0; j < NF; j++)
            wmma::fill_fragment(acc[i][j], 0.0f);

    auto load_A = [&](int s, int kc) {
        __half* base = Astg + s * ATSZ;
        #pragma unroll
        for (int c = tid; c < 512; c += 256) {
            int r = c >> 2;
            int ko = (c & 3) * 8;
            int gr = row0 + r;
            if (gr < M)
                __pipeline_memcpy_async(&base[r * LDT + ko], &A[(size_t)gr * lda + kc * 32 + ko], 16);
        }
    };

    #pragma unroll
    for (int c = tid; c < NOUT * (KK / 8); c += 256) {
        int r = c / (KK / 8);
        int ko = (c % (KK / 8)) * 8;
        __pipeline_memcpy_async(&Bs[r * LDB + ko], &gB[(size_t)r * KK + ko], 16);
    }
    load_A(0, 0);
    __pipeline_commit();

    #pragma unroll
    for (int kc = 0; kc < NC; kc++) {
        if (kc + 1 < NC) {
            load_A((kc + 1) & 1, kc + 1);
            __pipeline_commit();
            __pipeline_wait_prior(1);
        } else {
            __pipeline_wait_prior(0);
        }
        __syncthreads();

        __half* Ahs = Astg + (kc & 1) * ATSZ;

        #pragma unroll
        for (int ks = 0; ks < 32; ks += 16) {
            int kcol = kc * 32 + ks;
            wmma::fragment<wmma::matrix_a, 16, 16, 16, __half, wmma::row_major> fa[2];
            #pragma unroll
            for (int i = 0; i < 2; i++)
                wmma::load_matrix_sync(fa[i], &Ahs[(wr * 32 + i * 16) * LDT + ks], LDT);
            wmma::fragment<wmma::matrix_b, 16, 16, 16, __half, wmma::col_major> fb[NF];
            #pragma unroll
            for (int j = 0; j < NF; j++)
                wmma::load_matrix_sync(fb[j], &Bs[(wc * HALFN + j * 16) * LDB + kcol], LDB);
            #pragma unroll
            for (int i = 0; i < 2; i++)
                #pragma unroll
                for (int j = 0; j < NF; j++)
                    wmma::mma_sync(acc[i][j], fa[i], fb[j], acc[i][j]);
        }
        __syncthreads();
    }

    float* st = reinterpret_cast<float*>(sm) + wid * 320;
    #pragma unroll
    for (int i = 0; i < 2; i++)
        #pragma unroll
        for (int j = 0; j < NF; j++) {
            wmma::store_matrix_sync(st, acc[i][j], 20, wmma::mem_row_major);
            __syncwarp();
            #pragma unroll
            for (int e = 0; e < 8; e++) {
                int idx = lane + e * 32;
                int r = idx >> 4;
                int c = idx & 15;
                int grow = row0 + wr * 32 + i * 16 + r;
                int gcol = wc * HALFN + j * 16 + c;
                if (grow < M) {
                    float v = st[r * 20 + c];
                    if (bias) v += __ldg(&bias[gcol]);
                    if (C)  C[(size_t)grow * ldc + gcol] = v;
                    if (Ch) Ch[(size_t)grow * ldc + gcol] = __float2half(v);
                }
            }
            __syncwarp();
        }
}

// ================= fused gather(fp16, int2 edges, unroll 8) + LN + ReLU + res + concat ======
__global__ void gather_ln_kernel(const uint2* __restrict__ hG8, const uint2* __restrict__ hL8,
                                 const float4* __restrict__ x4,
                                 const int* __restrict__ rowG, const int* __restrict__ rowL,
                                 const int2* __restrict__ edgeG, const int2* __restrict__ edgeL,
                                 const float* __restrict__ dinvG, const float* __restrict__ dinvL,
                                 const float4* __restrict__ biasG4, const float4* __restrict__ biasL4,
                                 const float4* __restrict__ g4, const float4* __restrict__ b4,
                                 __half* __restrict__ cat, int residual) {
    int warp = (blockIdx.x * blockDim.x + threadIdx.x) >> 5;
    int lane = threadIdx.x & 31;
    if (warp >= NN) return;
    int n = warp;
    int half = blockIdx.y;

    const uint2* h8 = half ? hL8 : hG8;
    const int* rowptr = half ? rowL : rowG;
    const int2* edge = half ? edgeL : edgeG;
    const float* dinv = half ? dinvL : dinvG;
    const float4* bias4 = half ? biasL4 : biasG4;

    auto h2f4 = [](uint2 u) -> float4 {
        __half2 a = *reinterpret_cast<__half2*>(&u.x);
        __half2 b = *reinterpret_cast<__half2*>(&u.y);
        float2 fa = __half22float2(a);
        float2 fb = __half22float2(b);
        return make_float4(fa.x, fa.y, fb.x, fb.y);
    };

    float dv = __ldg(&dinv[n]);
    float sl = 2.0f * dv * dv;
    float4 h = h2f4(h8[n * 32 + lane]);
    float4 bb = __ldg(&bias4[lane]);
    float4 acc;
    acc.x = h.x * sl + bb.x;
    acc.y = h.y * sl + bb.y;
    acc.z = h.z * sl + bb.z;
    acc.w = h.w * sl + bb.w;

    int e = __ldg(&rowptr[n]);
    int e1 = __ldg(&rowptr[n + 1]);

    for (; e + 7 < e1; e += 8) {
        int2 p[8];
        #pragma unroll
        for (int q = 0; q < 8; q++) p[q] = __ldg(&edge[e + q]);
        uint2 u[8];
        #pragma unroll
        for (int q = 0; q < 8; q++) u[q] = h8[p[q].x * 32 + lane];
        #pragma unroll
        for (int q = 0; q < 8; q++) {
            float c = __int_as_float(p[q].y);
            float4 v = h2f4(u[q]);
            acc.x += c * v.x;
            acc.y += c * v.y;
            acc.z += c * v.z;
            acc.w += c * v.w;
        }
    }
    if (e + 3 < e1) {
        int2 p[4];
        #pragma unroll
        for (int q = 0; q < 4; q++) p[q] = __ldg(&edge[e + q]);
        uint2 u[4];
        #pragma unroll
        for (int q = 0; q < 4; q++) u[q] = h8[p[q].x * 32 + lane];
        #pragma unroll
        for (int q = 0; q < 4; q++) {
            float c = __int_as_float(p[q].y);
            float4 v = h2f4(u[q]);
            acc.x += c * v.x;
            acc.y += c * v.y;
            acc.z += c * v.z;
            acc.w += c * v.w;
        }
        e += 4;
    }
    for (; e < e1; e++) {
        int2 p0 = __ldg(&edge[e]);
        float c0 = __int_as_float(p0.y);
        float4 v0 = h2f4(h8[p0.x * 32 + lane]);
        acc.x += c0 * v0.x; acc.y += c0 * v0.y; acc.z += c0 * v0.z; acc.w += c0 * v0.w;
    }

    float s1 = acc.x + acc.y + acc.z + acc.w;
    float s2 = acc.x * acc.x + acc.y * acc.y + acc.z * acc.z + acc.w * acc.w;
    #pragma unroll
    for (int o = 16; o > 0; o >>= 1) {
        s1 += __shfl_xor_sync(0xffffffffu, s1, o);
        s2 += __shfl_xor_sync(0xffffffffu, s2, o);
    }
    float mu = s1 * (1.0f / HH);
    float var = s2 * (1.0f / HH) - mu * mu;
    float rstd = rsqrtf(var + LN_EPS);

    float4 gg = __ldg(&g4[lane]);
    float4 be = __ldg(&b4[lane]);
    float4 y;
    y.x = fmaxf((acc.x - mu) * rstd * gg.x + be.x, 0.0f);
    y.y = fmaxf((acc.y - mu) * rstd * gg.y + be.y, 0.0f);
    y.z = fmaxf((acc.z - mu) * rstd * gg.z + be.z, 0.0f);
    y.w = fmaxf((acc.w - mu) * rstd * gg.w + be.w, 0.0f);
    if (residual) {
        float4 xv = x4[n * 32 + lane];
        y.x += xv.x; y.y += xv.y; y.z += xv.z; y.w += xv.w;
    }
    __half2 ya = __floats2half2_rn(y.x, y.y);
    __half2 yb = __floats2half2_rn(y.z, y.w);
    uint2 u = { *(unsigned*)&ya, *(unsigned*)&yb };
    *reinterpret_cast<uint2*>(&cat[(size_t)n * 256 + half * 128 + lane * 4]) = u;
}

// ================= launch =================
extern "C" void kernel_launch(void* const* d_in, const int* in_sizes, int n_in,
                              void* d_out, int out_size) {
    const float* x_in  = (const float*)d_in[0];
    const float* WL    = (const float*)d_in[1];
    const float* bL    = (const float*)d_in[2];
    const float* WG    = (const float*)d_in[3];
    const float* bG    = (const float*)d_in[4];
    const float* linW  = (const float*)d_in[5];
    const float* linb  = (const float*)d_in[6];
    const float* ln_g  = (const float*)d_in[7];
    const float* ln_b  = (const float*)d_in[8];
    const float* finW  = (const float*)d_in[9];
    const float* finb  = (const float*)d_in[10];
    const int*   Ge    = (const int*)d_in[11];
    const int*   Le    = (const int*)d_in[12];
    int E_G = in_sizes[11] / 2;
    int E_L = in_sizes[12] / 2;
    float* out = (float*)d_out;

    float *px, *pdinvG, *pdinvL;
    __half *pxh, *phG, *phL, *pcat;
    int *pdegG, *pdegL, *prowG, *prowL, *pfillG, *pfillL, *pbsum;
    int2 *pedgeG, *pedgeL;
    __half *pBG, *pBL, *pBlin, *pBfin;
    cudaGetSymbolAddress((void**)&px,     g_x);
    cudaGetSymbolAddress((void**)&pxh,    g_xh);
    cudaGetSymbolAddress((void**)&phG,    g_hG);
    cudaGetSymbolAddress((void**)&phL,    g_hL);
    cudaGetSymbolAddress((void**)&pcat,   g_cat);
    cudaGetSymbolAddress((void**)&pdegG,  g_degG);
    cudaGetSymbolAddress((void**)&pdegL,  g_degL);
    cudaGetSymbolAddress((void**)&pdinvG, g_dinvG);
    cudaGetSymbolAddress((void**)&pdinvL, g_dinvL);
    cudaGetSymbolAddress((void**)&prowG,  g_rowptrG);
    cudaGetSymbolAddress((void**)&prowL,  g_rowptrL);
    cudaGetSymbolAddress((void**)&pfillG, g_fillG);
    cudaGetSymbolAddress((void**)&pfillL, g_fillL);
    cudaGetSymbolAddress((void**)&pedgeG, g_edgeG);
    cudaGetSymbolAddress((void**)&pedgeL, g_edgeL);
    cudaGetSymbolAddress((void**)&pbsum,  g_bsum);
    cudaGetSymbolAddress((void**)&pBG,    g_BG);
    cudaGetSymbolAddress((void**)&pBL,    g_BL);
    cudaGetSymbolAddress((void**)&pBlin,  g_Blin);
    cudaGetSymbolAddress((void**)&pBfin,  g_Bfin);

    const int SM_DUAL   = (128 * 136 + 2 * ATSZ) * 2;    // 55296
    const int SM_CONCAT = (64 * 264 + 2 * ATSZ) * 2;     // 54272
    const int SM_FINAL  = (64 * 136 + 2 * ATSZ) * 2;     // 37888

    static cudaStream_t s1 = nullptr;
    static cudaEvent_t evFork1, evJoin1;
    static int attr_set = 0;
    if (!attr_set) {
        cudaFuncSetAttribute((const void*)gemm_dual64_kernel, cudaFuncAttributeMaxDynamicSharedMemorySize, SM_DUAL);
        cudaFuncSetAttribute((const void*)gemm_bres_kernel<64, 256>, cudaFuncAttributeMaxDynamicSharedMemorySize, SM_CONCAT);
        cudaFuncSetAttribute((const void*)gemm_bres_kernel<64, 128>, cudaFuncAttributeMaxDynamicSharedMemorySize, SM_FINAL);
        cudaStreamCreateWithFlags(&s1, cudaStreamNonBlocking);
        cudaEventCreateWithFlags(&evFork1, cudaEventDisableTiming);
        cudaEventCreateWithFlags(&evJoin1, cudaEventDisableTiming);
        attr_set = 1;
    }

    // ---- fork: CSR build on side stream ----
    cudaEventRecord(evFork1, 0);
    cudaStreamWaitEvent(s1, evFork1, 0);

    zero_deg_kernel<<<NB196, 256, 0, s1>>>(pdegG, pdegL, NN);
    count_deg_kernel<<<(E_G + E_L + 255) / 256, 256, 0, s1>>>(Ge + E_G, E_G, Le + E_L, E_L, pdegG, pdegL);
    make_dinv_kernel<<<NB196, 256, 0, s1>>>(pdegG, pdinvG, pdegL, pdinvL, NN);
    scan_block_kernel<<<dim3(NB196, 2), 256, 0, s1>>>(pdegG, pdegL, prowG, prowL, pbsum, NN);
    scan_aux_kernel<<<1, 32, 0, s1>>>(pbsum, NB196);
    scan_add_kernel<<<dim3(NB196, 2), 256, 0, s1>>>(prowG, prowL, pfillG, pfillL, pbsum, NN, E_G, E_L);
    int fe = (E_G > E_L ? E_G : E_L);
    fill_csr_kernel<<<dim3((fe + 255) / 256, 2), 256, 0, s1>>>(Ge, E_G, Le, E_L,
        pfillG, pfillL, pedgeG, pedgeL, pdinvG, pdinvL);
    cudaEventRecord(evJoin1, s1);

    wsplit_all_kernel<<<dim3(4, 8, 10), dim3(32, 8)>>>(WG, WL, linW, finW, pBG, pBL, pBlin, pBfin);
    init_split_kernel<<<(NN * HH / 4 + 255) / 256, 256>>>((const float4*)x_in, (float4*)px, pxh);
    gemm_dual64_kernel<<<dim3(TILES, 2), 128, SM_DUAL>>>(pxh, pBG, pBL, phG, phL, NN);

    cudaStreamWaitEvent(0, evJoin1, 0);   // gather needs CSR

    int gatherBlocks = (NN * 32 + 255) / 256;

    for (int i = 0; i < DEPTH; i++) {
        if (i > 0) {
            size_t wo = (size_t)i * HH * HH;
            gemm_dual64_kernel<<<dim3(TILES, 2), 128, SM_DUAL>>>(pxh, pBG + wo, pBL + wo, phG, phL, NN);
        }
        int res = (i > 0) ? 1 : 0;
        gather_ln_kernel<<<dim3(gatherBlocks, 2), 256>>>(
            (const uint2*)phG, (const uint2*)phL, (const float4*)px,
            prowG, prowL, pedgeG, pedgeL, pdinvG, pdinvL,
            (const float4*)(bG + (size_t)i * HH), (const float4*)(bL + (size_t)i * HH),
            (const float4*)ln_g, (const float4*)ln_b, pcat, res);
        // concat linear, N-split into two 64-col halves via grid.y
        const __half* Bl0 = pBlin + (size_t)i * HH * 2 * HH;
        const __half* Bl1 = Bl0 + (size_t)64 * 2 * HH;
        const float* lb = linb + (size_t)i * HH;
        // last layer: write fp32 x directly into the out2 region (no copy)
        float* xdst = (i == DEPTH - 1) ? (out + (size_t)NN * OUTC) : px;
        gemm_bres_kernel<64, 256><<<dim3(TILES, 2), 256, SM_CONCAT>>>(
            pcat, 2 * HH, Bl0, Bl1, xdst, xdst + 64, HH, pxh, pxh + 64, lb, lb + 64, NN);
    }

    gemm_bres_kernel<64, 128><<<dim3(TILES, 1), 256, SM_FINAL>>>(
        pxh, HH, pBfin, nullptr, out, nullptr, OUTC, nullptr, nullptr, finb, nullptr, NN);
}